// round 5
// baseline (speedup 1.0000x reference)
#include <cuda_runtime.h>
#include <math.h>

// Problem constants (fixed by the reference)
#define BB   2
#define SS   2048
#define HH   1024
#define NHH  16
#define PHH  64
#define MM   (BB*SS)     // 4096 rows for all GEMMs
#define KK   1024        // GEMM reduction dim

// Scratch (allocation-free rule: __device__ globals)
__device__ float g_q[BB*NHH*SS*PHH];
__device__ float g_k[BB*NHH*SS*PHH];
__device__ float g_v[BB*NHH*SS*PHH];
__device__ float g_ctx[BB*SS*HH];

// ---------------------------------------------------------------------------
// GEMM: C = A @ W^T + bias.  A [M,K] row-major, W [N,K] row-major (NT gemm).
// 128x128 tile, BK=16, 256 threads, 8x8 results per thread (2x2 of 4x4).
// SPLIT=true writes output in [B,NH,S,PH] layout.
// ---------------------------------------------------------------------------
template<bool SPLIT>
__global__ __launch_bounds__(256) void gemm_nt(const float* __restrict__ A,
                                               const float* __restrict__ W,
                                               const float* __restrict__ bias,
                                               float* __restrict__ C)
{
    __shared__ float As[16][132];
    __shared__ float Bs[16][132];

    const int tid = threadIdx.x;
    const int bm = blockIdx.y * 128;
    const int bn = blockIdx.x * 128;
    const int tx = tid & 15;   // 0..15
    const int ty = tid >> 4;   // 0..15

    float c[2][2][4][4];
#pragma unroll
    for (int ia = 0; ia < 2; ia++)
#pragma unroll
        for (int jb = 0; jb < 2; jb++)
#pragma unroll
            for (int i = 0; i < 4; i++)
#pragma unroll
                for (int j = 0; j < 4; j++) c[ia][jb][i][j] = 0.f;

    for (int k0 = 0; k0 < KK; k0 += 16) {
#pragma unroll
        for (int l = 0; l < 2; l++) {
            int idx = tid + l * 256;          // 0..511
            int row = idx >> 2;               // 0..127
            int qq  = idx & 3;                // which float4 within 16-wide k
            float4 av = *(const float4*)&A[(size_t)(bm + row) * KK + k0 + qq * 4];
            As[qq*4+0][row] = av.x; As[qq*4+1][row] = av.y;
            As[qq*4+2][row] = av.z; As[qq*4+3][row] = av.w;
            float4 wv = *(const float4*)&W[(size_t)(bn + row) * KK + k0 + qq * 4];
            Bs[qq*4+0][row] = wv.x; Bs[qq*4+1][row] = wv.y;
            Bs[qq*4+2][row] = wv.z; Bs[qq*4+3][row] = wv.w;
        }
        __syncthreads();

#pragma unroll
        for (int k = 0; k < 16; k++) {
            float a0[4], a1[4], b0[4], b1[4];
            *(float4*)a0 = *(const float4*)&As[k][ty * 4];
            *(float4*)a1 = *(const float4*)&As[k][64 + ty * 4];
            *(float4*)b0 = *(const float4*)&Bs[k][tx * 4];
            *(float4*)b1 = *(const float4*)&Bs[k][64 + tx * 4];
#pragma unroll
            for (int i = 0; i < 4; i++)
#pragma unroll
                for (int j = 0; j < 4; j++) {
                    c[0][0][i][j] += a0[i] * b0[j];
                    c[0][1][i][j] += a0[i] * b1[j];
                    c[1][0][i][j] += a1[i] * b0[j];
                    c[1][1][i][j] += a1[i] * b1[j];
                }
        }
        __syncthreads();
    }

#pragma unroll
    for (int ia = 0; ia < 2; ia++)
#pragma unroll
        for (int i = 0; i < 4; i++) {
            int mrow = bm + ia * 64 + ty * 4 + i;
            int b = mrow >> 11;        // / 2048
            int s = mrow & 2047;
#pragma unroll
            for (int jb = 0; jb < 2; jb++)
#pragma unroll
                for (int j = 0; j < 4; j++) {
                    int ncol = bn + jb * 64 + tx * 4 + j;
                    float val = c[ia][jb][i][j] + bias[ncol];
                    if (SPLIT) {
                        int h = ncol >> 6;
                        int d = ncol & 63;
                        C[(((size_t)(b * NHH + h)) * SS + s) * PHH + d] = val;
                    } else {
                        C[(size_t)mrow * HH + ncol] = val;
                    }
                }
        }
}

// ---------------------------------------------------------------------------
// Attention v2: GEMM-shaped flash attention.
// Grid (S/128, NH, B), 256 threads. 128 q-rows per CTA, k-tiles of 128.
// Score phase: 128x128 tile, 8x8 per thread (1 B/FMA).
// PV phase: 128x64 tile, 8 rows x 8 d-cols per thread over half the kk range
//           (parity split), partials combined in epilogue (1 B/FMA).
// Softmax: separate row pass over Ps with per-row m/l/corr state in smem.
// ---------------------------------------------------------------------------
#define PADQ 132   // stride for Qt/Kt [64][132]
#define PADV 68    // stride for Vs [128][68]
#define PADP 132   // stride for Ps [128][132]

#define ATTN2_SMEM ((64*PADQ*2 + 128*PADV + 128*PADP + 3*128) * 4)

__global__ __launch_bounds__(256) void attn2_kernel(const float* __restrict__ Q,
                                                    const float* __restrict__ K,
                                                    const float* __restrict__ V,
                                                    const float* __restrict__ mask,
                                                    float* __restrict__ ctx)
{
    extern __shared__ float sm[];
    float* Qt = sm;                       // [64][PADQ]  Qt[d][row]
    float* Kt = Qt + 64 * PADQ;           // [64][PADQ]  Kt[d][col]
    float* Vs = Kt + 64 * PADQ;           // [128][PADV] Vs[kk][d]
    float* Ps = Vs + 128 * PADV;          // [128][PADP] Ps[row][col]
    float* sm_m    = Ps + 128 * PADP;     // [128]
    float* sm_l    = sm_m + 128;          // [128]
    float* sm_corr = sm_l + 128;          // [128]

    const int t  = threadIdx.x;
    const int ti = t >> 4;                // 0..15  (8 q-rows each)
    const int tj = t & 15;                // 0..15
    const int r0 = ti * 8;
    const int cA = tj * 4;                // score cols: cA+j (j<4), 64+cA+(j-4)
    const int dj = tj & 7;
    const int p  = tj >> 3;               // kk parity
    const int dA = dj * 4;                // d cols: dA+j (j<4), 32+dA+(j-4)

    const int qt = blockIdx.x;
    const int h  = blockIdx.y;
    const int b  = blockIdx.z;
    const int q0 = qt * 128;

    const size_t headoff = ((size_t)(b * NHH + h)) * SS * PHH;
    const float* Qg = Q + headoff + (size_t)q0 * PHH;
    const float* Kg = K + headoff;
    const float* Vg = V + headoff;
    const float* Mg = mask + (size_t)b * SS * SS + (size_t)q0 * SS;

    // Load Q transposed: Qt[d][row]
    for (int i = t; i < 128 * 16; i += 256) {
        int row = i >> 4, qq = i & 15;
        float4 v = *(const float4*)&Qg[(size_t)row * 64 + qq * 4];
        Qt[(qq*4+0) * PADQ + row] = v.x;
        Qt[(qq*4+1) * PADQ + row] = v.y;
        Qt[(qq*4+2) * PADQ + row] = v.z;
        Qt[(qq*4+3) * PADQ + row] = v.w;
    }
    if (t < 128) { sm_m[t] = -3.0e38f; sm_l[t] = 0.f; }

    float o[64];
#pragma unroll
    for (int i = 0; i < 64; i++) o[i] = 0.f;

    for (int kt = 0; kt < SS / 128; kt++) {
        __syncthreads();   // previous PV done with Ps/Vs

        // Load K (transposed) and V tiles
        for (int i = t; i < 128 * 16; i += 256) {
            int row = i >> 4, qq = i & 15;
            const float* krow = &Kg[(size_t)(kt * 128 + row) * 64 + qq * 4];
            float4 kv = *(const float4*)krow;
            Kt[(qq*4+0) * PADQ + row] = kv.x;
            Kt[(qq*4+1) * PADQ + row] = kv.y;
            Kt[(qq*4+2) * PADQ + row] = kv.z;
            Kt[(qq*4+3) * PADQ + row] = kv.w;
            float4 vv = *(const float4*)&Vg[(size_t)(kt * 128 + row) * 64 + qq * 4];
            *(float4*)&Vs[row * PADV + qq * 4] = vv;
        }
        __syncthreads();

        // ---- score phase: acc[8][8] over d=0..63 ----
        float acc[8][8];
#pragma unroll
        for (int i = 0; i < 8; i++)
#pragma unroll
            for (int j = 0; j < 8; j++) acc[i][j] = 0.f;

#pragma unroll 8
        for (int d = 0; d < 64; d++) {
            float a[8], bv[8];
            *(float4*)&a[0]  = *(const float4*)&Qt[d * PADQ + r0];
            *(float4*)&a[4]  = *(const float4*)&Qt[d * PADQ + r0 + 4];
            *(float4*)&bv[0] = *(const float4*)&Kt[d * PADQ + cA];
            *(float4*)&bv[4] = *(const float4*)&Kt[d * PADQ + 64 + cA];
#pragma unroll
            for (int i = 0; i < 8; i++)
#pragma unroll
                for (int j = 0; j < 8; j++) acc[i][j] += a[i] * bv[j];
        }

        // scale + multiplicative mask, publish to Ps
#pragma unroll
        for (int i = 0; i < 8; i++) {
            int r = r0 + i;
            const float* mrow = &Mg[(size_t)r * SS + kt * 128];
            float4 m0 = *(const float4*)&mrow[cA];
            float4 m1 = *(const float4*)&mrow[64 + cA];
            float4 s0 = make_float4(acc[i][0] * 0.125f * m0.x,
                                    acc[i][1] * 0.125f * m0.y,
                                    acc[i][2] * 0.125f * m0.z,
                                    acc[i][3] * 0.125f * m0.w);
            float4 s1 = make_float4(acc[i][4] * 0.125f * m1.x,
                                    acc[i][5] * 0.125f * m1.y,
                                    acc[i][6] * 0.125f * m1.z,
                                    acc[i][7] * 0.125f * m1.w);
            *(float4*)&Ps[r * PADP + cA]      = s0;
            *(float4*)&Ps[r * PADP + 64 + cA] = s1;
        }
        __syncthreads();

        // ---- row softmax pass (2-pass over Ps, half-row per thread) ----
        {
            int row = t >> 1, hf = t & 1;
            float* prow = &Ps[row * PADP + hf * 64];
            float mx = -3.0e38f;
#pragma unroll
            for (int q = 0; q < 16; q++) {
                float4 v = ((const float4*)prow)[q];
                mx = fmaxf(mx, fmaxf(fmaxf(v.x, v.y), fmaxf(v.z, v.w)));
            }
            mx = fmaxf(mx, __shfl_xor_sync(0xffffffffu, mx, 1));
            float mold = sm_m[row];
            float mnew = fmaxf(mold, mx);
            float corr = __expf(mold - mnew);
            float ts = 0.f;
#pragma unroll
            for (int q = 0; q < 16; q++) {
                float4 v = ((const float4*)prow)[q];
                v.x = __expf(v.x - mnew);
                v.y = __expf(v.y - mnew);
                v.z = __expf(v.z - mnew);
                v.w = __expf(v.w - mnew);
                ((float4*)prow)[q] = v;
                ts += v.x + v.y + v.z + v.w;
            }
            ts += __shfl_xor_sync(0xffffffffu, ts, 1);
            if (hf == 0) {
                sm_m[row] = mnew;
                sm_l[row] = sm_l[row] * corr + ts;
                sm_corr[row] = corr;
            }
        }
        __syncthreads();

        // ---- PV phase: o[i][j] over half the kk range (parity split) ----
        float corr8[8];
#pragma unroll
        for (int i = 0; i < 8; i++) corr8[i] = sm_corr[r0 + i];
#pragma unroll
        for (int i = 0; i < 8; i++)
#pragma unroll
            for (int j = 0; j < 8; j++) o[i*8+j] *= corr8[i];

#pragma unroll 4
        for (int x = 0; x < 64; x++) {
            int kk = 2 * x + p;
            float pa[8], vb[8];
#pragma unroll
            for (int i = 0; i < 8; i++) pa[i] = Ps[(r0 + i) * PADP + kk];
            *(float4*)&vb[0] = *(const float4*)&Vs[kk * PADV + dA];
            *(float4*)&vb[4] = *(const float4*)&Vs[kk * PADV + 32 + dA];
#pragma unroll
            for (int i = 0; i < 8; i++)
#pragma unroll
                for (int j = 0; j < 8; j++) o[i*8+j] += pa[i] * vb[j];
        }
    }

    // ---- epilogue: combine parity halves via Ps, normalize, write ----
    __syncthreads();
    if (p == 1) {
#pragma unroll
        for (int i = 0; i < 8; i++) {
            int r = r0 + i;
#pragma unroll
            for (int j = 0; j < 8; j++) {
                int dcol = (j < 4) ? (dA + j) : (32 + dA + j - 4);
                Ps[r * PADP + dcol] = o[i*8+j];
            }
        }
    }
    __syncthreads();
    if (p == 0) {
#pragma unroll
        for (int i = 0; i < 8; i++) {
            int r = r0 + i;
            float inv = 1.f / sm_l[r];
            float* og = &ctx[((size_t)b * SS + q0 + r) * HH + h * PHH];
            float4 o0, o1;
            o0.x = (o[i*8+0] + Ps[r * PADP + dA + 0]) * inv;
            o0.y = (o[i*8+1] + Ps[r * PADP + dA + 1]) * inv;
            o0.z = (o[i*8+2] + Ps[r * PADP + dA + 2]) * inv;
            o0.w = (o[i*8+3] + Ps[r * PADP + dA + 3]) * inv;
            o1.x = (o[i*8+4] + Ps[r * PADP + 32 + dA + 0]) * inv;
            o1.y = (o[i*8+5] + Ps[r * PADP + 32 + dA + 1]) * inv;
            o1.z = (o[i*8+6] + Ps[r * PADP + 32 + dA + 2]) * inv;
            o1.w = (o[i*8+7] + Ps[r * PADP + 32 + dA + 3]) * inv;
            *(float4*)&og[dA]      = o0;
            *(float4*)&og[32 + dA] = o1;
        }
    }
}

// ---------------------------------------------------------------------------
// Launch
// ---------------------------------------------------------------------------
extern "C" void kernel_launch(void* const* d_in, const int* in_sizes, int n_in,
                              void* d_out, int out_size)
{
    const float* key   = (const float*)d_in[0];
    const float* value = (const float*)d_in[1];
    const float* query = (const float*)d_in[2];
    const float* mask  = (const float*)d_in[3];
    // d_in[4] = i (unused)
    const float* Wq = (const float*)d_in[5];
    const float* bq = (const float*)d_in[6];
    const float* Wk = (const float*)d_in[7];
    const float* bk = (const float*)d_in[8];
    const float* Wv = (const float*)d_in[9];
    const float* bv = (const float*)d_in[10];
    const float* Wo = (const float*)d_in[11];
    const float* bo = (const float*)d_in[12];
    float* out = (float*)d_out;

    float *qp, *kp, *vp, *cp;
    cudaGetSymbolAddress((void**)&qp, g_q);
    cudaGetSymbolAddress((void**)&kp, g_k);
    cudaGetSymbolAddress((void**)&vp, g_v);
    cudaGetSymbolAddress((void**)&cp, g_ctx);

    dim3 gg(HH / 128, MM / 128);   // (8, 32)

    gemm_nt<true><<<gg, 256>>>(query, Wq, bq, qp);
    gemm_nt<true><<<gg, 256>>>(key,   Wk, bk, kp);
    gemm_nt<true><<<gg, 256>>>(value, Wv, bv, vp);

    cudaFuncSetAttribute(attn2_kernel,
                         cudaFuncAttributeMaxDynamicSharedMemorySize, ATTN2_SMEM);
    attn2_kernel<<<dim3(SS / 128, NHH, BB), 256, ATTN2_SMEM>>>(qp, kp, vp, mask, cp);

    gemm_nt<false><<<gg, 256>>>(cp, Wo, bo, out);
}

// round 8
// speedup vs baseline: 1.3488x; 1.3488x over previous
#include <cuda_runtime.h>
#include <cuda_bf16.h>
#include <cstdint>
#include <math.h>

#define BB   2
#define SS   2048
#define HH   1024
#define NHH  16
#define PHH  64
#define MM   (BB*SS)
#define KK   1024

__device__ float g_q[BB*NHH*SS*PHH];
__device__ float g_k[BB*NHH*SS*PHH];
__device__ float g_v[BB*NHH*SS*PHH];
__device__ float g_ctx[BB*SS*HH];
__device__ __nv_bfloat16 g_qh[MM*KK], g_ql[MM*KK];
__device__ __nv_bfloat16 g_kh[MM*KK], g_kl[MM*KK];
__device__ __nv_bfloat16 g_vh[MM*KK], g_vl[MM*KK];
__device__ __nv_bfloat16 g_ch[MM*KK], g_cl[MM*KK];
__device__ __nv_bfloat16 g_wqh[HH*HH], g_wql[HH*HH];
__device__ __nv_bfloat16 g_wkh[HH*HH], g_wkl[HH*HH];
__device__ __nv_bfloat16 g_wvh[HH*HH], g_wvl[HH*HH];
__device__ __nv_bfloat16 g_woh[HH*HH], g_wol[HH*HH];

__device__ __forceinline__ uint32_t smem_u32(const void* p) {
    uint32_t a;
    asm("{ .reg .u64 t; cvta.to.shared.u64 t, %1; cvt.u32.u64 %0, t; }" : "=r"(a) : "l"(p));
    return a;
}
__device__ __forceinline__ void cp_async16(uint32_t s, const void* g) {
    asm volatile("cp.async.cg.shared.global [%0], [%1], 16;" :: "r"(s), "l"(g));
}
__device__ __forceinline__ void cp_commit() {
    asm volatile("cp.async.commit_group;" ::: "memory");
}
template<int N> __device__ __forceinline__ void cp_wait() {
    asm volatile("cp.async.wait_group %0;" :: "n"(N) : "memory");
}
__device__ __forceinline__ void ldsm_x4(uint32_t addr, uint32_t* r) {
    asm volatile("ldmatrix.sync.aligned.m8n8.x4.shared.b16 {%0,%1,%2,%3}, [%4];"
                 : "=r"(r[0]), "=r"(r[1]), "=r"(r[2]), "=r"(r[3]) : "r"(addr));
}
__device__ __forceinline__ void mma16816(float* d, const uint32_t* a, const uint32_t* b) {
    asm volatile("mma.sync.aligned.m16n8k16.row.col.f32.bf16.bf16.f32 "
        "{%0,%1,%2,%3}, {%4,%5,%6,%7}, {%8,%9}, {%0,%1,%2,%3};"
        : "+f"(d[0]), "+f"(d[1]), "+f"(d[2]), "+f"(d[3])
        : "r"(a[0]), "r"(a[1]), "r"(a[2]), "r"(a[3]), "r"(b[0]), "r"(b[1]));
}

__global__ void split_convert(const float* __restrict__ src,
                              __nv_bfloat16* __restrict__ hi,
                              __nv_bfloat16* __restrict__ lo, int n4)
{
    int i = blockIdx.x * blockDim.x + threadIdx.x;
    if (i >= n4) return;
    float4 v = ((const float4*)src)[i];
    __nv_bfloat16 h0 = __float2bfloat16(v.x), h1 = __float2bfloat16(v.y);
    __nv_bfloat16 h2 = __float2bfloat16(v.z), h3 = __float2bfloat16(v.w);
    __nv_bfloat16 l0 = __float2bfloat16(v.x - __bfloat162float(h0));
    __nv_bfloat16 l1 = __float2bfloat16(v.y - __bfloat162float(h1));
    __nv_bfloat16 l2 = __float2bfloat16(v.z - __bfloat162float(h2));
    __nv_bfloat16 l3 = __float2bfloat16(v.w - __bfloat162float(h3));
    uint2 hv, lv;
    hv.x = (uint32_t)__bfloat16_as_ushort(h0) | ((uint32_t)__bfloat16_as_ushort(h1) << 16);
    hv.y = (uint32_t)__bfloat16_as_ushort(h2) | ((uint32_t)__bfloat16_as_ushort(h3) << 16);
    lv.x = (uint32_t)__bfloat16_as_ushort(l0) | ((uint32_t)__bfloat16_as_ushort(l1) << 16);
    lv.y = (uint32_t)__bfloat16_as_ushort(l2) | ((uint32_t)__bfloat16_as_ushort(l3) << 16);
    *(uint2*)(hi + (size_t)i * 4) = hv;
    *(uint2*)(lo + (size_t)i * 4) = lv;
}

// ---------------------------------------------------------------------------
// HMMA GEMM: C[M,N] = A@W^T + bias, split-bf16 (AhWh + AhWl + AlWh).
// 128x128 CTA tile, BK=64, 8 warps (warp tile 64x32), mma.m16n8k16,
// SW128 smem + ldmatrix, cp.async double buffer.
// ---------------------------------------------------------------------------
#define T_TILE 16384                 // 128 rows x 128B (64 bf16)
#define G2_SMEM (2 * 4 * T_TILE)     // 131072

__device__ __forceinline__ void prefetch_chunk(
    const __nv_bfloat16* __restrict__ Ah, const __nv_bfloat16* __restrict__ Al,
    const __nv_bfloat16* __restrict__ Wh, const __nv_bfloat16* __restrict__ Wl,
    int k0, uint32_t sbase, int tid)
{
    const __nv_bfloat16* srcs[4] = {Ah, Al, Wh, Wl};
#pragma unroll
    for (int t = 0; t < 4; t++) {
#pragma unroll
        for (int p = 0; p < 4; p++) {
            int idx = tid + p * 256;
            int row = idx >> 3, ch = idx & 7;
            uint32_t soff = sbase + t * T_TILE + row * 128 + ((ch ^ (row & 7)) << 4);
            cp_async16(soff, srcs[t] + (size_t)row * KK + k0 + ch * 8);
        }
    }
}

template<bool SPLIT>
__global__ __launch_bounds__(256) void gemm_tc(
    const __nv_bfloat16* __restrict__ Ahi, const __nv_bfloat16* __restrict__ Alo,
    const __nv_bfloat16* __restrict__ Whi, const __nv_bfloat16* __restrict__ Wlo,
    const float* __restrict__ bias, float* __restrict__ C)
{
    extern __shared__ char smem[];
    const uint32_t sbase = smem_u32(smem);
    const int tid  = threadIdx.x;
    const int wid  = tid >> 5;
    const int lane = tid & 31;
    const int wm = wid >> 2;        // 0..1
    const int wn = wid & 3;         // 0..3
    const int bm = blockIdx.y * 128;
    const int bn = blockIdx.x * 128;

    const __nv_bfloat16* Ah = Ahi + (size_t)bm * KK;
    const __nv_bfloat16* Al = Alo + (size_t)bm * KK;
    const __nv_bfloat16* Wh = Whi + (size_t)bn * KK;
    const __nv_bfloat16* Wl = Wlo + (size_t)bn * KK;

    // per-thread ldmatrix row offsets (bytes)
    const int L7 = lane & 7;
    const int aSel = lane >> 4;            // k-chunk select for A matrices
    const int bSel = (lane >> 3) & 1;      // k-chunk select for B matrices
    uint32_t aRow[4], bRow[2];
#pragma unroll
    for (int mi = 0; mi < 4; mi++)
        aRow[mi] = (uint32_t)(wm * 64 + mi * 16 + (lane & 15)) * 128;
#pragma unroll
    for (int nb = 0; nb < 2; nb++)
        bRow[nb] = (uint32_t)(wn * 32 + nb * 16 + ((lane >> 4) * 8) + L7) * 128;

    float acc[4][4][4];
#pragma unroll
    for (int mi = 0; mi < 4; mi++)
#pragma unroll
        for (int nj = 0; nj < 4; nj++)
#pragma unroll
            for (int q = 0; q < 4; q++) acc[mi][nj][q] = 0.f;

    prefetch_chunk(Ah, Al, Wh, Wl, 0, sbase, tid);
    cp_commit();

    for (int it = 0; it < 16; it++) {
        if (it < 15) {
            prefetch_chunk(Ah, Al, Wh, Wl, (it + 1) * 64,
                           sbase + ((it + 1) & 1) * 4 * T_TILE, tid);
            cp_commit();
            cp_wait<1>();
        } else {
            cp_wait<0>();
        }
        __syncthreads();

        const uint32_t tb = sbase + (it & 1) * 4 * T_TILE;
#pragma unroll
        for (int ks = 0; ks < 4; ks++) {
            const int kx = ks * 2;
            uint32_t aH[4][4], aL[4][4], bH[2][4], bL[2][4];
#pragma unroll
            for (int mi = 0; mi < 4; mi++) {
                uint32_t ad = tb + aRow[mi] + (uint32_t)(((kx + aSel) ^ L7) << 4);
                ldsm_x4(ad + 0 * T_TILE, aH[mi]);
                ldsm_x4(ad + 1 * T_TILE, aL[mi]);
            }
#pragma unroll
            for (int nb = 0; nb < 2; nb++) {
                uint32_t bd = tb + bRow[nb] + (uint32_t)(((kx + bSel) ^ L7) << 4);
                ldsm_x4(bd + 2 * T_TILE, bH[nb]);
                ldsm_x4(bd + 3 * T_TILE, bL[nb]);
            }
#pragma unroll
            for (int mi = 0; mi < 4; mi++)
#pragma unroll
                for (int nj = 0; nj < 4; nj++) {
                    const uint32_t* fH = &bH[nj >> 1][(nj & 1) * 2];
                    const uint32_t* fL = &bL[nj >> 1][(nj & 1) * 2];
                    mma16816(acc[mi][nj], aH[mi], fH);
                    mma16816(acc[mi][nj], aH[mi], fL);
                    mma16816(acc[mi][nj], aL[mi], fH);
                }
        }
        __syncthreads();
    }

    // epilogue: direct gmem stores (float2 per c-pair) + bias
#pragma unroll
    for (int mi = 0; mi < 4; mi++)
#pragma unroll
        for (int nj = 0; nj < 4; nj++) {
            int row0 = bm + wm * 64 + mi * 16 + (lane >> 2);
            int col  = bn + wn * 32 + nj * 8 + (lane & 3) * 2;
            float b0 = bias[col], b1 = bias[col + 1];
#pragma unroll
            for (int half = 0; half < 2; half++) {
                int row = row0 + half * 8;
                float v0 = acc[mi][nj][half * 2 + 0] + b0;
                float v1 = acc[mi][nj][half * 2 + 1] + b1;
                if (SPLIT) {
                    int b = row >> 11, s = row & 2047;
                    int h = col >> 6,  d = col & 63;
                    float2* dst = (float2*)&C[(((size_t)(b * NHH + h)) * SS + s) * PHH + d];
                    *dst = make_float2(v0, v1);
                } else {
                    *(float2*)&C[(size_t)row * HH + col] = make_float2(v0, v1);
                }
            }
        }
}

// -------- attention (unchanged from passing round-3 kernel) --------
#define PADQ 132
#define PADV 68
#define PADP 132
#define ATTN2_SMEM ((64*PADQ*2 + 128*PADV + 128*PADP + 3*128) * 4)

__global__ __launch_bounds__(256) void attn2_kernel(const float* __restrict__ Q,
                                                    const float* __restrict__ K,
                                                    const float* __restrict__ V,
                                                    const float* __restrict__ mask,
                                                    float* __restrict__ ctx)
{
    extern __shared__ float sm[];
    float* Qt = sm;
    float* Kt = Qt + 64 * PADQ;
    float* Vs = Kt + 64 * PADQ;
    float* Ps = Vs + 128 * PADV;
    float* sm_m    = Ps + 128 * PADP;
    float* sm_l    = sm_m + 128;
    float* sm_corr = sm_l + 128;

    const int t  = threadIdx.x;
    const int ti = t >> 4;
    const int tj = t & 15;
    const int r0 = ti * 8;
    const int cA = tj * 4;
    const int dj = tj & 7;
    const int p  = tj >> 3;
    const int dA = dj * 4;

    const int qt = blockIdx.x, h = blockIdx.y, b = blockIdx.z;
    const int q0 = qt * 128;

    const size_t headoff = ((size_t)(b * NHH + h)) * SS * PHH;
    const float* Qg = Q + headoff + (size_t)q0 * PHH;
    const float* Kg = K + headoff;
    const float* Vg = V + headoff;
    const float* Mg = mask + (size_t)b * SS * SS + (size_t)q0 * SS;

    for (int i = t; i < 128 * 16; i += 256) {
        int row = i >> 4, qq = i & 15;
        float4 v = *(const float4*)&Qg[(size_t)row * 64 + qq * 4];
        Qt[(qq*4+0) * PADQ + row] = v.x;
        Qt[(qq*4+1) * PADQ + row] = v.y;
        Qt[(qq*4+2) * PADQ + row] = v.z;
        Qt[(qq*4+3) * PADQ + row] = v.w;
    }
    if (t < 128) { sm_m[t] = -3.0e38f; sm_l[t] = 0.f; }

    float o[64];
#pragma unroll
    for (int i = 0; i < 64; i++) o[i] = 0.f;

    for (int kt = 0; kt < SS / 128; kt++) {
        __syncthreads();
        for (int i = t; i < 128 * 16; i += 256) {
            int row = i >> 4, qq = i & 15;
            float4 kv = *(const float4*)&Kg[(size_t)(kt * 128 + row) * 64 + qq * 4];
            Kt[(qq*4+0) * PADQ + row] = kv.x;
            Kt[(qq*4+1) * PADQ + row] = kv.y;
            Kt[(qq*4+2) * PADQ + row] = kv.z;
            Kt[(qq*4+3) * PADQ + row] = kv.w;
            float4 vv = *(const float4*)&Vg[(size_t)(kt * 128 + row) * 64 + qq * 4];
            *(float4*)&Vs[row * PADV + qq * 4] = vv;
        }
        __syncthreads();

        float acc[8][8];
#pragma unroll
        for (int i = 0; i < 8; i++)
#pragma unroll
            for (int j = 0; j < 8; j++) acc[i][j] = 0.f;

#pragma unroll 8
        for (int d = 0; d < 64; d++) {
            float a[8], bv[8];
            *(float4*)&a[0]  = *(const float4*)&Qt[d * PADQ + r0];
            *(float4*)&a[4]  = *(const float4*)&Qt[d * PADQ + r0 + 4];
            *(float4*)&bv[0] = *(const float4*)&Kt[d * PADQ + cA];
            *(float4*)&bv[4] = *(const float4*)&Kt[d * PADQ + 64 + cA];
#pragma unroll
            for (int i = 0; i < 8; i++)
#pragma unroll
                for (int j = 0; j < 8; j++) acc[i][j] += a[i] * bv[j];
        }

#pragma unroll
        for (int i = 0; i < 8; i++) {
            int r = r0 + i;
            const float* mrow = &Mg[(size_t)r * SS + kt * 128];
            float4 m0 = *(const float4*)&mrow[cA];
            float4 m1 = *(const float4*)&mrow[64 + cA];
            float4 s0 = make_float4(acc[i][0]*0.125f*m0.x, acc[i][1]*0.125f*m0.y,
                                    acc[i][2]*0.125f*m0.z, acc[i][3]*0.125f*m0.w);
            float4 s1 = make_float4(acc[i][4]*0.125f*m1.x, acc[i][5]*0.125f*m1.y,
                                    acc[i][6]*0.125f*m1.z, acc[i][7]*0.125f*m1.w);
            *(float4*)&Ps[r * PADP + cA]      = s0;
            *(float4*)&Ps[r * PADP + 64 + cA] = s1;
        }
        __syncthreads();

        {
            int row = t >> 1, hf = t & 1;
            float* prow = &Ps[row * PADP + hf * 64];
            float mx = -3.0e38f;
#pragma unroll
            for (int q = 0; q < 16; q++) {
                float4 v = ((const float4*)prow)[q];
                mx = fmaxf(mx, fmaxf(fmaxf(v.x, v.y), fmaxf(v.z, v.w)));
            }
            mx = fmaxf(mx, __shfl_xor_sync(0xffffffffu, mx, 1));
            float mold = sm_m[row];
            float mnew = fmaxf(mold, mx);
            float corr = __expf(mold - mnew);
            float ts = 0.f;
#pragma unroll
            for (int q = 0; q < 16; q++) {
                float4 v = ((const float4*)prow)[q];
                v.x = __expf(v.x - mnew); v.y = __expf(v.y - mnew);
                v.z = __expf(v.z - mnew); v.w = __expf(v.w - mnew);
                ((float4*)prow)[q] = v;
                ts += v.x + v.y + v.z + v.w;
            }
            ts += __shfl_xor_sync(0xffffffffu, ts, 1);
            if (hf == 0) {
                sm_m[row] = mnew;
                sm_l[row] = sm_l[row] * corr + ts;
                sm_corr[row] = corr;
            }
        }
        __syncthreads();

        float corr8[8];
#pragma unroll
        for (int i = 0; i < 8; i++) corr8[i] = sm_corr[r0 + i];
#pragma unroll
        for (int i = 0; i < 8; i++)
#pragma unroll
            for (int j = 0; j < 8; j++) o[i*8+j] *= corr8[i];

#pragma unroll 4
        for (int x = 0; x < 64; x++) {
            int kk = 2 * x + p;
            float pa[8], vb[8];
#pragma unroll
            for (int i = 0; i < 8; i++) pa[i] = Ps[(r0 + i) * PADP + kk];
            *(float4*)&vb[0] = *(const float4*)&Vs[kk * PADV + dA];
            *(float4*)&vb[4] = *(const float4*)&Vs[kk * PADV + 32 + dA];
#pragma unroll
            for (int i = 0; i < 8; i++)
#pragma unroll
                for (int j = 0; j < 8; j++) o[i*8+j] += pa[i] * vb[j];
        }
    }

    __syncthreads();
    if (p == 1) {
#pragma unroll
        for (int i = 0; i < 8; i++) {
            int r = r0 + i;
#pragma unroll
            for (int j = 0; j < 8; j++) {
                int dcol = (j < 4) ? (dA + j) : (32 + dA + j - 4);
                Ps[r * PADP + dcol] = o[i*8+j];
            }
        }
    }
    __syncthreads();
    if (p == 0) {
#pragma unroll
        for (int i = 0; i < 8; i++) {
            int r = r0 + i;
            float inv = 1.f / sm_l[r];
            float* og = &ctx[((size_t)b * SS + q0 + r) * HH + h * PHH];
            float4 o0, o1;
            o0.x = (o[i*8+0] + Ps[r*PADP + dA+0]) * inv;
            o0.y = (o[i*8+1] + Ps[r*PADP + dA+1]) * inv;
            o0.z = (o[i*8+2] + Ps[r*PADP + dA+2]) * inv;
            o0.w = (o[i*8+3] + Ps[r*PADP + dA+3]) * inv;
            o1.x = (o[i*8+4] + Ps[r*PADP + 32+dA+0]) * inv;
            o1.y = (o[i*8+5] + Ps[r*PADP + 32+dA+1]) * inv;
            o1.z = (o[i*8+6] + Ps[r*PADP + 32+dA+2]) * inv;
            o1.w = (o[i*8+7] + Ps[r*PADP + 32+dA+3]) * inv;
            *(float4*)&og[dA]      = o0;
            *(float4*)&og[32 + dA] = o1;
        }
    }
}

extern "C" void kernel_launch(void* const* d_in, const int* in_sizes, int n_in,
                              void* d_out, int out_size)
{
    const float* key   = (const float*)d_in[0];
    const float* value = (const float*)d_in[1];
    const float* query = (const float*)d_in[2];
    const float* mask  = (const float*)d_in[3];
    const float* Wq = (const float*)d_in[5];
    const float* bq = (const float*)d_in[6];
    const float* Wk = (const float*)d_in[7];
    const float* bk = (const float*)d_in[8];
    const float* Wv = (const float*)d_in[9];
    const float* bv = (const float*)d_in[10];
    const float* Wo = (const float*)d_in[11];
    const float* bo = (const float*)d_in[12];
    float* out = (float*)d_out;

    float *qp, *kp, *vp, *cp;
    cudaGetSymbolAddress((void**)&qp, g_q);
    cudaGetSymbolAddress((void**)&kp, g_k);
    cudaGetSymbolAddress((void**)&vp, g_v);
    cudaGetSymbolAddress((void**)&cp, g_ctx);

    __nv_bfloat16 *qh,*ql,*kh,*kl,*vh,*vl,*chp,*clp;
    __nv_bfloat16 *wqh,*wql,*wkh,*wkl,*wvh,*wvl,*woh,*wol;
    cudaGetSymbolAddress((void**)&qh, g_qh);  cudaGetSymbolAddress((void**)&ql, g_ql);
    cudaGetSymbolAddress((void**)&kh, g_kh);  cudaGetSymbolAddress((void**)&kl, g_kl);
    cudaGetSymbolAddress((void**)&vh, g_vh);  cudaGetSymbolAddress((void**)&vl, g_vl);
    cudaGetSymbolAddress((void**)&chp, g_ch); cudaGetSymbolAddress((void**)&clp, g_cl);
    cudaGetSymbolAddress((void**)&wqh, g_wqh); cudaGetSymbolAddress((void**)&wql, g_wql);
    cudaGetSymbolAddress((void**)&wkh, g_wkh); cudaGetSymbolAddress((void**)&wkl, g_wkl);
    cudaGetSymbolAddress((void**)&wvh, g_wvh); cudaGetSymbolAddress((void**)&wvl, g_wvl);
    cudaGetSymbolAddress((void**)&woh, g_woh); cudaGetSymbolAddress((void**)&wol, g_wol);

    int n4i = MM * KK / 4, n4w = HH * HH / 4;
    int gi = (n4i + 255) / 256, gw = (n4w + 255) / 256;
    split_convert<<<gi, 256>>>(query, qh, ql, n4i);
    split_convert<<<gi, 256>>>(key,   kh, kl, n4i);
    split_convert<<<gi, 256>>>(value, vh, vl, n4i);
    split_convert<<<gw, 256>>>(Wq, wqh, wql, n4w);
    split_convert<<<gw, 256>>>(Wk, wkh, wkl, n4w);
    split_convert<<<gw, 256>>>(Wv, wvh, wvl, n4w);
    split_convert<<<gw, 256>>>(Wo, woh, wol, n4w);

    cudaFuncSetAttribute(gemm_tc<true>,  cudaFuncAttributeMaxDynamicSharedMemorySize, G2_SMEM);
    cudaFuncSetAttribute(gemm_tc<false>, cudaFuncAttributeMaxDynamicSharedMemorySize, G2_SMEM);

    dim3 gg(HH / 128, MM / 128);
    gemm_tc<true><<<gg, 256, G2_SMEM>>>(qh, ql, wqh, wql, bq, qp);
    gemm_tc<true><<<gg, 256, G2_SMEM>>>(kh, kl, wkh, wkl, bk, kp);
    gemm_tc<true><<<gg, 256, G2_SMEM>>>(vh, vl, wvh, wvl, bv, vp);

    cudaFuncSetAttribute(attn2_kernel, cudaFuncAttributeMaxDynamicSharedMemorySize, ATTN2_SMEM);
    attn2_kernel<<<dim3(SS / 128, NHH, BB), 256, ATTN2_SMEM>>>(qp, kp, vp, mask, cp);

    split_convert<<<gi, 256>>>(cp, chp, clp, n4i);
    gemm_tc<false><<<gg, 256, G2_SMEM>>>(chp, clp, woh, wol, bo, out);
}

// round 9
// speedup vs baseline: 2.7630x; 2.0486x over previous
#include <cuda_runtime.h>
#include <cuda_bf16.h>
#include <cstdint>
#include <math.h>

#define BB   2
#define SS   2048
#define HH   1024
#define NHH  16
#define PHH  64
#define MM   (BB*SS)
#define KK   1024

// split-bf16 scratch
__device__ __nv_bfloat16 g_qh[MM*KK], g_ql[MM*KK];   // q,k,v in [b,h,s,d]
__device__ __nv_bfloat16 g_kh[MM*KK], g_kl[MM*KK];
__device__ __nv_bfloat16 g_vh[MM*KK], g_vl[MM*KK];
__device__ __nv_bfloat16 g_ch[MM*KK], g_cl[MM*KK];   // staging + ctx
__device__ __nv_bfloat16 g_wqh[HH*HH], g_wql[HH*HH];
__device__ __nv_bfloat16 g_wkh[HH*HH], g_wkl[HH*HH];
__device__ __nv_bfloat16 g_wvh[HH*HH], g_wvl[HH*HH];
__device__ __nv_bfloat16 g_woh[HH*HH], g_wol[HH*HH];

__device__ __forceinline__ uint32_t smem_u32(const void* p) {
    uint32_t a;
    asm("{ .reg .u64 t; cvta.to.shared.u64 t, %1; cvt.u32.u64 %0, t; }" : "=r"(a) : "l"(p));
    return a;
}
__device__ __forceinline__ void cp_async16(uint32_t s, const void* g) {
    asm volatile("cp.async.cg.shared.global [%0], [%1], 16;" :: "r"(s), "l"(g));
}
__device__ __forceinline__ void cp_commit() {
    asm volatile("cp.async.commit_group;" ::: "memory");
}
template<int N> __device__ __forceinline__ void cp_wait() {
    asm volatile("cp.async.wait_group %0;" :: "n"(N) : "memory");
}
__device__ __forceinline__ void ldsm_x4(uint32_t addr, uint32_t* r) {
    asm volatile("ldmatrix.sync.aligned.m8n8.x4.shared.b16 {%0,%1,%2,%3}, [%4];"
                 : "=r"(r[0]), "=r"(r[1]), "=r"(r[2]), "=r"(r[3]) : "r"(addr));
}
__device__ __forceinline__ void ldsm_x4_t(uint32_t addr, uint32_t* r) {
    asm volatile("ldmatrix.sync.aligned.m8n8.x4.trans.shared.b16 {%0,%1,%2,%3}, [%4];"
                 : "=r"(r[0]), "=r"(r[1]), "=r"(r[2]), "=r"(r[3]) : "r"(addr));
}
__device__ __forceinline__ void mma16816(float* d, const uint32_t* a, const uint32_t* b) {
    asm volatile("mma.sync.aligned.m16n8k16.row.col.f32.bf16.bf16.f32 "
        "{%0,%1,%2,%3}, {%4,%5,%6,%7}, {%8,%9}, {%0,%1,%2,%3};"
        : "+f"(d[0]), "+f"(d[1]), "+f"(d[2]), "+f"(d[3])
        : "r"(a[0]), "r"(a[1]), "r"(a[2]), "r"(a[3]), "r"(b[0]), "r"(b[1]));
}
__device__ __forceinline__ uint32_t bits2(__nv_bfloat162 v) {
    return *(uint32_t*)&v;
}

__global__ void split_convert(const float* __restrict__ src,
                              __nv_bfloat16* __restrict__ hi,
                              __nv_bfloat16* __restrict__ lo, int n4)
{
    int i = blockIdx.x * blockDim.x + threadIdx.x;
    if (i >= n4) return;
    float4 v = ((const float4*)src)[i];
    __nv_bfloat16 h0 = __float2bfloat16(v.x), h1 = __float2bfloat16(v.y);
    __nv_bfloat16 h2 = __float2bfloat16(v.z), h3 = __float2bfloat16(v.w);
    __nv_bfloat16 l0 = __float2bfloat16(v.x - __bfloat162float(h0));
    __nv_bfloat16 l1 = __float2bfloat16(v.y - __bfloat162float(h1));
    __nv_bfloat16 l2 = __float2bfloat16(v.z - __bfloat162float(h2));
    __nv_bfloat16 l3 = __float2bfloat16(v.w - __bfloat162float(h3));
    uint2 hv, lv;
    hv.x = (uint32_t)__bfloat16_as_ushort(h0) | ((uint32_t)__bfloat16_as_ushort(h1) << 16);
    hv.y = (uint32_t)__bfloat16_as_ushort(h2) | ((uint32_t)__bfloat16_as_ushort(h3) << 16);
    lv.x = (uint32_t)__bfloat16_as_ushort(l0) | ((uint32_t)__bfloat16_as_ushort(l1) << 16);
    lv.y = (uint32_t)__bfloat16_as_ushort(l2) | ((uint32_t)__bfloat16_as_ushort(l3) << 16);
    *(uint2*)(hi + (size_t)i * 4) = hv;
    *(uint2*)(lo + (size_t)i * 4) = lv;
}

// ---------------------------------------------------------------------------
// HMMA GEMM: 128x128 CTA tile, BK=64, 8 warps, split-bf16 3-term.
// ---------------------------------------------------------------------------
#define T_TILE 16384
#define G2_SMEM (2 * 4 * T_TILE)

__device__ __forceinline__ void prefetch_chunk(
    const __nv_bfloat16* __restrict__ Ah, const __nv_bfloat16* __restrict__ Al,
    const __nv_bfloat16* __restrict__ Wh, const __nv_bfloat16* __restrict__ Wl,
    int k0, uint32_t sbase, int tid)
{
    const __nv_bfloat16* srcs[4] = {Ah, Al, Wh, Wl};
#pragma unroll
    for (int t = 0; t < 4; t++) {
#pragma unroll
        for (int p = 0; p < 4; p++) {
            int idx = tid + p * 256;
            int row = idx >> 3, ch = idx & 7;
            uint32_t soff = sbase + t * T_TILE + row * 128 + ((ch ^ (row & 7)) << 4);
            cp_async16(soff, srcs[t] + (size_t)row * KK + k0 + ch * 8);
        }
    }
}

template<bool SPLITB16>
__global__ __launch_bounds__(256) void gemm_tc(
    const __nv_bfloat16* __restrict__ Ahi, const __nv_bfloat16* __restrict__ Alo,
    const __nv_bfloat16* __restrict__ Whi, const __nv_bfloat16* __restrict__ Wlo,
    const float* __restrict__ bias, float* __restrict__ C,
    __nv_bfloat16* __restrict__ Chi, __nv_bfloat16* __restrict__ Clo)
{
    extern __shared__ char smem[];
    const uint32_t sbase = smem_u32(smem);
    const int tid  = threadIdx.x;
    const int wid  = tid >> 5;
    const int lane = tid & 31;
    const int wm = wid >> 2;
    const int wn = wid & 3;
    const int bm = blockIdx.y * 128;
    const int bn = blockIdx.x * 128;

    const __nv_bfloat16* Ah = Ahi + (size_t)bm * KK;
    const __nv_bfloat16* Al = Alo + (size_t)bm * KK;
    const __nv_bfloat16* Wh = Whi + (size_t)bn * KK;
    const __nv_bfloat16* Wl = Wlo + (size_t)bn * KK;

    const int L7 = lane & 7;
    const int aSel = lane >> 4;
    const int bSel = (lane >> 3) & 1;
    uint32_t aRow[4], bRow[2];
#pragma unroll
    for (int mi = 0; mi < 4; mi++)
        aRow[mi] = (uint32_t)(wm * 64 + mi * 16 + (lane & 15)) * 128;
#pragma unroll
    for (int nb = 0; nb < 2; nb++)
        bRow[nb] = (uint32_t)(wn * 32 + nb * 16 + ((lane >> 4) * 8) + L7) * 128;

    float acc[4][4][4];
#pragma unroll
    for (int mi = 0; mi < 4; mi++)
#pragma unroll
        for (int nj = 0; nj < 4; nj++)
#pragma unroll
            for (int q = 0; q < 4; q++) acc[mi][nj][q] = 0.f;

    prefetch_chunk(Ah, Al, Wh, Wl, 0, sbase, tid);
    cp_commit();

    for (int it = 0; it < 16; it++) {
        if (it < 15) {
            prefetch_chunk(Ah, Al, Wh, Wl, (it + 1) * 64,
                           sbase + ((it + 1) & 1) * 4 * T_TILE, tid);
            cp_commit();
            cp_wait<1>();
        } else {
            cp_wait<0>();
        }
        __syncthreads();

        const uint32_t tb = sbase + (it & 1) * 4 * T_TILE;
#pragma unroll
        for (int ks = 0; ks < 4; ks++) {
            const int kx = ks * 2;
            uint32_t aH[4][4], aL[4][4], bH[2][4], bL[2][4];
#pragma unroll
            for (int mi = 0; mi < 4; mi++) {
                uint32_t ad = tb + aRow[mi] + (uint32_t)(((kx + aSel) ^ L7) << 4);
                ldsm_x4(ad + 0 * T_TILE, aH[mi]);
                ldsm_x4(ad + 1 * T_TILE, aL[mi]);
            }
#pragma unroll
            for (int nb = 0; nb < 2; nb++) {
                uint32_t bd = tb + bRow[nb] + (uint32_t)(((kx + bSel) ^ L7) << 4);
                ldsm_x4(bd + 2 * T_TILE, bH[nb]);
                ldsm_x4(bd + 3 * T_TILE, bL[nb]);
            }
#pragma unroll
            for (int mi = 0; mi < 4; mi++)
#pragma unroll
                for (int nj = 0; nj < 4; nj++) {
                    const uint32_t* fH = &bH[nj >> 1][(nj & 1) * 2];
                    const uint32_t* fL = &bL[nj >> 1][(nj & 1) * 2];
                    mma16816(acc[mi][nj], aH[mi], fH);
                    mma16816(acc[mi][nj], aH[mi], fL);
                    mma16816(acc[mi][nj], aL[mi], fH);
                }
        }
        __syncthreads();
    }

#pragma unroll
    for (int mi = 0; mi < 4; mi++)
#pragma unroll
        for (int nj = 0; nj < 4; nj++) {
            int row0 = bm + wm * 64 + mi * 16 + (lane >> 2);
            int col  = bn + wn * 32 + nj * 8 + (lane & 3) * 2;
            float b0 = bias[col], b1 = bias[col + 1];
#pragma unroll
            for (int half = 0; half < 2; half++) {
                int row = row0 + half * 8;
                float v0 = acc[mi][nj][half * 2 + 0] + b0;
                float v1 = acc[mi][nj][half * 2 + 1] + b1;
                if (SPLITB16) {
                    int b = row >> 11, s = row & 2047;
                    int h = col >> 6,  d = col & 63;
                    size_t idx = (((size_t)(b * NHH + h)) * SS + s) * PHH + d;
                    __nv_bfloat162 hv = __floats2bfloat162_rn(v0, v1);
                    float r0 = v0 - __bfloat162float(hv.x);
                    float r1 = v1 - __bfloat162float(hv.y);
                    __nv_bfloat162 lv = __floats2bfloat162_rn(r0, r1);
                    *(__nv_bfloat162*)&Chi[idx] = hv;
                    *(__nv_bfloat162*)&Clo[idx] = lv;
                } else {
                    *(float2*)&C[(size_t)row * HH + col] = make_float2(v0, v1);
                }
            }
        }
}

// ---------------------------------------------------------------------------
// HMMA flash attention, split-bf16, P kept in registers.
// ---------------------------------------------------------------------------
#define ATT_SMEM (2 * 4 * T_TILE)

__device__ __forceinline__ void attn_prefetch(
    const __nv_bfloat16* __restrict__ Kh, const __nv_bfloat16* __restrict__ Kl,
    const __nv_bfloat16* __restrict__ Vh, const __nv_bfloat16* __restrict__ Vl,
    int kt, uint32_t dst, int tid)
{
    const __nv_bfloat16* srcs[4] = {Kh, Kl, Vh, Vl};
#pragma unroll
    for (int t = 0; t < 4; t++) {
#pragma unroll
        for (int p = 0; p < 4; p++) {
            int idx = tid + p * 256;
            int row = idx >> 3, ch = idx & 7;
            uint32_t soff = dst + t * T_TILE + row * 128 + ((ch ^ (row & 7)) << 4);
            cp_async16(soff, srcs[t] + (size_t)(kt * 128 + row) * PHH + ch * 8);
        }
    }
}

__global__ __launch_bounds__(256) void attn3_kernel(
    const __nv_bfloat16* __restrict__ Qh, const __nv_bfloat16* __restrict__ Ql,
    const __nv_bfloat16* __restrict__ Kh, const __nv_bfloat16* __restrict__ Kl,
    const __nv_bfloat16* __restrict__ Vh, const __nv_bfloat16* __restrict__ Vl,
    const float* __restrict__ mask,
    __nv_bfloat16* __restrict__ Ch, __nv_bfloat16* __restrict__ Cl)
{
    extern __shared__ char smem[];
    const uint32_t sbase = smem_u32(smem);
    const int tid  = threadIdx.x;
    const int wid  = tid >> 5;
    const int lane = tid & 31;
    const int L7   = lane & 7;
    const int qt = blockIdx.x, h = blockIdx.y, b = blockIdx.z;
    const int q0 = qt * 128;

    const size_t hoff = ((size_t)(b * NHH + h)) * SS * PHH;
    const __nv_bfloat16* Qhg = Qh + hoff + (size_t)q0 * PHH;
    const __nv_bfloat16* Qlg = Ql + hoff + (size_t)q0 * PHH;
    const __nv_bfloat16* Khg = Kh + hoff;
    const __nv_bfloat16* Klg = Kl + hoff;
    const __nv_bfloat16* Vhg = Vh + hoff;
    const __nv_bfloat16* Vlg = Vl + hoff;
    const float* Mg = mask + (size_t)b * SS * SS + (size_t)q0 * SS;

    // stage Q in buf1 K-slots, extract A-fragments, release
    {
        uint32_t qb = sbase + 4 * T_TILE;
#pragma unroll
        for (int p = 0; p < 4; p++) {
            int idx = tid + p * 256;
            int row = idx >> 3, ch = idx & 7;
            uint32_t soff = qb + row * 128 + ((ch ^ (row & 7)) << 4);
            cp_async16(soff, Qhg + (size_t)row * PHH + ch * 8);
            cp_async16(soff + T_TILE, Qlg + (size_t)row * PHH + ch * 8);
        }
        cp_commit();
        cp_wait<0>();
        __syncthreads();
    }
    uint32_t qfH[4][4], qfL[4][4];
    {
        uint32_t qb = sbase + 4 * T_TILE;
        uint32_t aRow = (uint32_t)(wid * 16 + (lane & 15)) * 128;
        int aSel = lane >> 4;
#pragma unroll
        for (int ks = 0; ks < 4; ks++) {
            uint32_t ad = qb + aRow + (uint32_t)(((2 * ks + aSel) ^ L7) << 4);
            ldsm_x4(ad, qfH[ks]);
            ldsm_x4(ad + T_TILE, qfL[ks]);
        }
        __syncthreads();
    }

    float pv[8][4];
#pragma unroll
    for (int nj = 0; nj < 8; nj++)
#pragma unroll
        for (int q = 0; q < 4; q++) pv[nj][q] = 0.f;
    float mA = -1e30f, mB = -1e30f, lA = 0.f, lB = 0.f;

    const int rA = wid * 16 + (lane >> 2);
    const int rB = rA + 8;

    attn_prefetch(Khg, Klg, Vhg, Vlg, 0, sbase, tid);
    cp_commit();

    for (int kt = 0; kt < SS / 128; kt++) {
        if (kt < 15) {
            attn_prefetch(Khg, Klg, Vhg, Vlg, kt + 1,
                          sbase + ((kt + 1) & 1) * 4 * T_TILE, tid);
            cp_commit();
            cp_wait<1>();
        } else {
            cp_wait<0>();
        }
        __syncthreads();

        const uint32_t kb = sbase + (kt & 1) * 4 * T_TILE;

        float accS[16][4];
#pragma unroll
        for (int nj = 0; nj < 16; nj++)
#pragma unroll
            for (int q = 0; q < 4; q++) accS[nj][q] = 0.f;

#pragma unroll
        for (int ks = 0; ks < 4; ks++) {
#pragma unroll
            for (int jp = 0; jp < 8; jp++) {
                uint32_t row = (uint32_t)(jp * 16 + ((lane >> 4) * 8) + L7);
                uint32_t ad = kb + row * 128 +
                              (uint32_t)(((2 * ks + ((lane >> 3) & 1)) ^ L7) << 4);
                uint32_t bH[4], bL[4];
                ldsm_x4(ad, bH);
                ldsm_x4(ad + T_TILE, bL);
                mma16816(accS[2*jp],   qfH[ks], &bH[0]);
                mma16816(accS[2*jp],   qfH[ks], &bL[0]);
                mma16816(accS[2*jp],   qfL[ks], &bH[0]);
                mma16816(accS[2*jp+1], qfH[ks], &bH[2]);
                mma16816(accS[2*jp+1], qfH[ks], &bL[2]);
                mma16816(accS[2*jp+1], qfL[ks], &bH[2]);
            }
        }

        {
            const int colb = kt * 128 + (lane & 3) * 2;
#pragma unroll
            for (int nj = 0; nj < 16; nj++) {
                float2 ma = *(const float2*)&Mg[(size_t)rA * SS + colb + nj * 8];
                float2 mb = *(const float2*)&Mg[(size_t)rB * SS + colb + nj * 8];
                accS[nj][0] *= 0.125f * ma.x;
                accS[nj][1] *= 0.125f * ma.y;
                accS[nj][2] *= 0.125f * mb.x;
                accS[nj][3] *= 0.125f * mb.y;
            }
        }
        float mxA = -1e30f, mxB = -1e30f;
#pragma unroll
        for (int nj = 0; nj < 16; nj++) {
            mxA = fmaxf(mxA, fmaxf(accS[nj][0], accS[nj][1]));
            mxB = fmaxf(mxB, fmaxf(accS[nj][2], accS[nj][3]));
        }
        mxA = fmaxf(mxA, __shfl_xor_sync(0xffffffffu, mxA, 1));
        mxA = fmaxf(mxA, __shfl_xor_sync(0xffffffffu, mxA, 2));
        mxB = fmaxf(mxB, __shfl_xor_sync(0xffffffffu, mxB, 1));
        mxB = fmaxf(mxB, __shfl_xor_sync(0xffffffffu, mxB, 2));
        float mnA = fmaxf(mA, mxA), mnB = fmaxf(mB, mxB);
        float corrA = __expf(mA - mnA), corrB = __expf(mB - mnB);
        float tsA = 0.f, tsB = 0.f;
#pragma unroll
        for (int nj = 0; nj < 16; nj++) {
            accS[nj][0] = __expf(accS[nj][0] - mnA);
            accS[nj][1] = __expf(accS[nj][1] - mnA);
            accS[nj][2] = __expf(accS[nj][2] - mnB);
            accS[nj][3] = __expf(accS[nj][3] - mnB);
            tsA += accS[nj][0] + accS[nj][1];
            tsB += accS[nj][2] + accS[nj][3];
        }
        tsA += __shfl_xor_sync(0xffffffffu, tsA, 1);
        tsA += __shfl_xor_sync(0xffffffffu, tsA, 2);
        tsB += __shfl_xor_sync(0xffffffffu, tsB, 1);
        tsB += __shfl_xor_sync(0xffffffffu, tsB, 2);
        lA = lA * corrA + tsA;
        lB = lB * corrB + tsB;
        mA = mnA; mB = mnB;

#pragma unroll
        for (int nj = 0; nj < 8; nj++) {
            pv[nj][0] *= corrA; pv[nj][1] *= corrA;
            pv[nj][2] *= corrB; pv[nj][3] *= corrB;
        }

        const uint32_t vb = kb + 2 * T_TILE;
#pragma unroll
        for (int ks = 0; ks < 8; ks++) {
            const float* s0 = accS[2*ks];
            const float* s1 = accS[2*ks+1];
            __nv_bfloat162 h0 = __floats2bfloat162_rn(s0[0], s0[1]);
            __nv_bfloat162 h1 = __floats2bfloat162_rn(s0[2], s0[3]);
            __nv_bfloat162 h2 = __floats2bfloat162_rn(s1[0], s1[1]);
            __nv_bfloat162 h3 = __floats2bfloat162_rn(s1[2], s1[3]);
            uint32_t aPH[4] = {bits2(h0), bits2(h1), bits2(h2), bits2(h3)};
            __nv_bfloat162 e0 = __floats2bfloat162_rn(s0[0] - __bfloat162float(h0.x),
                                                      s0[1] - __bfloat162float(h0.y));
            __nv_bfloat162 e1 = __floats2bfloat162_rn(s0[2] - __bfloat162float(h1.x),
                                                      s0[3] - __bfloat162float(h1.y));
            __nv_bfloat162 e2 = __floats2bfloat162_rn(s1[0] - __bfloat162float(h2.x),
                                                      s1[1] - __bfloat162float(h2.y));
            __nv_bfloat162 e3 = __floats2bfloat162_rn(s1[2] - __bfloat162float(h3.x),
                                                      s1[3] - __bfloat162float(h3.y));
            uint32_t aPL[4] = {bits2(e0), bits2(e1), bits2(e2), bits2(e3)};

            uint32_t row = (uint32_t)(ks * 16 + (lane & 15));
#pragma unroll
            for (int jp = 0; jp < 4; jp++) {
                uint32_t ad = vb + row * 128 +
                              (uint32_t)(((2 * jp + (lane >> 4)) ^ L7) << 4);
                uint32_t vH[4], vL[4];
                ldsm_x4_t(ad, vH);
                ldsm_x4_t(ad + T_TILE, vL);
                mma16816(pv[2*jp],   aPH, &vH[0]);
                mma16816(pv[2*jp],   aPH, &vL[0]);
                mma16816(pv[2*jp],   aPL, &vH[0]);
                mma16816(pv[2*jp+1], aPH, &vH[2]);
                mma16816(pv[2*jp+1], aPH, &vL[2]);
                mma16816(pv[2*jp+1], aPL, &vH[2]);
            }
        }
        __syncthreads();
    }

    const float invA = 1.f / lA, invB = 1.f / lB;
    const int gA = q0 + rA, gB = q0 + rB;
#pragma unroll
    for (int nj = 0; nj < 8; nj++) {
        int d = nj * 8 + (lane & 3) * 2;
        float v0 = pv[nj][0] * invA, v1 = pv[nj][1] * invA;
        float v2 = pv[nj][2] * invB, v3 = pv[nj][3] * invB;
        size_t iA = ((size_t)b * SS + gA) * HH + h * PHH + d;
        size_t iB = ((size_t)b * SS + gB) * HH + h * PHH + d;
        __nv_bfloat162 hA = __floats2bfloat162_rn(v0, v1);
        __nv_bfloat162 lAv = __floats2bfloat162_rn(v0 - __bfloat162float(hA.x),
                                                   v1 - __bfloat162float(hA.y));
        __nv_bfloat162 hB = __floats2bfloat162_rn(v2, v3);
        __nv_bfloat162 lBv = __floats2bfloat162_rn(v2 - __bfloat162float(hB.x),
                                                   v3 - __bfloat162float(hB.y));
        *(__nv_bfloat162*)&Ch[iA] = hA;
        *(__nv_bfloat162*)&Cl[iA] = lAv;
        *(__nv_bfloat162*)&Ch[iB] = hB;
        *(__nv_bfloat162*)&Cl[iB] = lBv;
    }
}

extern "C" void kernel_launch(void* const* d_in, const int* in_sizes, int n_in,
                              void* d_out, int out_size)
{
    const float* key   = (const float*)d_in[0];
    const float* value = (const float*)d_in[1];
    const float* query = (const float*)d_in[2];
    const float* mask  = (const float*)d_in[3];
    const float* Wq = (const float*)d_in[5];
    const float* bq = (const float*)d_in[6];
    const float* Wk = (const float*)d_in[7];
    const float* bk = (const float*)d_in[8];
    const float* Wv = (const float*)d_in[9];
    const float* bv = (const float*)d_in[10];
    const float* Wo = (const float*)d_in[11];
    const float* bo = (const float*)d_in[12];
    float* out = (float*)d_out;

    __nv_bfloat16 *qh,*ql,*kh,*kl,*vh,*vl,*chp,*clp;
    __nv_bfloat16 *wqh,*wql,*wkh,*wkl,*wvh,*wvl,*woh,*wol;
    cudaGetSymbolAddress((void**)&qh, g_qh);  cudaGetSymbolAddress((void**)&ql, g_ql);
    cudaGetSymbolAddress((void**)&kh, g_kh);  cudaGetSymbolAddress((void**)&kl, g_kl);
    cudaGetSymbolAddress((void**)&vh, g_vh);  cudaGetSymbolAddress((void**)&vl, g_vl);
    cudaGetSymbolAddress((void**)&chp, g_ch); cudaGetSymbolAddress((void**)&clp, g_cl);
    cudaGetSymbolAddress((void**)&wqh, g_wqh); cudaGetSymbolAddress((void**)&wql, g_wql);
    cudaGetSymbolAddress((void**)&wkh, g_wkh); cudaGetSymbolAddress((void**)&wkl, g_wkl);
    cudaGetSymbolAddress((void**)&wvh, g_wvh); cudaGetSymbolAddress((void**)&wvl, g_wvl);
    cudaGetSymbolAddress((void**)&woh, g_woh); cudaGetSymbolAddress((void**)&wol, g_wol);

    int n4i = MM * KK / 4, n4w = HH * HH / 4;
    int gi = (n4i + 255) / 256, gw = (n4w + 255) / 256;

    split_convert<<<gw, 256>>>(Wq, wqh, wql, n4w);
    split_convert<<<gw, 256>>>(Wk, wkh, wkl, n4w);
    split_convert<<<gw, 256>>>(Wv, wvh, wvl, n4w);
    split_convert<<<gw, 256>>>(Wo, woh, wol, n4w);

    cudaFuncSetAttribute(gemm_tc<true>,  cudaFuncAttributeMaxDynamicSharedMemorySize, G2_SMEM);
    cudaFuncSetAttribute(gemm_tc<false>, cudaFuncAttributeMaxDynamicSharedMemorySize, G2_SMEM);

    dim3 gg(HH / 128, MM / 128);
    // stage each input in ch/cl, project into split-bf16 [b,h,s,d]
    split_convert<<<gi, 256>>>(query, chp, clp, n4i);
    gemm_tc<true><<<gg, 256, G2_SMEM>>>(chp, clp, wqh, wql, bq, nullptr, qh, ql);
    split_convert<<<gi, 256>>>(key, chp, clp, n4i);
    gemm_tc<true><<<gg, 256, G2_SMEM>>>(chp, clp, wkh, wkl, bk, nullptr, kh, kl);
    split_convert<<<gi, 256>>>(value, chp, clp, n4i);
    gemm_tc<true><<<gg, 256, G2_SMEM>>>(chp, clp, wvh, wvl, bv, nullptr, vh, vl);

    cudaFuncSetAttribute(attn3_kernel, cudaFuncAttributeMaxDynamicSharedMemorySize, ATT_SMEM);
    attn3_kernel<<<dim3(SS / 128, NHH, BB), 256, ATT_SMEM>>>(
        qh, ql, kh, kl, vh, vl, mask, chp, clp);

    gemm_tc<false><<<gg, 256, G2_SMEM>>>(chp, clp, woh, wol, bo, out, nullptr, nullptr);
}

// round 10
// speedup vs baseline: 2.8776x; 1.0415x over previous
#include <cuda_runtime.h>
#include <cuda_bf16.h>
#include <cstdint>
#include <math.h>

#define BB   2
#define SS   2048
#define HH   1024
#define NHH  16
#define PHH  64
#define MM   (BB*SS)
#define KK   1024

// split-bf16 scratch
__device__ __nv_bfloat16 g_qh[MM*KK], g_ql[MM*KK];   // q,k,v in [b,h,s,d]
__device__ __nv_bfloat16 g_kh[MM*KK], g_kl[MM*KK];
__device__ __nv_bfloat16 g_vh[MM*KK], g_vl[MM*KK];
__device__ __nv_bfloat16 g_ch[MM*KK], g_cl[MM*KK];   // ctx
// input staging (one per projection so converts don't serialize with GEMMs)
__device__ __nv_bfloat16 g_sqh[MM*KK], g_sql[MM*KK];
__device__ __nv_bfloat16 g_skh[MM*KK], g_skl[MM*KK];
__device__ __nv_bfloat16 g_svh[MM*KK], g_svl[MM*KK];
__device__ __nv_bfloat16 g_wqh[HH*HH], g_wql[HH*HH];
__device__ __nv_bfloat16 g_wkh[HH*HH], g_wkl[HH*HH];
__device__ __nv_bfloat16 g_wvh[HH*HH], g_wvl[HH*HH];
__device__ __nv_bfloat16 g_woh[HH*HH], g_wol[HH*HH];

__device__ __forceinline__ uint32_t smem_u32(const void* p) {
    uint32_t a;
    asm("{ .reg .u64 t; cvta.to.shared.u64 t, %1; cvt.u32.u64 %0, t; }" : "=r"(a) : "l"(p));
    return a;
}
__device__ __forceinline__ void cp_async16(uint32_t s, const void* g) {
    asm volatile("cp.async.cg.shared.global [%0], [%1], 16;" :: "r"(s), "l"(g));
}
__device__ __forceinline__ void cp_commit() {
    asm volatile("cp.async.commit_group;" ::: "memory");
}
template<int N> __device__ __forceinline__ void cp_wait() {
    asm volatile("cp.async.wait_group %0;" :: "n"(N) : "memory");
}
__device__ __forceinline__ void ldsm_x4(uint32_t addr, uint32_t* r) {
    asm volatile("ldmatrix.sync.aligned.m8n8.x4.shared.b16 {%0,%1,%2,%3}, [%4];"
                 : "=r"(r[0]), "=r"(r[1]), "=r"(r[2]), "=r"(r[3]) : "r"(addr));
}
__device__ __forceinline__ void ldsm_x4_t(uint32_t addr, uint32_t* r) {
    asm volatile("ldmatrix.sync.aligned.m8n8.x4.trans.shared.b16 {%0,%1,%2,%3}, [%4];"
                 : "=r"(r[0]), "=r"(r[1]), "=r"(r[2]), "=r"(r[3]) : "r"(addr));
}
__device__ __forceinline__ void mma16816(float* d, const uint32_t* a, const uint32_t* b) {
    asm volatile("mma.sync.aligned.m16n8k16.row.col.f32.bf16.bf16.f32 "
        "{%0,%1,%2,%3}, {%4,%5,%6,%7}, {%8,%9}, {%0,%1,%2,%3};"
        : "+f"(d[0]), "+f"(d[1]), "+f"(d[2]), "+f"(d[3])
        : "r"(a[0]), "r"(a[1]), "r"(a[2]), "r"(a[3]), "r"(b[0]), "r"(b[1]));
}
__device__ __forceinline__ uint32_t bits2(__nv_bfloat162 v) {
    return *(uint32_t*)&v;
}

// ---------------------------------------------------------------------------
// Fused split-convert: 7 arrays in one launch.
// Jobs 0-2: inputs (n4 = 1048576, 4096 blocks each); jobs 3-6: weights
// (n4 = 262144, 1024 blocks each). Total 16384 blocks.
// ---------------------------------------------------------------------------
struct Cvt7 {
    const float* src[7];
    __nv_bfloat16* hi[7];
    __nv_bfloat16* lo[7];
};

__global__ __launch_bounds__(256) void convert_all(Cvt7 jobs)
{
    int bid = blockIdx.x;
    int j, base;
    if (bid < 12288) { j = bid >> 12;            base = bid & 4095; }
    else             { j = 3 + ((bid - 12288) >> 10); base = (bid - 12288) & 1023; }
    int i = base * 256 + threadIdx.x;

    float4 v = ((const float4*)jobs.src[j])[i];
    __nv_bfloat16 h0 = __float2bfloat16(v.x), h1 = __float2bfloat16(v.y);
    __nv_bfloat16 h2 = __float2bfloat16(v.z), h3 = __float2bfloat16(v.w);
    __nv_bfloat16 l0 = __float2bfloat16(v.x - __bfloat162float(h0));
    __nv_bfloat16 l1 = __float2bfloat16(v.y - __bfloat162float(h1));
    __nv_bfloat16 l2 = __float2bfloat16(v.z - __bfloat162float(h2));
    __nv_bfloat16 l3 = __float2bfloat16(v.w - __bfloat162float(h3));
    uint2 hv, lv;
    hv.x = (uint32_t)__bfloat16_as_ushort(h0) | ((uint32_t)__bfloat16_as_ushort(h1) << 16);
    hv.y = (uint32_t)__bfloat16_as_ushort(h2) | ((uint32_t)__bfloat16_as_ushort(h3) << 16);
    lv.x = (uint32_t)__bfloat16_as_ushort(l0) | ((uint32_t)__bfloat16_as_ushort(l1) << 16);
    lv.y = (uint32_t)__bfloat16_as_ushort(l2) | ((uint32_t)__bfloat16_as_ushort(l3) << 16);
    *(uint2*)(jobs.hi[j] + (size_t)i * 4) = hv;
    *(uint2*)(jobs.lo[j] + (size_t)i * 4) = lv;
}

// ---------------------------------------------------------------------------
// HMMA GEMM core: 128x128 CTA tile, BK=64, 8 warps, split-bf16 3-term.
// ---------------------------------------------------------------------------
#define T_TILE 16384
#define G2_SMEM (2 * 4 * T_TILE)

__device__ __forceinline__ void prefetch_chunk(
    const __nv_bfloat16* __restrict__ Ah, const __nv_bfloat16* __restrict__ Al,
    const __nv_bfloat16* __restrict__ Wh, const __nv_bfloat16* __restrict__ Wl,
    int k0, uint32_t sbase, int tid)
{
    const __nv_bfloat16* srcs[4] = {Ah, Al, Wh, Wl};
#pragma unroll
    for (int t = 0; t < 4; t++) {
#pragma unroll
        for (int p = 0; p < 4; p++) {
            int idx = tid + p * 256;
            int row = idx >> 3, ch = idx & 7;
            uint32_t soff = sbase + t * T_TILE + row * 128 + ((ch ^ (row & 7)) << 4);
            cp_async16(soff, srcs[t] + (size_t)row * KK + k0 + ch * 8);
        }
    }
}

// shared mainloop; epilogue differs by template flag
template<bool SPLITB16>
__device__ __forceinline__ void gemm_body(
    const __nv_bfloat16* Ah, const __nv_bfloat16* Al,
    const __nv_bfloat16* Wh, const __nv_bfloat16* Wl,
    const float* bias, float* C,
    __nv_bfloat16* Chi, __nv_bfloat16* Clo,
    int bm, int bn, uint32_t sbase)
{
    const int tid  = threadIdx.x;
    const int wid  = tid >> 5;
    const int lane = tid & 31;
    const int wm = wid >> 2;
    const int wn = wid & 3;

    const int L7 = lane & 7;
    const int aSel = lane >> 4;
    const int bSel = (lane >> 3) & 1;
    uint32_t aRow[4], bRow[2];
#pragma unroll
    for (int mi = 0; mi < 4; mi++)
        aRow[mi] = (uint32_t)(wm * 64 + mi * 16 + (lane & 15)) * 128;
#pragma unroll
    for (int nb = 0; nb < 2; nb++)
        bRow[nb] = (uint32_t)(wn * 32 + nb * 16 + ((lane >> 4) * 8) + L7) * 128;

    float acc[4][4][4];
#pragma unroll
    for (int mi = 0; mi < 4; mi++)
#pragma unroll
        for (int nj = 0; nj < 4; nj++)
#pragma unroll
            for (int q = 0; q < 4; q++) acc[mi][nj][q] = 0.f;

    prefetch_chunk(Ah, Al, Wh, Wl, 0, sbase, tid);
    cp_commit();

    for (int it = 0; it < 16; it++) {
        if (it < 15) {
            prefetch_chunk(Ah, Al, Wh, Wl, (it + 1) * 64,
                           sbase + ((it + 1) & 1) * 4 * T_TILE, tid);
            cp_commit();
            cp_wait<1>();
        } else {
            cp_wait<0>();
        }
        __syncthreads();

        const uint32_t tb = sbase + (it & 1) * 4 * T_TILE;
#pragma unroll
        for (int ks = 0; ks < 4; ks++) {
            const int kx = ks * 2;
            uint32_t aH[4][4], aL[4][4], bH[2][4], bL[2][4];
#pragma unroll
            for (int mi = 0; mi < 4; mi++) {
                uint32_t ad = tb + aRow[mi] + (uint32_t)(((kx + aSel) ^ L7) << 4);
                ldsm_x4(ad + 0 * T_TILE, aH[mi]);
                ldsm_x4(ad + 1 * T_TILE, aL[mi]);
            }
#pragma unroll
            for (int nb = 0; nb < 2; nb++) {
                uint32_t bd = tb + bRow[nb] + (uint32_t)(((kx + bSel) ^ L7) << 4);
                ldsm_x4(bd + 2 * T_TILE, bH[nb]);
                ldsm_x4(bd + 3 * T_TILE, bL[nb]);
            }
#pragma unroll
            for (int mi = 0; mi < 4; mi++)
#pragma unroll
                for (int nj = 0; nj < 4; nj++) {
                    const uint32_t* fH = &bH[nj >> 1][(nj & 1) * 2];
                    const uint32_t* fL = &bL[nj >> 1][(nj & 1) * 2];
                    mma16816(acc[mi][nj], aH[mi], fH);
                    mma16816(acc[mi][nj], aH[mi], fL);
                    mma16816(acc[mi][nj], aL[mi], fH);
                }
        }
        __syncthreads();
    }

#pragma unroll
    for (int mi = 0; mi < 4; mi++)
#pragma unroll
        for (int nj = 0; nj < 4; nj++) {
            int row0 = bm + wm * 64 + mi * 16 + (lane >> 2);
            int col  = bn + wn * 32 + nj * 8 + (lane & 3) * 2;
            float b0 = bias[col], b1 = bias[col + 1];
#pragma unroll
            for (int half = 0; half < 2; half++) {
                int row = row0 + half * 8;
                float v0 = acc[mi][nj][half * 2 + 0] + b0;
                float v1 = acc[mi][nj][half * 2 + 1] + b1;
                if (SPLITB16) {
                    int b = row >> 11, s = row & 2047;
                    int h = col >> 6,  d = col & 63;
                    size_t idx = (((size_t)(b * NHH + h)) * SS + s) * PHH + d;
                    __nv_bfloat162 hv = __floats2bfloat162_rn(v0, v1);
                    float r0 = v0 - __bfloat162float(hv.x);
                    float r1 = v1 - __bfloat162float(hv.y);
                    __nv_bfloat162 lv = __floats2bfloat162_rn(r0, r1);
                    *(__nv_bfloat162*)&Chi[idx] = hv;
                    *(__nv_bfloat162*)&Clo[idx] = lv;
                } else {
                    *(float2*)&C[(size_t)row * HH + col] = make_float2(v0, v1);
                }
            }
        }
}

// fused q/k/v projections: blockIdx.z selects the projection
struct Gemm3 {
    const __nv_bfloat16 *Ah[3], *Al[3], *Wh[3], *Wl[3];
    const float* bias[3];
    __nv_bfloat16 *Ch[3], *Cl[3];
};

__global__ __launch_bounds__(256) void gemm_qkv(Gemm3 g)
{
    extern __shared__ char smem[];
    const uint32_t sbase = smem_u32(smem);
    const int z = blockIdx.z;
    const int bm = blockIdx.y * 128;
    const int bn = blockIdx.x * 128;
    gemm_body<true>(g.Ah[z] + (size_t)bm * KK, g.Al[z] + (size_t)bm * KK,
                    g.Wh[z] + (size_t)bn * KK, g.Wl[z] + (size_t)bn * KK,
                    g.bias[z], nullptr, g.Ch[z], g.Cl[z], bm, bn, sbase);
}

__global__ __launch_bounds__(256) void gemm_out(
    const __nv_bfloat16* __restrict__ Ahi, const __nv_bfloat16* __restrict__ Alo,
    const __nv_bfloat16* __restrict__ Whi, const __nv_bfloat16* __restrict__ Wlo,
    const float* __restrict__ bias, float* __restrict__ C)
{
    extern __shared__ char smem[];
    const uint32_t sbase = smem_u32(smem);
    const int bm = blockIdx.y * 128;
    const int bn = blockIdx.x * 128;
    gemm_body<false>(Ahi + (size_t)bm * KK, Alo + (size_t)bm * KK,
                     Whi + (size_t)bn * KK, Wlo + (size_t)bn * KK,
                     bias, C, nullptr, nullptr, bm, bn, sbase);
}

// ---------------------------------------------------------------------------
// HMMA flash attention, split-bf16, P in registers, mask prefetched to regs.
// ---------------------------------------------------------------------------
#define ATT_SMEM (2 * 4 * T_TILE)

__device__ __forceinline__ void attn_prefetch(
    const __nv_bfloat16* __restrict__ Kh, const __nv_bfloat16* __restrict__ Kl,
    const __nv_bfloat16* __restrict__ Vh, const __nv_bfloat16* __restrict__ Vl,
    int kt, uint32_t dst, int tid)
{
    const __nv_bfloat16* srcs[4] = {Kh, Kl, Vh, Vl};
#pragma unroll
    for (int t = 0; t < 4; t++) {
#pragma unroll
        for (int p = 0; p < 4; p++) {
            int idx = tid + p * 256;
            int row = idx >> 3, ch = idx & 7;
            uint32_t soff = dst + t * T_TILE + row * 128 + ((ch ^ (row & 7)) << 4);
            cp_async16(soff, srcs[t] + (size_t)(kt * 128 + row) * PHH + ch * 8);
        }
    }
}

__global__ __launch_bounds__(256) void attn3_kernel(
    const __nv_bfloat16* __restrict__ Qh, const __nv_bfloat16* __restrict__ Ql,
    const __nv_bfloat16* __restrict__ Kh, const __nv_bfloat16* __restrict__ Kl,
    const __nv_bfloat16* __restrict__ Vh, const __nv_bfloat16* __restrict__ Vl,
    const float* __restrict__ mask,
    __nv_bfloat16* __restrict__ Ch, __nv_bfloat16* __restrict__ Cl)
{
    extern __shared__ char smem[];
    const uint32_t sbase = smem_u32(smem);
    const int tid  = threadIdx.x;
    const int wid  = tid >> 5;
    const int lane = tid & 31;
    const int L7   = lane & 7;
    const int qt = blockIdx.x, h = blockIdx.y, b = blockIdx.z;
    const int q0 = qt * 128;

    const size_t hoff = ((size_t)(b * NHH + h)) * SS * PHH;
    const __nv_bfloat16* Qhg = Qh + hoff + (size_t)q0 * PHH;
    const __nv_bfloat16* Qlg = Ql + hoff + (size_t)q0 * PHH;
    const __nv_bfloat16* Khg = Kh + hoff;
    const __nv_bfloat16* Klg = Kl + hoff;
    const __nv_bfloat16* Vhg = Vh + hoff;
    const __nv_bfloat16* Vlg = Vl + hoff;
    const float* Mg = mask + (size_t)b * SS * SS + (size_t)q0 * SS;

    // stage Q in buf1 K-slots, extract A-fragments, release
    {
        uint32_t qb = sbase + 4 * T_TILE;
#pragma unroll
        for (int p = 0; p < 4; p++) {
            int idx = tid + p * 256;
            int row = idx >> 3, ch = idx & 7;
            uint32_t soff = qb + row * 128 + ((ch ^ (row & 7)) << 4);
            cp_async16(soff, Qhg + (size_t)row * PHH + ch * 8);
            cp_async16(soff + T_TILE, Qlg + (size_t)row * PHH + ch * 8);
        }
        cp_commit();
        cp_wait<0>();
        __syncthreads();
    }
    uint32_t qfH[4][4], qfL[4][4];
    {
        uint32_t qb = sbase + 4 * T_TILE;
        uint32_t aRow = (uint32_t)(wid * 16 + (lane & 15)) * 128;
        int aSel = lane >> 4;
#pragma unroll
        for (int ks = 0; ks < 4; ks++) {
            uint32_t ad = qb + aRow + (uint32_t)(((2 * ks + aSel) ^ L7) << 4);
            ldsm_x4(ad, qfH[ks]);
            ldsm_x4(ad + T_TILE, qfL[ks]);
        }
        __syncthreads();
    }

    float pv[8][4];
#pragma unroll
    for (int nj = 0; nj < 8; nj++)
#pragma unroll
        for (int q = 0; q < 4; q++) pv[nj][q] = 0.f;
    float mA = -1e30f, mB = -1e30f, lA = 0.f, lB = 0.f;

    const int rA = wid * 16 + (lane >> 2);
    const int rB = rA + 8;

    attn_prefetch(Khg, Klg, Vhg, Vlg, 0, sbase, tid);
    cp_commit();

    for (int kt = 0; kt < SS / 128; kt++) {
        // ---- mask prefetch: independent of smem pipeline, issued first ----
        float2 pmA[16], pmB[16];
        {
            const int colb = kt * 128 + (lane & 3) * 2;
            const float* mra = &Mg[(size_t)rA * SS + colb];
            const float* mrb = &Mg[(size_t)rB * SS + colb];
#pragma unroll
            for (int nj = 0; nj < 16; nj++) {
                pmA[nj] = *(const float2*)&mra[nj * 8];
                pmB[nj] = *(const float2*)&mrb[nj * 8];
            }
        }

        if (kt < 15) {
            attn_prefetch(Khg, Klg, Vhg, Vlg, kt + 1,
                          sbase + ((kt + 1) & 1) * 4 * T_TILE, tid);
            cp_commit();
            cp_wait<1>();
        } else {
            cp_wait<0>();
        }
        __syncthreads();

        const uint32_t kb = sbase + (kt & 1) * 4 * T_TILE;

        float accS[16][4];
#pragma unroll
        for (int nj = 0; nj < 16; nj++)
#pragma unroll
            for (int q = 0; q < 4; q++) accS[nj][q] = 0.f;

#pragma unroll
        for (int ks = 0; ks < 4; ks++) {
#pragma unroll
            for (int jp = 0; jp < 8; jp++) {
                uint32_t row = (uint32_t)(jp * 16 + ((lane >> 4) * 8) + L7);
                uint32_t ad = kb + row * 128 +
                              (uint32_t)(((2 * ks + ((lane >> 3) & 1)) ^ L7) << 4);
                uint32_t bH[4], bL[4];
                ldsm_x4(ad, bH);
                ldsm_x4(ad + T_TILE, bL);
                mma16816(accS[2*jp],   qfH[ks], &bH[0]);
                mma16816(accS[2*jp],   qfH[ks], &bL[0]);
                mma16816(accS[2*jp],   qfL[ks], &bH[0]);
                mma16816(accS[2*jp+1], qfH[ks], &bH[2]);
                mma16816(accS[2*jp+1], qfH[ks], &bL[2]);
                mma16816(accS[2*jp+1], qfL[ks], &bH[2]);
            }
        }

#pragma unroll
        for (int nj = 0; nj < 16; nj++) {
            accS[nj][0] *= 0.125f * pmA[nj].x;
            accS[nj][1] *= 0.125f * pmA[nj].y;
            accS[nj][2] *= 0.125f * pmB[nj].x;
            accS[nj][3] *= 0.125f * pmB[nj].y;
        }
        float mxA = -1e30f, mxB = -1e30f;
#pragma unroll
        for (int nj = 0; nj < 16; nj++) {
            mxA = fmaxf(mxA, fmaxf(accS[nj][0], accS[nj][1]));
            mxB = fmaxf(mxB, fmaxf(accS[nj][2], accS[nj][3]));
        }
        mxA = fmaxf(mxA, __shfl_xor_sync(0xffffffffu, mxA, 1));
        mxA = fmaxf(mxA, __shfl_xor_sync(0xffffffffu, mxA, 2));
        mxB = fmaxf(mxB, __shfl_xor_sync(0xffffffffu, mxB, 1));
        mxB = fmaxf(mxB, __shfl_xor_sync(0xffffffffu, mxB, 2));
        float mnA = fmaxf(mA, mxA), mnB = fmaxf(mB, mxB);
        float corrA = __expf(mA - mnA), corrB = __expf(mB - mnB);
        float tsA = 0.f, tsB = 0.f;
#pragma unroll
        for (int nj = 0; nj < 16; nj++) {
            accS[nj][0] = __expf(accS[nj][0] - mnA);
            accS[nj][1] = __expf(accS[nj][1] - mnA);
            accS[nj][2] = __expf(accS[nj][2] - mnB);
            accS[nj][3] = __expf(accS[nj][3] - mnB);
            tsA += accS[nj][0] + accS[nj][1];
            tsB += accS[nj][2] + accS[nj][3];
        }
        tsA += __shfl_xor_sync(0xffffffffu, tsA, 1);
        tsA += __shfl_xor_sync(0xffffffffu, tsA, 2);
        tsB += __shfl_xor_sync(0xffffffffu, tsB, 1);
        tsB += __shfl_xor_sync(0xffffffffu, tsB, 2);
        lA = lA * corrA + tsA;
        lB = lB * corrB + tsB;
        mA = mnA; mB = mnB;

#pragma unroll
        for (int nj = 0; nj < 8; nj++) {
            pv[nj][0] *= corrA; pv[nj][1] *= corrA;
            pv[nj][2] *= corrB; pv[nj][3] *= corrB;
        }

        const uint32_t vb = kb + 2 * T_TILE;
#pragma unroll
        for (int ks = 0; ks < 8; ks++) {
            const float* s0 = accS[2*ks];
            const float* s1 = accS[2*ks+1];
            __nv_bfloat162 h0 = __floats2bfloat162_rn(s0[0], s0[1]);
            __nv_bfloat162 h1 = __floats2bfloat162_rn(s0[2], s0[3]);
            __nv_bfloat162 h2 = __floats2bfloat162_rn(s1[0], s1[1]);
            __nv_bfloat162 h3 = __floats2bfloat162_rn(s1[2], s1[3]);
            uint32_t aPH[4] = {bits2(h0), bits2(h1), bits2(h2), bits2(h3)};
            __nv_bfloat162 e0 = __floats2bfloat162_rn(s0[0] - __bfloat162float(h0.x),
                                                      s0[1] - __bfloat162float(h0.y));
            __nv_bfloat162 e1 = __floats2bfloat162_rn(s0[2] - __bfloat162float(h1.x),
                                                      s0[3] - __bfloat162float(h1.y));
            __nv_bfloat162 e2 = __floats2bfloat162_rn(s1[0] - __bfloat162float(h2.x),
                                                      s1[1] - __bfloat162float(h2.y));
            __nv_bfloat162 e3 = __floats2bfloat162_rn(s1[2] - __bfloat162float(h3.x),
                                                      s1[3] - __bfloat162float(h3.y));
            uint32_t aPL[4] = {bits2(e0), bits2(e1), bits2(e2), bits2(e3)};

            uint32_t row = (uint32_t)(ks * 16 + (lane & 15));
#pragma unroll
            for (int jp = 0; jp < 4; jp++) {
                uint32_t ad = vb + row * 128 +
                              (uint32_t)(((2 * jp + (lane >> 4)) ^ L7) << 4);
                uint32_t vH[4], vL[4];
                ldsm_x4_t(ad, vH);
                ldsm_x4_t(ad + T_TILE, vL);
                mma16816(pv[2*jp],   aPH, &vH[0]);
                mma16816(pv[2*jp],   aPH, &vL[0]);
                mma16816(pv[2*jp],   aPL, &vH[0]);
                mma16816(pv[2*jp+1], aPH, &vH[2]);
                mma16816(pv[2*jp+1], aPH, &vL[2]);
                mma16816(pv[2*jp+1], aPL, &vH[2]);
            }
        }
        __syncthreads();
    }

    const float invA = 1.f / lA, invB = 1.f / lB;
    const int gA = q0 + rA, gB = q0 + rB;
#pragma unroll
    for (int nj = 0; nj < 8; nj++) {
        int d = nj * 8 + (lane & 3) * 2;
        float v0 = pv[nj][0] * invA, v1 = pv[nj][1] * invA;
        float v2 = pv[nj][2] * invB, v3 = pv[nj][3] * invB;
        size_t iA = ((size_t)b * SS + gA) * HH + h * PHH + d;
        size_t iB = ((size_t)b * SS + gB) * HH + h * PHH + d;
        __nv_bfloat162 hA = __floats2bfloat162_rn(v0, v1);
        __nv_bfloat162 lAv = __floats2bfloat162_rn(v0 - __bfloat162float(hA.x),
                                                   v1 - __bfloat162float(hA.y));
        __nv_bfloat162 hB = __floats2bfloat162_rn(v2, v3);
        __nv_bfloat162 lBv = __floats2bfloat162_rn(v2 - __bfloat162float(hB.x),
                                                   v3 - __bfloat162float(hB.y));
        *(__nv_bfloat162*)&Ch[iA] = hA;
        *(__nv_bfloat162*)&Cl[iA] = lAv;
        *(__nv_bfloat162*)&Ch[iB] = hB;
        *(__nv_bfloat162*)&Cl[iB] = lBv;
    }
}

extern "C" void kernel_launch(void* const* d_in, const int* in_sizes, int n_in,
                              void* d_out, int out_size)
{
    const float* key   = (const float*)d_in[0];
    const float* value = (const float*)d_in[1];
    const float* query = (const float*)d_in[2];
    const float* mask  = (const float*)d_in[3];
    const float* Wq = (const float*)d_in[5];
    const float* bq = (const float*)d_in[6];
    const float* Wk = (const float*)d_in[7];
    const float* bk = (const float*)d_in[8];
    const float* Wv = (const float*)d_in[9];
    const float* bv = (const float*)d_in[10];
    const float* Wo = (const float*)d_in[11];
    const float* bo = (const float*)d_in[12];
    float* out = (float*)d_out;

    __nv_bfloat16 *qh,*ql,*kh,*kl,*vh,*vl,*chp,*clp;
    __nv_bfloat16 *sqh,*sql,*skh,*skl,*svh,*svl;
    __nv_bfloat16 *wqh,*wql,*wkh,*wkl,*wvh,*wvl,*woh,*wol;
    cudaGetSymbolAddress((void**)&qh, g_qh);  cudaGetSymbolAddress((void**)&ql, g_ql);
    cudaGetSymbolAddress((void**)&kh, g_kh);  cudaGetSymbolAddress((void**)&kl, g_kl);
    cudaGetSymbolAddress((void**)&vh, g_vh);  cudaGetSymbolAddress((void**)&vl, g_vl);
    cudaGetSymbolAddress((void**)&chp, g_ch); cudaGetSymbolAddress((void**)&clp, g_cl);
    cudaGetSymbolAddress((void**)&sqh, g_sqh); cudaGetSymbolAddress((void**)&sql, g_sql);
    cudaGetSymbolAddress((void**)&skh, g_skh); cudaGetSymbolAddress((void**)&skl, g_skl);
    cudaGetSymbolAddress((void**)&svh, g_svh); cudaGetSymbolAddress((void**)&svl, g_svl);
    cudaGetSymbolAddress((void**)&wqh, g_wqh); cudaGetSymbolAddress((void**)&wql, g_wql);
    cudaGetSymbolAddress((void**)&wkh, g_wkh); cudaGetSymbolAddress((void**)&wkl, g_wkl);
    cudaGetSymbolAddress((void**)&wvh, g_wvh); cudaGetSymbolAddress((void**)&wvl, g_wvl);
    cudaGetSymbolAddress((void**)&woh, g_woh); cudaGetSymbolAddress((void**)&wol, g_wol);

    // 1) all converts in one launch
    Cvt7 cv;
    cv.src[0] = query; cv.hi[0] = sqh; cv.lo[0] = sql;
    cv.src[1] = key;   cv.hi[1] = skh; cv.lo[1] = skl;
    cv.src[2] = value; cv.hi[2] = svh; cv.lo[2] = svl;
    cv.src[3] = Wq; cv.hi[3] = wqh; cv.lo[3] = wql;
    cv.src[4] = Wk; cv.hi[4] = wkh; cv.lo[4] = wkl;
    cv.src[5] = Wv; cv.hi[5] = wvh; cv.lo[5] = wvl;
    cv.src[6] = Wo; cv.hi[6] = woh; cv.lo[6] = wol;
    convert_all<<<16384, 256>>>(cv);

    // 2) fused q/k/v projections
    Gemm3 g3;
    g3.Ah[0] = sqh; g3.Al[0] = sql; g3.Wh[0] = wqh; g3.Wl[0] = wql;
    g3.bias[0] = bq; g3.Ch[0] = qh; g3.Cl[0] = ql;
    g3.Ah[1] = skh; g3.Al[1] = skl; g3.Wh[1] = wkh; g3.Wl[1] = wkl;
    g3.bias[1] = bk; g3.Ch[1] = kh; g3.Cl[1] = kl;
    g3.Ah[2] = svh; g3.Al[2] = svl; g3.Wh[2] = wvh; g3.Wl[2] = wvl;
    g3.bias[2] = bv; g3.Ch[2] = vh; g3.Cl[2] = vl;

    cudaFuncSetAttribute(gemm_qkv, cudaFuncAttributeMaxDynamicSharedMemorySize, G2_SMEM);
    cudaFuncSetAttribute(gemm_out, cudaFuncAttributeMaxDynamicSharedMemorySize, G2_SMEM);
    gemm_qkv<<<dim3(HH / 128, MM / 128, 3), 256, G2_SMEM>>>(g3);

    // 3) attention
    cudaFuncSetAttribute(attn3_kernel, cudaFuncAttributeMaxDynamicSharedMemorySize, ATT_SMEM);
    attn3_kernel<<<dim3(SS / 128, NHH, BB), 256, ATT_SMEM>>>(
        qh, ql, kh, kl, vh, vl, mask, chp, clp);

    // 4) output projection
    gemm_out<<<dim3(HH / 128, MM / 128), 256, G2_SMEM>>>(chp, clp, woh, wol, bo, out);
}

// round 11
// speedup vs baseline: 3.0621x; 1.0641x over previous
#include <cuda_runtime.h>
#include <cuda_bf16.h>
#include <cstdint>
#include <math.h>

#define BB   2
#define SS   2048
#define HH   1024
#define NHH  16
#define PHH  64
#define MM   (BB*SS)
#define KK   1024

// split-bf16 scratch
__device__ __nv_bfloat16 g_qh[MM*KK], g_ql[MM*KK];   // q,k,v in [b,h,s,d]
__device__ __nv_bfloat16 g_kh[MM*KK], g_kl[MM*KK];
__device__ __nv_bfloat16 g_vh[MM*KK], g_vl[MM*KK];
__device__ __nv_bfloat16 g_ch[MM*KK], g_cl[MM*KK];   // ctx
__device__ __nv_bfloat16 g_sqh[MM*KK], g_sql[MM*KK]; // input staging
__device__ __nv_bfloat16 g_skh[MM*KK], g_skl[MM*KK];
__device__ __nv_bfloat16 g_svh[MM*KK], g_svl[MM*KK];
__device__ __nv_bfloat16 g_wqh[HH*HH], g_wql[HH*HH];
__device__ __nv_bfloat16 g_wkh[HH*HH], g_wkl[HH*HH];
__device__ __nv_bfloat16 g_wvh[HH*HH], g_wvl[HH*HH];
__device__ __nv_bfloat16 g_woh[HH*HH], g_wol[HH*HH];

__device__ __forceinline__ uint32_t smem_u32(const void* p) {
    uint32_t a;
    asm("{ .reg .u64 t; cvta.to.shared.u64 t, %1; cvt.u32.u64 %0, t; }" : "=r"(a) : "l"(p));
    return a;
}
__device__ __forceinline__ void cp_async16(uint32_t s, const void* g) {
    asm volatile("cp.async.cg.shared.global [%0], [%1], 16;" :: "r"(s), "l"(g));
}
__device__ __forceinline__ void cp_commit() {
    asm volatile("cp.async.commit_group;" ::: "memory");
}
template<int N> __device__ __forceinline__ void cp_wait() {
    asm volatile("cp.async.wait_group %0;" :: "n"(N) : "memory");
}
__device__ __forceinline__ void ldsm_x4(uint32_t addr, uint32_t* r) {
    asm volatile("ldmatrix.sync.aligned.m8n8.x4.shared.b16 {%0,%1,%2,%3}, [%4];"
                 : "=r"(r[0]), "=r"(r[1]), "=r"(r[2]), "=r"(r[3]) : "r"(addr));
}
__device__ __forceinline__ void ldsm_x4_t(uint32_t addr, uint32_t* r) {
    asm volatile("ldmatrix.sync.aligned.m8n8.x4.trans.shared.b16 {%0,%1,%2,%3}, [%4];"
                 : "=r"(r[0]), "=r"(r[1]), "=r"(r[2]), "=r"(r[3]) : "r"(addr));
}
__device__ __forceinline__ void mma16816(float* d, const uint32_t* a, const uint32_t* b) {
    asm volatile("mma.sync.aligned.m16n8k16.row.col.f32.bf16.bf16.f32 "
        "{%0,%1,%2,%3}, {%4,%5,%6,%7}, {%8,%9}, {%0,%1,%2,%3};"
        : "+f"(d[0]), "+f"(d[1]), "+f"(d[2]), "+f"(d[3])
        : "r"(a[0]), "r"(a[1]), "r"(a[2]), "r"(a[3]), "r"(b[0]), "r"(b[1]));
}
__device__ __forceinline__ uint32_t bits2(__nv_bfloat162 v) {
    return *(uint32_t*)&v;
}

// ---------------------------------------------------------------------------
// Fused split-convert: 7 arrays in one launch.
// ---------------------------------------------------------------------------
struct Cvt7 {
    const float* src[7];
    __nv_bfloat16* hi[7];
    __nv_bfloat16* lo[7];
};

__global__ __launch_bounds__(256) void convert_all(Cvt7 jobs)
{
    int bid = blockIdx.x;
    int j, base;
    if (bid < 12288) { j = bid >> 12;            base = bid & 4095; }
    else             { j = 3 + ((bid - 12288) >> 10); base = (bid - 12288) & 1023; }
    int i = base * 256 + threadIdx.x;

    float4 v = ((const float4*)jobs.src[j])[i];
    __nv_bfloat16 h0 = __float2bfloat16(v.x), h1 = __float2bfloat16(v.y);
    __nv_bfloat16 h2 = __float2bfloat16(v.z), h3 = __float2bfloat16(v.w);
    __nv_bfloat16 l0 = __float2bfloat16(v.x - __bfloat162float(h0));
    __nv_bfloat16 l1 = __float2bfloat16(v.y - __bfloat162float(h1));
    __nv_bfloat16 l2 = __float2bfloat16(v.z - __bfloat162float(h2));
    __nv_bfloat16 l3 = __float2bfloat16(v.w - __bfloat162float(h3));
    uint2 hv, lv;
    hv.x = (uint32_t)__bfloat16_as_ushort(h0) | ((uint32_t)__bfloat16_as_ushort(h1) << 16);
    hv.y = (uint32_t)__bfloat16_as_ushort(h2) | ((uint32_t)__bfloat16_as_ushort(h3) << 16);
    lv.x = (uint32_t)__bfloat16_as_ushort(l0) | ((uint32_t)__bfloat16_as_ushort(l1) << 16);
    lv.y = (uint32_t)__bfloat16_as_ushort(l2) | ((uint32_t)__bfloat16_as_ushort(l3) << 16);
    *(uint2*)(jobs.hi[j] + (size_t)i * 4) = hv;
    *(uint2*)(jobs.lo[j] + (size_t)i * 4) = lv;
}

// ---------------------------------------------------------------------------
// HMMA GEMM: CTA tile 128(M)x64(N), BK=64, 8 warps (warp tile 32x32),
// split-bf16 3-term, 96KB smem -> 2 CTAs/SM.
// Stage layout: [Ah 16K | Al 16K | Wh 8K | Wl 8K], x2 buffers.
// ---------------------------------------------------------------------------
#define GA_TILE 16384
#define GW_TILE 8192
#define G_STAGE (2*GA_TILE + 2*GW_TILE)   // 49152
#define G3_SMEM (2 * G_STAGE)             // 98304

__device__ __forceinline__ void prefetch_g(
    const __nv_bfloat16* __restrict__ Ah, const __nv_bfloat16* __restrict__ Al,
    const __nv_bfloat16* __restrict__ Wh, const __nv_bfloat16* __restrict__ Wl,
    int k0, uint32_t stage, int tid)
{
    // A tiles: 128 rows
#pragma unroll
    for (int t = 0; t < 2; t++) {
        const __nv_bfloat16* src = t ? Al : Ah;
        uint32_t base = stage + t * GA_TILE;
#pragma unroll
        for (int p = 0; p < 4; p++) {
            int idx = tid + p * 256;
            int row = idx >> 3, ch = idx & 7;
            cp_async16(base + row * 128 + ((ch ^ (row & 7)) << 4),
                       src + (size_t)row * KK + k0 + ch * 8);
        }
    }
    // W tiles: 64 rows
#pragma unroll
    for (int t = 0; t < 2; t++) {
        const __nv_bfloat16* src = t ? Wl : Wh;
        uint32_t base = stage + 2 * GA_TILE + t * GW_TILE;
#pragma unroll
        for (int p = 0; p < 2; p++) {
            int idx = tid + p * 256;
            int row = idx >> 3, ch = idx & 7;
            cp_async16(base + row * 128 + ((ch ^ (row & 7)) << 4),
                       src + (size_t)row * KK + k0 + ch * 8);
        }
    }
}

template<bool SPLITB16>
__device__ __forceinline__ void gemm_body(
    const __nv_bfloat16* Ah, const __nv_bfloat16* Al,
    const __nv_bfloat16* Wh, const __nv_bfloat16* Wl,
    const float* bias, float* C,
    __nv_bfloat16* Chi, __nv_bfloat16* Clo,
    int bm, int bn, uint32_t sbase)
{
    const int tid  = threadIdx.x;
    const int wid  = tid >> 5;
    const int lane = tid & 31;
    const int wm = wid >> 1;        // 0..3
    const int wn = wid & 1;         // 0..1

    const int L7 = lane & 7;
    const int aSel = lane >> 4;
    const int bSel = (lane >> 3) & 1;
    uint32_t aRow[2], bRow[2];
#pragma unroll
    for (int mi = 0; mi < 2; mi++)
        aRow[mi] = (uint32_t)(wm * 32 + mi * 16 + (lane & 15)) * 128;
#pragma unroll
    for (int nb = 0; nb < 2; nb++)
        bRow[nb] = (uint32_t)(wn * 32 + nb * 16 + ((lane >> 4) * 8) + L7) * 128;

    float acc[2][4][4];
#pragma unroll
    for (int mi = 0; mi < 2; mi++)
#pragma unroll
        for (int nj = 0; nj < 4; nj++)
#pragma unroll
            for (int q = 0; q < 4; q++) acc[mi][nj][q] = 0.f;

    prefetch_g(Ah, Al, Wh, Wl, 0, sbase, tid);
    cp_commit();

    for (int it = 0; it < 16; it++) {
        if (it < 15) {
            prefetch_g(Ah, Al, Wh, Wl, (it + 1) * 64,
                       sbase + ((it + 1) & 1) * G_STAGE, tid);
            cp_commit();
            cp_wait<1>();
        } else {
            cp_wait<0>();
        }
        __syncthreads();

        const uint32_t tb = sbase + (it & 1) * G_STAGE;
#pragma unroll
        for (int ks = 0; ks < 4; ks++) {
            const int kx = ks * 2;
            uint32_t aH[2][4], aL[2][4], bH[2][4], bL[2][4];
#pragma unroll
            for (int mi = 0; mi < 2; mi++) {
                uint32_t ad = tb + aRow[mi] + (uint32_t)(((kx + aSel) ^ L7) << 4);
                ldsm_x4(ad, aH[mi]);
                ldsm_x4(ad + GA_TILE, aL[mi]);
            }
#pragma unroll
            for (int nb = 0; nb < 2; nb++) {
                uint32_t bd = tb + 2 * GA_TILE + bRow[nb] +
                              (uint32_t)(((kx + bSel) ^ L7) << 4);
                ldsm_x4(bd, bH[nb]);
                ldsm_x4(bd + GW_TILE, bL[nb]);
            }
#pragma unroll
            for (int mi = 0; mi < 2; mi++)
#pragma unroll
                for (int nj = 0; nj < 4; nj++) {
                    const uint32_t* fH = &bH[nj >> 1][(nj & 1) * 2];
                    const uint32_t* fL = &bL[nj >> 1][(nj & 1) * 2];
                    mma16816(acc[mi][nj], aH[mi], fH);
                    mma16816(acc[mi][nj], aH[mi], fL);
                    mma16816(acc[mi][nj], aL[mi], fH);
                }
        }
        __syncthreads();
    }

#pragma unroll
    for (int mi = 0; mi < 2; mi++)
#pragma unroll
        for (int nj = 0; nj < 4; nj++) {
            int row0 = bm + wm * 32 + mi * 16 + (lane >> 2);
            int col  = bn + wn * 32 + nj * 8 + (lane & 3) * 2;
            float b0 = bias[col], b1 = bias[col + 1];
#pragma unroll
            for (int half = 0; half < 2; half++) {
                int row = row0 + half * 8;
                float v0 = acc[mi][nj][half * 2 + 0] + b0;
                float v1 = acc[mi][nj][half * 2 + 1] + b1;
                if (SPLITB16) {
                    int b = row >> 11, s = row & 2047;
                    int h = col >> 6,  d = col & 63;
                    size_t idx = (((size_t)(b * NHH + h)) * SS + s) * PHH + d;
                    __nv_bfloat162 hv = __floats2bfloat162_rn(v0, v1);
                    float r0 = v0 - __bfloat162float(hv.x);
                    float r1 = v1 - __bfloat162float(hv.y);
                    __nv_bfloat162 lv = __floats2bfloat162_rn(r0, r1);
                    *(__nv_bfloat162*)&Chi[idx] = hv;
                    *(__nv_bfloat162*)&Clo[idx] = lv;
                } else {
                    *(float2*)&C[(size_t)row * HH + col] = make_float2(v0, v1);
                }
            }
        }
}

struct Gemm3 {
    const __nv_bfloat16 *Ah[3], *Al[3], *Wh[3], *Wl[3];
    const float* bias[3];
    __nv_bfloat16 *Ch[3], *Cl[3];
};

__global__ __launch_bounds__(256, 2) void gemm_qkv(Gemm3 g)
{
    extern __shared__ char smem[];
    const uint32_t sbase = smem_u32(smem);
    const int z = blockIdx.z;
    const int bm = blockIdx.y * 128;
    const int bn = blockIdx.x * 64;
    gemm_body<true>(g.Ah[z] + (size_t)bm * KK, g.Al[z] + (size_t)bm * KK,
                    g.Wh[z] + (size_t)bn * KK, g.Wl[z] + (size_t)bn * KK,
                    g.bias[z], nullptr, g.Ch[z], g.Cl[z], bm, bn, sbase);
}

__global__ __launch_bounds__(256, 2) void gemm_out(
    const __nv_bfloat16* __restrict__ Ahi, const __nv_bfloat16* __restrict__ Alo,
    const __nv_bfloat16* __restrict__ Whi, const __nv_bfloat16* __restrict__ Wlo,
    const float* __restrict__ bias, float* __restrict__ C)
{
    extern __shared__ char smem[];
    const uint32_t sbase = smem_u32(smem);
    const int bm = blockIdx.y * 128;
    const int bn = blockIdx.x * 64;
    gemm_body<false>(Ahi + (size_t)bm * KK, Alo + (size_t)bm * KK,
                     Whi + (size_t)bn * KK, Wlo + (size_t)bn * KK,
                     bias, C, nullptr, nullptr, bm, bn, sbase);
}

// ---------------------------------------------------------------------------
// HMMA flash attention v4: KV tile 64 rows double-buffered, Q resident in
// smem (frags re-loaded per ks), split-bf16, P in registers.
// smem: [Qh 16K | Ql 16K | buf0 4x8K | buf1 4x8K] = 96KB -> 2 CTAs/SM.
// ---------------------------------------------------------------------------
#define KT_BYTES 8192
#define KV_STAGE (4 * KT_BYTES)           // 32768
#define ATT_Q    32768
#define ATT_SMEM (ATT_Q + 2 * KV_STAGE)   // 98304

__device__ __forceinline__ void attn_prefetch(
    const __nv_bfloat16* __restrict__ Kh, const __nv_bfloat16* __restrict__ Kl,
    const __nv_bfloat16* __restrict__ Vh, const __nv_bfloat16* __restrict__ Vl,
    int kt, uint32_t dst, int tid)
{
    const __nv_bfloat16* srcs[4] = {Kh, Kl, Vh, Vl};
#pragma unroll
    for (int t = 0; t < 4; t++) {
#pragma unroll
        for (int p = 0; p < 2; p++) {
            int idx = tid + p * 256;
            int row = idx >> 3, ch = idx & 7;
            uint32_t soff = dst + t * KT_BYTES + row * 128 + ((ch ^ (row & 7)) << 4);
            cp_async16(soff, srcs[t] + (size_t)(kt * 64 + row) * PHH + ch * 8);
        }
    }
}

__global__ __launch_bounds__(256, 2) void attn4_kernel(
    const __nv_bfloat16* __restrict__ Qh, const __nv_bfloat16* __restrict__ Ql,
    const __nv_bfloat16* __restrict__ Kh, const __nv_bfloat16* __restrict__ Kl,
    const __nv_bfloat16* __restrict__ Vh, const __nv_bfloat16* __restrict__ Vl,
    const float* __restrict__ mask,
    __nv_bfloat16* __restrict__ Ch, __nv_bfloat16* __restrict__ Cl)
{
    extern __shared__ char smem[];
    const uint32_t sbase = smem_u32(smem);
    const uint32_t kvb = sbase + ATT_Q;
    const int tid  = threadIdx.x;
    const int wid  = tid >> 5;
    const int lane = tid & 31;
    const int L7   = lane & 7;
    const int qt = blockIdx.x, h = blockIdx.y, b = blockIdx.z;
    const int q0 = qt * 128;

    const size_t hoff = ((size_t)(b * NHH + h)) * SS * PHH;
    const __nv_bfloat16* Qhg = Qh + hoff + (size_t)q0 * PHH;
    const __nv_bfloat16* Qlg = Ql + hoff + (size_t)q0 * PHH;
    const __nv_bfloat16* Khg = Kh + hoff;
    const __nv_bfloat16* Klg = Kl + hoff;
    const __nv_bfloat16* Vhg = Vh + hoff;
    const __nv_bfloat16* Vlg = Vl + hoff;
    const float* Mg = mask + (size_t)b * SS * SS + (size_t)q0 * SS;

    // stage Q (resident for whole kernel)
#pragma unroll
    for (int p = 0; p < 4; p++) {
        int idx = tid + p * 256;
        int row = idx >> 3, ch = idx & 7;
        uint32_t soff = sbase + row * 128 + ((ch ^ (row & 7)) << 4);
        cp_async16(soff, Qhg + (size_t)row * PHH + ch * 8);
        cp_async16(soff + 16384, Qlg + (size_t)row * PHH + ch * 8);
    }
    cp_commit();
    attn_prefetch(Khg, Klg, Vhg, Vlg, 0, kvb, tid);
    cp_commit();

    float pv[8][4];
#pragma unroll
    for (int nj = 0; nj < 8; nj++)
#pragma unroll
        for (int q = 0; q < 4; q++) pv[nj][q] = 0.f;
    float mA = -1e30f, mB = -1e30f, lA = 0.f, lB = 0.f;

    const int rA = wid * 16 + (lane >> 2);
    const int rB = rA + 8;
    const uint32_t aRowQ = (uint32_t)(wid * 16 + (lane & 15)) * 128;
    const int aSel = lane >> 4;
    const int bSel = (lane >> 3) & 1;

    for (int kt = 0; kt < SS / 64; kt++) {
        if (kt < SS / 64 - 1) {
            attn_prefetch(Khg, Klg, Vhg, Vlg, kt + 1,
                          kvb + ((kt + 1) & 1) * KV_STAGE, tid);
            cp_commit();
            cp_wait<1>();
        } else {
            cp_wait<0>();
        }
        __syncthreads();

        const uint32_t kb = kvb + (kt & 1) * KV_STAGE;

        // ---- score: S[16 x 64] = 3-term split ----
        float accS[8][4];
#pragma unroll
        for (int nj = 0; nj < 8; nj++)
#pragma unroll
            for (int q = 0; q < 4; q++) accS[nj][q] = 0.f;

#pragma unroll
        for (int ks = 0; ks < 4; ks++) {
            uint32_t qad = sbase + aRowQ + (uint32_t)(((2 * ks + aSel) ^ L7) << 4);
            uint32_t qH[4], qL[4];
            ldsm_x4(qad, qH);
            ldsm_x4(qad + 16384, qL);
#pragma unroll
            for (int jp = 0; jp < 4; jp++) {
                uint32_t row = (uint32_t)(jp * 16 + ((lane >> 4) * 8) + L7);
                uint32_t ad = kb + row * 128 +
                              (uint32_t)(((2 * ks + bSel) ^ L7) << 4);
                uint32_t bH[4], bL[4];
                ldsm_x4(ad, bH);
                ldsm_x4(ad + KT_BYTES, bL);
                mma16816(accS[2*jp],   qH, &bH[0]);
                mma16816(accS[2*jp],   qH, &bL[0]);
                mma16816(accS[2*jp],   qL, &bH[0]);
                mma16816(accS[2*jp+1], qH, &bH[2]);
                mma16816(accS[2*jp+1], qH, &bL[2]);
                mma16816(accS[2*jp+1], qL, &bH[2]);
            }
        }

        // ---- scale * mask (inline loads), online softmax ----
        {
            const int colb = kt * 64 + (lane & 3) * 2;
            const float* mra = &Mg[(size_t)rA * SS + colb];
            const float* mrb = &Mg[(size_t)rB * SS + colb];
#pragma unroll
            for (int nj = 0; nj < 8; nj++) {
                float2 ma = *(const float2*)&mra[nj * 8];
                float2 mb = *(const float2*)&mrb[nj * 8];
                accS[nj][0] *= 0.125f * ma.x;
                accS[nj][1] *= 0.125f * ma.y;
                accS[nj][2] *= 0.125f * mb.x;
                accS[nj][3] *= 0.125f * mb.y;
            }
        }
        float mxA = -1e30f, mxB = -1e30f;
#pragma unroll
        for (int nj = 0; nj < 8; nj++) {
            mxA = fmaxf(mxA, fmaxf(accS[nj][0], accS[nj][1]));
            mxB = fmaxf(mxB, fmaxf(accS[nj][2], accS[nj][3]));
        }
        mxA = fmaxf(mxA, __shfl_xor_sync(0xffffffffu, mxA, 1));
        mxA = fmaxf(mxA, __shfl_xor_sync(0xffffffffu, mxA, 2));
        mxB = fmaxf(mxB, __shfl_xor_sync(0xffffffffu, mxB, 1));
        mxB = fmaxf(mxB, __shfl_xor_sync(0xffffffffu, mxB, 2));
        float mnA = fmaxf(mA, mxA), mnB = fmaxf(mB, mxB);
        float corrA = __expf(mA - mnA), corrB = __expf(mB - mnB);
        float tsA = 0.f, tsB = 0.f;
#pragma unroll
        for (int nj = 0; nj < 8; nj++) {
            accS[nj][0] = __expf(accS[nj][0] - mnA);
            accS[nj][1] = __expf(accS[nj][1] - mnA);
            accS[nj][2] = __expf(accS[nj][2] - mnB);
            accS[nj][3] = __expf(accS[nj][3] - mnB);
            tsA += accS[nj][0] + accS[nj][1];
            tsB += accS[nj][2] + accS[nj][3];
        }
        tsA += __shfl_xor_sync(0xffffffffu, tsA, 1);
        tsA += __shfl_xor_sync(0xffffffffu, tsA, 2);
        tsB += __shfl_xor_sync(0xffffffffu, tsB, 1);
        tsB += __shfl_xor_sync(0xffffffffu, tsB, 2);
        lA = lA * corrA + tsA;
        lB = lB * corrB + tsB;
        mA = mnA; mB = mnB;

#pragma unroll
        for (int nj = 0; nj < 8; nj++) {
            pv[nj][0] *= corrA; pv[nj][1] *= corrA;
            pv[nj][2] *= corrB; pv[nj][3] *= corrB;
        }

        // ---- PV: 3-term split, P from registers ----
        const uint32_t vb = kb + 2 * KT_BYTES;
#pragma unroll
        for (int ks = 0; ks < 4; ks++) {
            const float* s0 = accS[2*ks];
            const float* s1 = accS[2*ks+1];
            __nv_bfloat162 h0 = __floats2bfloat162_rn(s0[0], s0[1]);
            __nv_bfloat162 h1 = __floats2bfloat162_rn(s0[2], s0[3]);
            __nv_bfloat162 h2 = __floats2bfloat162_rn(s1[0], s1[1]);
            __nv_bfloat162 h3 = __floats2bfloat162_rn(s1[2], s1[3]);
            uint32_t aPH[4] = {bits2(h0), bits2(h1), bits2(h2), bits2(h3)};
            __nv_bfloat162 e0 = __floats2bfloat162_rn(s0[0] - __bfloat162float(h0.x),
                                                      s0[1] - __bfloat162float(h0.y));
            __nv_bfloat162 e1 = __floats2bfloat162_rn(s0[2] - __bfloat162float(h1.x),
                                                      s0[3] - __bfloat162float(h1.y));
            __nv_bfloat162 e2 = __floats2bfloat162_rn(s1[0] - __bfloat162float(h2.x),
                                                      s1[1] - __bfloat162float(h2.y));
            __nv_bfloat162 e3 = __floats2bfloat162_rn(s1[2] - __bfloat162float(h3.x),
                                                      s1[3] - __bfloat162float(h3.y));
            uint32_t aPL[4] = {bits2(e0), bits2(e1), bits2(e2), bits2(e3)};

            uint32_t row = (uint32_t)(ks * 16 + (lane & 15));
#pragma unroll
            for (int jp = 0; jp < 4; jp++) {
                uint32_t ad = vb + row * 128 +
                              (uint32_t)(((2 * jp + (lane >> 4)) ^ L7) << 4);
                uint32_t vH[4], vL[4];
                ldsm_x4_t(ad, vH);
                ldsm_x4_t(ad + KT_BYTES, vL);
                mma16816(pv[2*jp],   aPH, &vH[0]);
                mma16816(pv[2*jp],   aPH, &vL[0]);
                mma16816(pv[2*jp],   aPL, &vH[0]);
                mma16816(pv[2*jp+1], aPH, &vH[2]);
                mma16816(pv[2*jp+1], aPH, &vL[2]);
                mma16816(pv[2*jp+1], aPL, &vH[2]);
            }
        }
        __syncthreads();
    }

    const float invA = 1.f / lA, invB = 1.f / lB;
    const int gA = q0 + rA, gB = q0 + rB;
#pragma unroll
    for (int nj = 0; nj < 8; nj++) {
        int d = nj * 8 + (lane & 3) * 2;
        float v0 = pv[nj][0] * invA, v1 = pv[nj][1] * invA;
        float v2 = pv[nj][2] * invB, v3 = pv[nj][3] * invB;
        size_t iA = ((size_t)b * SS + gA) * HH + h * PHH + d;
        size_t iB = ((size_t)b * SS + gB) * HH + h * PHH + d;
        __nv_bfloat162 hA = __floats2bfloat162_rn(v0, v1);
        __nv_bfloat162 lAv = __floats2bfloat162_rn(v0 - __bfloat162float(hA.x),
                                                   v1 - __bfloat162float(hA.y));
        __nv_bfloat162 hB = __floats2bfloat162_rn(v2, v3);
        __nv_bfloat162 lBv = __floats2bfloat162_rn(v2 - __bfloat162float(hB.x),
                                                   v3 - __bfloat162float(hB.y));
        *(__nv_bfloat162*)&Ch[iA] = hA;
        *(__nv_bfloat162*)&Cl[iA] = lAv;
        *(__nv_bfloat162*)&Ch[iB] = hB;
        *(__nv_bfloat162*)&Cl[iB] = lBv;
    }
}

extern "C" void kernel_launch(void* const* d_in, const int* in_sizes, int n_in,
                              void* d_out, int out_size)
{
    const float* key   = (const float*)d_in[0];
    const float* value = (const float*)d_in[1];
    const float* query = (const float*)d_in[2];
    const float* mask  = (const float*)d_in[3];
    const float* Wq = (const float*)d_in[5];
    const float* bq = (const float*)d_in[6];
    const float* Wk = (const float*)d_in[7];
    const float* bk = (const float*)d_in[8];
    const float* Wv = (const float*)d_in[9];
    const float* bv = (const float*)d_in[10];
    const float* Wo = (const float*)d_in[11];
    const float* bo = (const float*)d_in[12];
    float* out = (float*)d_out;

    __nv_bfloat16 *qh,*ql,*kh,*kl,*vh,*vl,*chp,*clp;
    __nv_bfloat16 *sqh,*sql,*skh,*skl,*svh,*svl;
    __nv_bfloat16 *wqh,*wql,*wkh,*wkl,*wvh,*wvl,*woh,*wol;
    cudaGetSymbolAddress((void**)&qh, g_qh);  cudaGetSymbolAddress((void**)&ql, g_ql);
    cudaGetSymbolAddress((void**)&kh, g_kh);  cudaGetSymbolAddress((void**)&kl, g_kl);
    cudaGetSymbolAddress((void**)&vh, g_vh);  cudaGetSymbolAddress((void**)&vl, g_vl);
    cudaGetSymbolAddress((void**)&chp, g_ch); cudaGetSymbolAddress((void**)&clp, g_cl);
    cudaGetSymbolAddress((void**)&sqh, g_sqh); cudaGetSymbolAddress((void**)&sql, g_sql);
    cudaGetSymbolAddress((void**)&skh, g_skh); cudaGetSymbolAddress((void**)&skl, g_skl);
    cudaGetSymbolAddress((void**)&svh, g_svh); cudaGetSymbolAddress((void**)&svl, g_svl);
    cudaGetSymbolAddress((void**)&wqh, g_wqh); cudaGetSymbolAddress((void**)&wql, g_wql);
    cudaGetSymbolAddress((void**)&wkh, g_wkh); cudaGetSymbolAddress((void**)&wkl, g_wkl);
    cudaGetSymbolAddress((void**)&wvh, g_wvh); cudaGetSymbolAddress((void**)&wvl, g_wvl);
    cudaGetSymbolAddress((void**)&woh, g_woh); cudaGetSymbolAddress((void**)&wol, g_wol);

    // 1) all converts in one launch
    Cvt7 cv;
    cv.src[0] = query; cv.hi[0] = sqh; cv.lo[0] = sql;
    cv.src[1] = key;   cv.hi[1] = skh; cv.lo[1] = skl;
    cv.src[2] = value; cv.hi[2] = svh; cv.lo[2] = svl;
    cv.src[3] = Wq; cv.hi[3] = wqh; cv.lo[3] = wql;
    cv.src[4] = Wk; cv.hi[4] = wkh; cv.lo[4] = wkl;
    cv.src[5] = Wv; cv.hi[5] = wvh; cv.lo[5] = wvl;
    cv.src[6] = Wo; cv.hi[6] = woh; cv.lo[6] = wol;
    convert_all<<<16384, 256>>>(cv);

    // 2) fused q/k/v projections
    Gemm3 g3;
    g3.Ah[0] = sqh; g3.Al[0] = sql; g3.Wh[0] = wqh; g3.Wl[0] = wql;
    g3.bias[0] = bq; g3.Ch[0] = qh; g3.Cl[0] = ql;
    g3.Ah[1] = skh; g3.Al[1] = skl; g3.Wh[1] = wkh; g3.Wl[1] = wkl;
    g3.bias[1] = bk; g3.Ch[1] = kh; g3.Cl[1] = kl;
    g3.Ah[2] = svh; g3.Al[2] = svl; g3.Wh[2] = wvh; g3.Wl[2] = wvl;
    g3.bias[2] = bv; g3.Ch[2] = vh; g3.Cl[2] = vl;

    cudaFuncSetAttribute(gemm_qkv, cudaFuncAttributeMaxDynamicSharedMemorySize, G3_SMEM);
    cudaFuncSetAttribute(gemm_out, cudaFuncAttributeMaxDynamicSharedMemorySize, G3_SMEM);
    gemm_qkv<<<dim3(HH / 64, MM / 128, 3), 256, G3_SMEM>>>(g3);

    // 3) attention
    cudaFuncSetAttribute(attn4_kernel, cudaFuncAttributeMaxDynamicSharedMemorySize, ATT_SMEM);
    attn4_kernel<<<dim3(SS / 128, NHH, BB), 256, ATT_SMEM>>>(
        qh, ql, kh, kl, vh, vl, mask, chp, clp);

    // 4) output projection
    gemm_out<<<dim3(HH / 64, MM / 128), 256, G3_SMEM>>>(chp, clp, woh, wol, bo, out);
}

// round 12
// speedup vs baseline: 3.1168x; 1.0178x over previous
#include <cuda_runtime.h>
#include <cuda_bf16.h>
#include <cstdint>
#include <math.h>

#define BB   2
#define SS   2048
#define HH   1024
#define NHH  16
#define PHH  64
#define MM   (BB*SS)
#define KK   1024

// split-bf16 scratch
__device__ __nv_bfloat16 g_qh[MM*KK], g_ql[MM*KK];   // q,k,v in [b,h,s,d]
__device__ __nv_bfloat16 g_kh[MM*KK], g_kl[MM*KK];
__device__ __nv_bfloat16 g_vh[MM*KK], g_vl[MM*KK];
__device__ __nv_bfloat16 g_ch[MM*KK], g_cl[MM*KK];   // ctx
__device__ __nv_bfloat16 g_sqh[MM*KK], g_sql[MM*KK]; // input staging
__device__ __nv_bfloat16 g_skh[MM*KK], g_skl[MM*KK];
__device__ __nv_bfloat16 g_svh[MM*KK], g_svl[MM*KK];
__device__ __nv_bfloat16 g_wqh[HH*HH], g_wql[HH*HH];
__device__ __nv_bfloat16 g_wkh[HH*HH], g_wkl[HH*HH];
__device__ __nv_bfloat16 g_wvh[HH*HH], g_wvl[HH*HH];
__device__ __nv_bfloat16 g_woh[HH*HH], g_wol[HH*HH];

__device__ __forceinline__ uint32_t smem_u32(const void* p) {
    uint32_t a;
    asm("{ .reg .u64 t; cvta.to.shared.u64 t, %1; cvt.u32.u64 %0, t; }" : "=r"(a) : "l"(p));
    return a;
}
__device__ __forceinline__ void cp_async16(uint32_t s, const void* g) {
    asm volatile("cp.async.cg.shared.global [%0], [%1], 16;" :: "r"(s), "l"(g));
}
__device__ __forceinline__ void cp_commit() {
    asm volatile("cp.async.commit_group;" ::: "memory");
}
template<int N> __device__ __forceinline__ void cp_wait() {
    asm volatile("cp.async.wait_group %0;" :: "n"(N) : "memory");
}
__device__ __forceinline__ void ldsm_x4(uint32_t addr, uint32_t* r) {
    asm volatile("ldmatrix.sync.aligned.m8n8.x4.shared.b16 {%0,%1,%2,%3}, [%4];"
                 : "=r"(r[0]), "=r"(r[1]), "=r"(r[2]), "=r"(r[3]) : "r"(addr));
}
__device__ __forceinline__ void ldsm_x4_t(uint32_t addr, uint32_t* r) {
    asm volatile("ldmatrix.sync.aligned.m8n8.x4.trans.shared.b16 {%0,%1,%2,%3}, [%4];"
                 : "=r"(r[0]), "=r"(r[1]), "=r"(r[2]), "=r"(r[3]) : "r"(addr));
}
__device__ __forceinline__ void mma16816(float* d, const uint32_t* a, const uint32_t* b) {
    asm volatile("mma.sync.aligned.m16n8k16.row.col.f32.bf16.bf16.f32 "
        "{%0,%1,%2,%3}, {%4,%5,%6,%7}, {%8,%9}, {%0,%1,%2,%3};"
        : "+f"(d[0]), "+f"(d[1]), "+f"(d[2]), "+f"(d[3])
        : "r"(a[0]), "r"(a[1]), "r"(a[2]), "r"(a[3]), "r"(b[0]), "r"(b[1]));
}
__device__ __forceinline__ uint32_t bits2(__nv_bfloat162 v) {
    return *(uint32_t*)&v;
}

// ---------------------------------------------------------------------------
// Fused split-convert: 7 arrays in one launch.
// ---------------------------------------------------------------------------
struct Cvt7 {
    const float* src[7];
    __nv_bfloat16* hi[7];
    __nv_bfloat16* lo[7];
};

__global__ __launch_bounds__(256) void convert_all(Cvt7 jobs)
{
    int bid = blockIdx.x;
    int j, base;
    if (bid < 12288) { j = bid >> 12;            base = bid & 4095; }
    else             { j = 3 + ((bid - 12288) >> 10); base = (bid - 12288) & 1023; }
    int i = base * 256 + threadIdx.x;

    float4 v = ((const float4*)jobs.src[j])[i];
    __nv_bfloat16 h0 = __float2bfloat16(v.x), h1 = __float2bfloat16(v.y);
    __nv_bfloat16 h2 = __float2bfloat16(v.z), h3 = __float2bfloat16(v.w);
    __nv_bfloat16 l0 = __float2bfloat16(v.x - __bfloat162float(h0));
    __nv_bfloat16 l1 = __float2bfloat16(v.y - __bfloat162float(h1));
    __nv_bfloat16 l2 = __float2bfloat16(v.z - __bfloat162float(h2));
    __nv_bfloat16 l3 = __float2bfloat16(v.w - __bfloat162float(h3));
    uint2 hv, lv;
    hv.x = (uint32_t)__bfloat16_as_ushort(h0) | ((uint32_t)__bfloat16_as_ushort(h1) << 16);
    hv.y = (uint32_t)__bfloat16_as_ushort(h2) | ((uint32_t)__bfloat16_as_ushort(h3) << 16);
    lv.x = (uint32_t)__bfloat16_as_ushort(l0) | ((uint32_t)__bfloat16_as_ushort(l1) << 16);
    lv.y = (uint32_t)__bfloat16_as_ushort(l2) | ((uint32_t)__bfloat16_as_ushort(l3) << 16);
    *(uint2*)(jobs.hi[j] + (size_t)i * 4) = hv;
    *(uint2*)(jobs.lo[j] + (size_t)i * 4) = lv;
}

// ---------------------------------------------------------------------------
// HMMA GEMM: CTA tile 128(M)x64(N), BK=64, 8 warps (warp tile 32x32),
// split-bf16 3-term issued TERM-MAJOR (acc reuse distance 8).
// ---------------------------------------------------------------------------
#define GA_TILE 16384
#define GW_TILE 8192
#define G_STAGE (2*GA_TILE + 2*GW_TILE)   // 49152
#define G3_SMEM (2 * G_STAGE)             // 98304

__device__ __forceinline__ void prefetch_g(
    const __nv_bfloat16* __restrict__ Ah, const __nv_bfloat16* __restrict__ Al,
    const __nv_bfloat16* __restrict__ Wh, const __nv_bfloat16* __restrict__ Wl,
    int k0, uint32_t stage, int tid)
{
#pragma unroll
    for (int t = 0; t < 2; t++) {
        const __nv_bfloat16* src = t ? Al : Ah;
        uint32_t base = stage + t * GA_TILE;
#pragma unroll
        for (int p = 0; p < 4; p++) {
            int idx = tid + p * 256;
            int row = idx >> 3, ch = idx & 7;
            cp_async16(base + row * 128 + ((ch ^ (row & 7)) << 4),
                       src + (size_t)row * KK + k0 + ch * 8);
        }
    }
#pragma unroll
    for (int t = 0; t < 2; t++) {
        const __nv_bfloat16* src = t ? Wl : Wh;
        uint32_t base = stage + 2 * GA_TILE + t * GW_TILE;
#pragma unroll
        for (int p = 0; p < 2; p++) {
            int idx = tid + p * 256;
            int row = idx >> 3, ch = idx & 7;
            cp_async16(base + row * 128 + ((ch ^ (row & 7)) << 4),
                       src + (size_t)row * KK + k0 + ch * 8);
        }
    }
}

template<bool SPLITB16>
__device__ __forceinline__ void gemm_body(
    const __nv_bfloat16* Ah, const __nv_bfloat16* Al,
    const __nv_bfloat16* Wh, const __nv_bfloat16* Wl,
    const float* bias, float* C,
    __nv_bfloat16* Chi, __nv_bfloat16* Clo,
    int bm, int bn, uint32_t sbase)
{
    const int tid  = threadIdx.x;
    const int wid  = tid >> 5;
    const int lane = tid & 31;
    const int wm = wid >> 1;
    const int wn = wid & 1;

    const int L7 = lane & 7;
    const int aSel = lane >> 4;
    const int bSel = (lane >> 3) & 1;
    uint32_t aRow[2], bRow[2];
#pragma unroll
    for (int mi = 0; mi < 2; mi++)
        aRow[mi] = (uint32_t)(wm * 32 + mi * 16 + (lane & 15)) * 128;
#pragma unroll
    for (int nb = 0; nb < 2; nb++)
        bRow[nb] = (uint32_t)(wn * 32 + nb * 16 + ((lane >> 4) * 8) + L7) * 128;

    float acc[2][4][4];
#pragma unroll
    for (int mi = 0; mi < 2; mi++)
#pragma unroll
        for (int nj = 0; nj < 4; nj++)
#pragma unroll
            for (int q = 0; q < 4; q++) acc[mi][nj][q] = 0.f;

    prefetch_g(Ah, Al, Wh, Wl, 0, sbase, tid);
    cp_commit();

    for (int it = 0; it < 16; it++) {
        if (it < 15) {
            prefetch_g(Ah, Al, Wh, Wl, (it + 1) * 64,
                       sbase + ((it + 1) & 1) * G_STAGE, tid);
            cp_commit();
            cp_wait<1>();
        } else {
            cp_wait<0>();
        }
        __syncthreads();

        const uint32_t tb = sbase + (it & 1) * G_STAGE;
#pragma unroll
        for (int ks = 0; ks < 4; ks++) {
            const int kx = ks * 2;
            uint32_t aH[2][4], aL[2][4], bH[2][4], bL[2][4];
#pragma unroll
            for (int mi = 0; mi < 2; mi++) {
                uint32_t ad = tb + aRow[mi] + (uint32_t)(((kx + aSel) ^ L7) << 4);
                ldsm_x4(ad, aH[mi]);
                ldsm_x4(ad + GA_TILE, aL[mi]);
            }
#pragma unroll
            for (int nb = 0; nb < 2; nb++) {
                uint32_t bd = tb + 2 * GA_TILE + bRow[nb] +
                              (uint32_t)(((kx + bSel) ^ L7) << 4);
                ldsm_x4(bd, bH[nb]);
                ldsm_x4(bd + GW_TILE, bL[nb]);
            }
            // term-major: acc reuse distance = 8
#pragma unroll
            for (int mi = 0; mi < 2; mi++)
#pragma unroll
                for (int nj = 0; nj < 4; nj++)
                    mma16816(acc[mi][nj], aH[mi], &bH[nj >> 1][(nj & 1) * 2]);
#pragma unroll
            for (int mi = 0; mi < 2; mi++)
#pragma unroll
                for (int nj = 0; nj < 4; nj++)
                    mma16816(acc[mi][nj], aH[mi], &bL[nj >> 1][(nj & 1) * 2]);
#pragma unroll
            for (int mi = 0; mi < 2; mi++)
#pragma unroll
                for (int nj = 0; nj < 4; nj++)
                    mma16816(acc[mi][nj], aL[mi], &bH[nj >> 1][(nj & 1) * 2]);
        }
        __syncthreads();
    }

#pragma unroll
    for (int mi = 0; mi < 2; mi++)
#pragma unroll
        for (int nj = 0; nj < 4; nj++) {
            int row0 = bm + wm * 32 + mi * 16 + (lane >> 2);
            int col  = bn + wn * 32 + nj * 8 + (lane & 3) * 2;
            float b0 = bias[col], b1 = bias[col + 1];
#pragma unroll
            for (int half = 0; half < 2; half++) {
                int row = row0 + half * 8;
                float v0 = acc[mi][nj][half * 2 + 0] + b0;
                float v1 = acc[mi][nj][half * 2 + 1] + b1;
                if (SPLITB16) {
                    int b = row >> 11, s = row & 2047;
                    int h = col >> 6,  d = col & 63;
                    size_t idx = (((size_t)(b * NHH + h)) * SS + s) * PHH + d;
                    __nv_bfloat162 hv = __floats2bfloat162_rn(v0, v1);
                    float r0 = v0 - __bfloat162float(hv.x);
                    float r1 = v1 - __bfloat162float(hv.y);
                    __nv_bfloat162 lv = __floats2bfloat162_rn(r0, r1);
                    *(__nv_bfloat162*)&Chi[idx] = hv;
                    *(__nv_bfloat162*)&Clo[idx] = lv;
                } else {
                    *(float2*)&C[(size_t)row * HH + col] = make_float2(v0, v1);
                }
            }
        }
}

struct Gemm3 {
    const __nv_bfloat16 *Ah[3], *Al[3], *Wh[3], *Wl[3];
    const float* bias[3];
    __nv_bfloat16 *Ch[3], *Cl[3];
};

__global__ __launch_bounds__(256, 2) void gemm_qkv(Gemm3 g)
{
    extern __shared__ char smem[];
    const uint32_t sbase = smem_u32(smem);
    const int z = blockIdx.z;
    const int bm = blockIdx.y * 128;
    const int bn = blockIdx.x * 64;
    gemm_body<true>(g.Ah[z] + (size_t)bm * KK, g.Al[z] + (size_t)bm * KK,
                    g.Wh[z] + (size_t)bn * KK, g.Wl[z] + (size_t)bn * KK,
                    g.bias[z], nullptr, g.Ch[z], g.Cl[z], bm, bn, sbase);
}

__global__ __launch_bounds__(256, 2) void gemm_out(
    const __nv_bfloat16* __restrict__ Ahi, const __nv_bfloat16* __restrict__ Alo,
    const __nv_bfloat16* __restrict__ Whi, const __nv_bfloat16* __restrict__ Wlo,
    const float* __restrict__ bias, float* __restrict__ C)
{
    extern __shared__ char smem[];
    const uint32_t sbase = smem_u32(smem);
    const int bm = blockIdx.y * 128;
    const int bn = blockIdx.x * 64;
    gemm_body<false>(Ahi + (size_t)bm * KK, Alo + (size_t)bm * KK,
                     Whi + (size_t)bn * KK, Wlo + (size_t)bn * KK,
                     bias, C, nullptr, nullptr, bm, bn, sbase);
}

// ---------------------------------------------------------------------------
// HMMA flash attention v5: KV tile 64 rows double-buffered, Q resident in
// smem, split-bf16, P in registers, MMAs issued term-major per jp-pair
// (acc reuse distance 4).
// ---------------------------------------------------------------------------
#define KT_BYTES 8192
#define KV_STAGE (4 * KT_BYTES)
#define ATT_Q    32768
#define ATT_SMEM (ATT_Q + 2 * KV_STAGE)

__device__ __forceinline__ void attn_prefetch(
    const __nv_bfloat16* __restrict__ Kh, const __nv_bfloat16* __restrict__ Kl,
    const __nv_bfloat16* __restrict__ Vh, const __nv_bfloat16* __restrict__ Vl,
    int kt, uint32_t dst, int tid)
{
    const __nv_bfloat16* srcs[4] = {Kh, Kl, Vh, Vl};
#pragma unroll
    for (int t = 0; t < 4; t++) {
#pragma unroll
        for (int p = 0; p < 2; p++) {
            int idx = tid + p * 256;
            int row = idx >> 3, ch = idx & 7;
            uint32_t soff = dst + t * KT_BYTES + row * 128 + ((ch ^ (row & 7)) << 4);
            cp_async16(soff, srcs[t] + (size_t)(kt * 64 + row) * PHH + ch * 8);
        }
    }
}

__global__ __launch_bounds__(256, 2) void attn5_kernel(
    const __nv_bfloat16* __restrict__ Qh, const __nv_bfloat16* __restrict__ Ql,
    const __nv_bfloat16* __restrict__ Kh, const __nv_bfloat16* __restrict__ Kl,
    const __nv_bfloat16* __restrict__ Vh, const __nv_bfloat16* __restrict__ Vl,
    const float* __restrict__ mask,
    __nv_bfloat16* __restrict__ Ch, __nv_bfloat16* __restrict__ Cl)
{
    extern __shared__ char smem[];
    const uint32_t sbase = smem_u32(smem);
    const uint32_t kvb = sbase + ATT_Q;
    const int tid  = threadIdx.x;
    const int wid  = tid >> 5;
    const int lane = tid & 31;
    const int L7   = lane & 7;
    const int qt = blockIdx.x, h = blockIdx.y, b = blockIdx.z;
    const int q0 = qt * 128;

    const size_t hoff = ((size_t)(b * NHH + h)) * SS * PHH;
    const __nv_bfloat16* Qhg = Qh + hoff + (size_t)q0 * PHH;
    const __nv_bfloat16* Qlg = Ql + hoff + (size_t)q0 * PHH;
    const __nv_bfloat16* Khg = Kh + hoff;
    const __nv_bfloat16* Klg = Kl + hoff;
    const __nv_bfloat16* Vhg = Vh + hoff;
    const __nv_bfloat16* Vlg = Vl + hoff;
    const float* Mg = mask + (size_t)b * SS * SS + (size_t)q0 * SS;

    // stage Q (resident)
#pragma unroll
    for (int p = 0; p < 4; p++) {
        int idx = tid + p * 256;
        int row = idx >> 3, ch = idx & 7;
        uint32_t soff = sbase + row * 128 + ((ch ^ (row & 7)) << 4);
        cp_async16(soff, Qhg + (size_t)row * PHH + ch * 8);
        cp_async16(soff + 16384, Qlg + (size_t)row * PHH + ch * 8);
    }
    cp_commit();
    attn_prefetch(Khg, Klg, Vhg, Vlg, 0, kvb, tid);
    cp_commit();

    float pv[8][4];
#pragma unroll
    for (int nj = 0; nj < 8; nj++)
#pragma unroll
        for (int q = 0; q < 4; q++) pv[nj][q] = 0.f;
    float mA = -1e30f, mB = -1e30f, lA = 0.f, lB = 0.f;

    const int rA = wid * 16 + (lane >> 2);
    const int rB = rA + 8;
    const uint32_t aRowQ = (uint32_t)(wid * 16 + (lane & 15)) * 128;
    const int aSel = lane >> 4;
    const int bSel = (lane >> 3) & 1;

    for (int kt = 0; kt < SS / 64; kt++) {
        if (kt < SS / 64 - 1) {
            attn_prefetch(Khg, Klg, Vhg, Vlg, kt + 1,
                          kvb + ((kt + 1) & 1) * KV_STAGE, tid);
            cp_commit();
            cp_wait<1>();
        } else {
            cp_wait<0>();
        }
        __syncthreads();

        const uint32_t kb = kvb + (kt & 1) * KV_STAGE;

        // ---- score: S[16 x 64], term-major per jp-pair ----
        float accS[8][4];
#pragma unroll
        for (int nj = 0; nj < 8; nj++)
#pragma unroll
            for (int q = 0; q < 4; q++) accS[nj][q] = 0.f;

#pragma unroll
        for (int ks = 0; ks < 4; ks++) {
            uint32_t qad = sbase + aRowQ + (uint32_t)(((2 * ks + aSel) ^ L7) << 4);
            uint32_t qH[4], qL[4];
            ldsm_x4(qad, qH);
            ldsm_x4(qad + 16384, qL);
#pragma unroll
            for (int jpp = 0; jpp < 2; jpp++) {
                const int jp0 = jpp * 2, jp1 = jp0 + 1;
                uint32_t r0 = (uint32_t)(jp0 * 16 + ((lane >> 4) * 8) + L7);
                uint32_t r1 = (uint32_t)(jp1 * 16 + ((lane >> 4) * 8) + L7);
                uint32_t co = (uint32_t)(((2 * ks + bSel) ^ L7) << 4);
                uint32_t b0H[4], b0L[4], b1H[4], b1L[4];
                ldsm_x4(kb + r0 * 128 + co, b0H);
                ldsm_x4(kb + r0 * 128 + co + KT_BYTES, b0L);
                ldsm_x4(kb + r1 * 128 + co, b1H);
                ldsm_x4(kb + r1 * 128 + co + KT_BYTES, b1L);
                float* s0 = accS[2*jp0];
                float* s1 = accS[2*jp0+1];
                float* s2 = accS[2*jp1];
                float* s3 = accS[2*jp1+1];
                mma16816(s0, qH, &b0H[0]); mma16816(s1, qH, &b0H[2]);
                mma16816(s2, qH, &b1H[0]); mma16816(s3, qH, &b1H[2]);
                mma16816(s0, qH, &b0L[0]); mma16816(s1, qH, &b0L[2]);
                mma16816(s2, qH, &b1L[0]); mma16816(s3, qH, &b1L[2]);
                mma16816(s0, qL, &b0H[0]); mma16816(s1, qL, &b0H[2]);
                mma16816(s2, qL, &b1H[0]); mma16816(s3, qL, &b1H[2]);
            }
        }

        // ---- scale * mask, online softmax ----
        {
            const int colb = kt * 64 + (lane & 3) * 2;
            const float* mra = &Mg[(size_t)rA * SS + colb];
            const float* mrb = &Mg[(size_t)rB * SS + colb];
#pragma unroll
            for (int nj = 0; nj < 8; nj++) {
                float2 ma = *(const float2*)&mra[nj * 8];
                float2 mb = *(const float2*)&mrb[nj * 8];
                accS[nj][0] *= 0.125f * ma.x;
                accS[nj][1] *= 0.125f * ma.y;
                accS[nj][2] *= 0.125f * mb.x;
                accS[nj][3] *= 0.125f * mb.y;
            }
        }
        float mxA = -1e30f, mxB = -1e30f;
#pragma unroll
        for (int nj = 0; nj < 8; nj++) {
            mxA = fmaxf(mxA, fmaxf(accS[nj][0], accS[nj][1]));
            mxB = fmaxf(mxB, fmaxf(accS[nj][2], accS[nj][3]));
        }
        mxA = fmaxf(mxA, __shfl_xor_sync(0xffffffffu, mxA, 1));
        mxA = fmaxf(mxA, __shfl_xor_sync(0xffffffffu, mxA, 2));
        mxB = fmaxf(mxB, __shfl_xor_sync(0xffffffffu, mxB, 1));
        mxB = fmaxf(mxB, __shfl_xor_sync(0xffffffffu, mxB, 2));
        float mnA = fmaxf(mA, mxA), mnB = fmaxf(mB, mxB);
        float corrA = __expf(mA - mnA), corrB = __expf(mB - mnB);
        float tsA = 0.f, tsB = 0.f;
#pragma unroll
        for (int nj = 0; nj < 8; nj++) {
            accS[nj][0] = __expf(accS[nj][0] - mnA);
            accS[nj][1] = __expf(accS[nj][1] - mnA);
            accS[nj][2] = __expf(accS[nj][2] - mnB);
            accS[nj][3] = __expf(accS[nj][3] - mnB);
            tsA += accS[nj][0] + accS[nj][1];
            tsB += accS[nj][2] + accS[nj][3];
        }
        tsA += __shfl_xor_sync(0xffffffffu, tsA, 1);
        tsA += __shfl_xor_sync(0xffffffffu, tsA, 2);
        tsB += __shfl_xor_sync(0xffffffffu, tsB, 1);
        tsB += __shfl_xor_sync(0xffffffffu, tsB, 2);
        lA = lA * corrA + tsA;
        lB = lB * corrB + tsB;
        mA = mnA; mB = mnB;

#pragma unroll
        for (int nj = 0; nj < 8; nj++) {
            pv[nj][0] *= corrA; pv[nj][1] *= corrA;
            pv[nj][2] *= corrB; pv[nj][3] *= corrB;
        }

        // ---- PV: 3-term split, P from registers, term-major per jp-pair ----
        const uint32_t vb = kb + 2 * KT_BYTES;
#pragma unroll
        for (int ks = 0; ks < 4; ks++) {
            const float* s0 = accS[2*ks];
            const float* s1 = accS[2*ks+1];
            __nv_bfloat162 h0 = __floats2bfloat162_rn(s0[0], s0[1]);
            __nv_bfloat162 h1 = __floats2bfloat162_rn(s0[2], s0[3]);
            __nv_bfloat162 h2 = __floats2bfloat162_rn(s1[0], s1[1]);
            __nv_bfloat162 h3 = __floats2bfloat162_rn(s1[2], s1[3]);
            uint32_t aPH[4] = {bits2(h0), bits2(h1), bits2(h2), bits2(h3)};
            __nv_bfloat162 e0 = __floats2bfloat162_rn(s0[0] - __bfloat162float(h0.x),
                                                      s0[1] - __bfloat162float(h0.y));
            __nv_bfloat162 e1 = __floats2bfloat162_rn(s0[2] - __bfloat162float(h1.x),
                                                      s0[3] - __bfloat162float(h1.y));
            __nv_bfloat162 e2 = __floats2bfloat162_rn(s1[0] - __bfloat162float(h2.x),
                                                      s1[1] - __bfloat162float(h2.y));
            __nv_bfloat162 e3 = __floats2bfloat162_rn(s1[2] - __bfloat162float(h3.x),
                                                      s1[3] - __bfloat162float(h3.y));
            uint32_t aPL[4] = {bits2(e0), bits2(e1), bits2(e2), bits2(e3)};

            uint32_t row = (uint32_t)(ks * 16 + (lane & 15));
#pragma unroll
            for (int jpp = 0; jpp < 2; jpp++) {
                const int jp0 = jpp * 2, jp1 = jp0 + 1;
                uint32_t c0 = (uint32_t)(((2 * jp0 + (lane >> 4)) ^ L7) << 4);
                uint32_t c1 = (uint32_t)(((2 * jp1 + (lane >> 4)) ^ L7) << 4);
                uint32_t v0H[4], v0L[4], v1H[4], v1L[4];
                ldsm_x4_t(vb + row * 128 + c0, v0H);
                ldsm_x4_t(vb + row * 128 + c0 + KT_BYTES, v0L);
                ldsm_x4_t(vb + row * 128 + c1, v1H);
                ldsm_x4_t(vb + row * 128 + c1 + KT_BYTES, v1L);
                float* p0 = pv[2*jp0];
                float* p1 = pv[2*jp0+1];
                float* p2 = pv[2*jp1];
                float* p3 = pv[2*jp1+1];
                mma16816(p0, aPH, &v0H[0]); mma16816(p1, aPH, &v0H[2]);
                mma16816(p2, aPH, &v1H[0]); mma16816(p3, aPH, &v1H[2]);
                mma16816(p0, aPH, &v0L[0]); mma16816(p1, aPH, &v0L[2]);
                mma16816(p2, aPH, &v1L[0]); mma16816(p3, aPH, &v1L[2]);
                mma16816(p0, aPL, &v0H[0]); mma16816(p1, aPL, &v0H[2]);
                mma16816(p2, aPL, &v1H[0]); mma16816(p3, aPL, &v1H[2]);
            }
        }
        __syncthreads();
    }

    const float invA = 1.f / lA, invB = 1.f / lB;
    const int gA = q0 + rA, gB = q0 + rB;
#pragma unroll
    for (int nj = 0; nj < 8; nj++) {
        int d = nj * 8 + (lane & 3) * 2;
        float v0 = pv[nj][0] * invA, v1 = pv[nj][1] * invA;
        float v2 = pv[nj][2] * invB, v3 = pv[nj][3] * invB;
        size_t iA = ((size_t)b * SS + gA) * HH + h * PHH + d;
        size_t iB = ((size_t)b * SS + gB) * HH + h * PHH + d;
        __nv_bfloat162 hA = __floats2bfloat162_rn(v0, v1);
        __nv_bfloat162 lAv = __floats2bfloat162_rn(v0 - __bfloat162float(hA.x),
                                                   v1 - __bfloat162float(hA.y));
        __nv_bfloat162 hB = __floats2bfloat162_rn(v2, v3);
        __nv_bfloat162 lBv = __floats2bfloat162_rn(v2 - __bfloat162float(hB.x),
                                                   v3 - __bfloat162float(hB.y));
        *(__nv_bfloat162*)&Ch[iA] = hA;
        *(__nv_bfloat162*)&Cl[iA] = lAv;
        *(__nv_bfloat162*)&Ch[iB] = hB;
        *(__nv_bfloat162*)&Cl[iB] = lBv;
    }
}

extern "C" void kernel_launch(void* const* d_in, const int* in_sizes, int n_in,
                              void* d_out, int out_size)
{
    const float* key   = (const float*)d_in[0];
    const float* value = (const float*)d_in[1];
    const float* query = (const float*)d_in[2];
    const float* mask  = (const float*)d_in[3];
    const float* Wq = (const float*)d_in[5];
    const float* bq = (const float*)d_in[6];
    const float* Wk = (const float*)d_in[7];
    const float* bk = (const float*)d_in[8];
    const float* Wv = (const float*)d_in[9];
    const float* bv = (const float*)d_in[10];
    const float* Wo = (const float*)d_in[11];
    const float* bo = (const float*)d_in[12];
    float* out = (float*)d_out;

    __nv_bfloat16 *qh,*ql,*kh,*kl,*vh,*vl,*chp,*clp;
    __nv_bfloat16 *sqh,*sql,*skh,*skl,*svh,*svl;
    __nv_bfloat16 *wqh,*wql,*wkh,*wkl,*wvh,*wvl,*woh,*wol;
    cudaGetSymbolAddress((void**)&qh, g_qh);  cudaGetSymbolAddress((void**)&ql, g_ql);
    cudaGetSymbolAddress((void**)&kh, g_kh);  cudaGetSymbolAddress((void**)&kl, g_kl);
    cudaGetSymbolAddress((void**)&vh, g_vh);  cudaGetSymbolAddress((void**)&vl, g_vl);
    cudaGetSymbolAddress((void**)&chp, g_ch); cudaGetSymbolAddress((void**)&clp, g_cl);
    cudaGetSymbolAddress((void**)&sqh, g_sqh); cudaGetSymbolAddress((void**)&sql, g_sql);
    cudaGetSymbolAddress((void**)&skh, g_skh); cudaGetSymbolAddress((void**)&skl, g_skl);
    cudaGetSymbolAddress((void**)&svh, g_svh); cudaGetSymbolAddress((void**)&svl, g_svl);
    cudaGetSymbolAddress((void**)&wqh, g_wqh); cudaGetSymbolAddress((void**)&wql, g_wql);
    cudaGetSymbolAddress((void**)&wkh, g_wkh); cudaGetSymbolAddress((void**)&wkl, g_wkl);
    cudaGetSymbolAddress((void**)&wvh, g_wvh); cudaGetSymbolAddress((void**)&wvl, g_wvl);
    cudaGetSymbolAddress((void**)&woh, g_woh); cudaGetSymbolAddress((void**)&wol, g_wol);

    Cvt7 cv;
    cv.src[0] = query; cv.hi[0] = sqh; cv.lo[0] = sql;
    cv.src[1] = key;   cv.hi[1] = skh; cv.lo[1] = skl;
    cv.src[2] = value; cv.hi[2] = svh; cv.lo[2] = svl;
    cv.src[3] = Wq; cv.hi[3] = wqh; cv.lo[3] = wql;
    cv.src[4] = Wk; cv.hi[4] = wkh; cv.lo[4] = wkl;
    cv.src[5] = Wv; cv.hi[5] = wvh; cv.lo[5] = wvl;
    cv.src[6] = Wo; cv.hi[6] = woh; cv.lo[6] = wol;
    convert_all<<<16384, 256>>>(cv);

    Gemm3 g3;
    g3.Ah[0] = sqh; g3.Al[0] = sql; g3.Wh[0] = wqh; g3.Wl[0] = wql;
    g3.bias[0] = bq; g3.Ch[0] = qh; g3.Cl[0] = ql;
    g3.Ah[1] = skh; g3.Al[1] = skl; g3.Wh[1] = wkh; g3.Wl[1] = wkl;
    g3.bias[1] = bk; g3.Ch[1] = kh; g3.Cl[1] = kl;
    g3.Ah[2] = svh; g3.Al[2] = svl; g3.Wh[2] = wvh; g3.Wl[2] = wvl;
    g3.bias[2] = bv; g3.Ch[2] = vh; g3.Cl[2] = vl;

    cudaFuncSetAttribute(gemm_qkv, cudaFuncAttributeMaxDynamicSharedMemorySize, G3_SMEM);
    cudaFuncSetAttribute(gemm_out, cudaFuncAttributeMaxDynamicSharedMemorySize, G3_SMEM);
    gemm_qkv<<<dim3(HH / 64, MM / 128, 3), 256, G3_SMEM>>>(g3);

    cudaFuncSetAttribute(attn5_kernel, cudaFuncAttributeMaxDynamicSharedMemorySize, ATT_SMEM);
    attn5_kernel<<<dim3(SS / 128, NHH, BB), 256, ATT_SMEM>>>(
        qh, ql, kh, kl, vh, vl, mask, chp, clp);

    gemm_out<<<dim3(HH / 64, MM / 128), 256, G3_SMEM>>>(chp, clp, woh, wol, bo, out);
}

// round 13
// speedup vs baseline: 3.6364x; 1.1667x over previous
#include <cuda_runtime.h>
#include <cuda_bf16.h>
#include <cuda_fp16.h>
#include <cstdint>
#include <math.h>

#define BB   2
#define SS   2048
#define HH   1024
#define NHH  16
#define PHH  64
#define MM   (BB*SS)
#define KK   1024

// bf16 split scratch (GEMM path)
__device__ __nv_bfloat16 g_ch[MM*KK], g_cl[MM*KK];   // ctx (attn out, bf16 split)
__device__ __nv_bfloat16 g_sqh[MM*KK], g_sql[MM*KK]; // input staging
__device__ __nv_bfloat16 g_skh[MM*KK], g_skl[MM*KK];
__device__ __nv_bfloat16 g_svh[MM*KK], g_svl[MM*KK];
__device__ __nv_bfloat16 g_wqh[HH*HH], g_wql[HH*HH];
__device__ __nv_bfloat16 g_wkh[HH*HH], g_wkl[HH*HH];
__device__ __nv_bfloat16 g_wvh[HH*HH], g_wvl[HH*HH];
__device__ __nv_bfloat16 g_woh[HH*HH], g_wol[HH*HH];
// fp16 q/k/v for attention ([b,h,s,d])
__device__ __half g_q16h[MM*KK], g_q16l[MM*KK];
__device__ __half g_k16[MM*KK], g_v16[MM*KK];

__device__ __forceinline__ uint32_t smem_u32(const void* p) {
    uint32_t a;
    asm("{ .reg .u64 t; cvta.to.shared.u64 t, %1; cvt.u32.u64 %0, t; }" : "=r"(a) : "l"(p));
    return a;
}
__device__ __forceinline__ void cp_async16(uint32_t s, const void* g) {
    asm volatile("cp.async.cg.shared.global [%0], [%1], 16;" :: "r"(s), "l"(g));
}
__device__ __forceinline__ void cp_commit() {
    asm volatile("cp.async.commit_group;" ::: "memory");
}
template<int N> __device__ __forceinline__ void cp_wait() {
    asm volatile("cp.async.wait_group %0;" :: "n"(N) : "memory");
}
__device__ __forceinline__ void ldsm_x4(uint32_t addr, uint32_t* r) {
    asm volatile("ldmatrix.sync.aligned.m8n8.x4.shared.b16 {%0,%1,%2,%3}, [%4];"
                 : "=r"(r[0]), "=r"(r[1]), "=r"(r[2]), "=r"(r[3]) : "r"(addr));
}
__device__ __forceinline__ void ldsm_x4_t(uint32_t addr, uint32_t* r) {
    asm volatile("ldmatrix.sync.aligned.m8n8.x4.trans.shared.b16 {%0,%1,%2,%3}, [%4];"
                 : "=r"(r[0]), "=r"(r[1]), "=r"(r[2]), "=r"(r[3]) : "r"(addr));
}
__device__ __forceinline__ void mma16816(float* d, const uint32_t* a, const uint32_t* b) {
    asm volatile("mma.sync.aligned.m16n8k16.row.col.f32.bf16.bf16.f32 "
        "{%0,%1,%2,%3}, {%4,%5,%6,%7}, {%8,%9}, {%0,%1,%2,%3};"
        : "+f"(d[0]), "+f"(d[1]), "+f"(d[2]), "+f"(d[3])
        : "r"(a[0]), "r"(a[1]), "r"(a[2]), "r"(a[3]), "r"(b[0]), "r"(b[1]));
}
__device__ __forceinline__ void mmaf16(float* d, const uint32_t* a, const uint32_t* b) {
    asm volatile("mma.sync.aligned.m16n8k16.row.col.f32.f16.f16.f32 "
        "{%0,%1,%2,%3}, {%4,%5,%6,%7}, {%8,%9}, {%0,%1,%2,%3};"
        : "+f"(d[0]), "+f"(d[1]), "+f"(d[2]), "+f"(d[3])
        : "r"(a[0]), "r"(a[1]), "r"(a[2]), "r"(a[3]), "r"(b[0]), "r"(b[1]));
}
__device__ __forceinline__ uint32_t h2bits(__half2 v) { return *(uint32_t*)&v; }

// ---------------------------------------------------------------------------
// Fused split-convert: 7 arrays in one launch (bf16 staging for GEMMs).
// ---------------------------------------------------------------------------
struct Cvt7 {
    const float* src[7];
    __nv_bfloat16* hi[7];
    __nv_bfloat16* lo[7];
};

__global__ __launch_bounds__(256) void convert_all(Cvt7 jobs)
{
    int bid = blockIdx.x;
    int j, base;
    if (bid < 12288) { j = bid >> 12;            base = bid & 4095; }
    else             { j = 3 + ((bid - 12288) >> 10); base = (bid - 12288) & 1023; }
    int i = base * 256 + threadIdx.x;

    float4 v = ((const float4*)jobs.src[j])[i];
    __nv_bfloat16 h0 = __float2bfloat16(v.x), h1 = __float2bfloat16(v.y);
    __nv_bfloat16 h2 = __float2bfloat16(v.z), h3 = __float2bfloat16(v.w);
    __nv_bfloat16 l0 = __float2bfloat16(v.x - __bfloat162float(h0));
    __nv_bfloat16 l1 = __float2bfloat16(v.y - __bfloat162float(h1));
    __nv_bfloat16 l2 = __float2bfloat16(v.z - __bfloat162float(h2));
    __nv_bfloat16 l3 = __float2bfloat16(v.w - __bfloat162float(h3));
    uint2 hv, lv;
    hv.x = (uint32_t)__bfloat16_as_ushort(h0) | ((uint32_t)__bfloat16_as_ushort(h1) << 16);
    hv.y = (uint32_t)__bfloat16_as_ushort(h2) | ((uint32_t)__bfloat16_as_ushort(h3) << 16);
    lv.x = (uint32_t)__bfloat16_as_ushort(l0) | ((uint32_t)__bfloat16_as_ushort(l1) << 16);
    lv.y = (uint32_t)__bfloat16_as_ushort(l2) | ((uint32_t)__bfloat16_as_ushort(l3) << 16);
    *(uint2*)(jobs.hi[j] + (size_t)i * 4) = hv;
    *(uint2*)(jobs.lo[j] + (size_t)i * 4) = lv;
}

// ---------------------------------------------------------------------------
// HMMA GEMM: CTA tile 128x64, BK=64, 8 warps, split-bf16 3-term,
// single __syncthreads per chunk.
// MODE 0: fp32 C output. MODE 1: split-fp16 output to [b,h,s,d] (Hl optional).
// ---------------------------------------------------------------------------
#define GA_TILE 16384
#define GW_TILE 8192
#define G_STAGE (2*GA_TILE + 2*GW_TILE)   // 49152
#define G3_SMEM (2 * G_STAGE)             // 98304

__device__ __forceinline__ void prefetch_g(
    const __nv_bfloat16* __restrict__ Ah, const __nv_bfloat16* __restrict__ Al,
    const __nv_bfloat16* __restrict__ Wh, const __nv_bfloat16* __restrict__ Wl,
    int k0, uint32_t stage, int tid)
{
#pragma unroll
    for (int t = 0; t < 2; t++) {
        const __nv_bfloat16* src = t ? Al : Ah;
        uint32_t base = stage + t * GA_TILE;
#pragma unroll
        for (int p = 0; p < 4; p++) {
            int idx = tid + p * 256;
            int row = idx >> 3, ch = idx & 7;
            cp_async16(base + row * 128 + ((ch ^ (row & 7)) << 4),
                       src + (size_t)row * KK + k0 + ch * 8);
        }
    }
#pragma unroll
    for (int t = 0; t < 2; t++) {
        const __nv_bfloat16* src = t ? Wl : Wh;
        uint32_t base = stage + 2 * GA_TILE + t * GW_TILE;
#pragma unroll
        for (int p = 0; p < 2; p++) {
            int idx = tid + p * 256;
            int row = idx >> 3, ch = idx & 7;
            cp_async16(base + row * 128 + ((ch ^ (row & 7)) << 4),
                       src + (size_t)row * KK + k0 + ch * 8);
        }
    }
}

template<int MODE>
__device__ __forceinline__ void gemm_body(
    const __nv_bfloat16* Ah, const __nv_bfloat16* Al,
    const __nv_bfloat16* Wh, const __nv_bfloat16* Wl,
    const float* bias, float* C,
    __half* Hhi, __half* Hlo,
    int bm, int bn, uint32_t sbase)
{
    const int tid  = threadIdx.x;
    const int wid  = tid >> 5;
    const int lane = tid & 31;
    const int wm = wid >> 1;
    const int wn = wid & 1;

    const int L7 = lane & 7;
    const int aSel = lane >> 4;
    const int bSel = (lane >> 3) & 1;
    uint32_t aRow[2], bRow[2];
#pragma unroll
    for (int mi = 0; mi < 2; mi++)
        aRow[mi] = (uint32_t)(wm * 32 + mi * 16 + (lane & 15)) * 128;
#pragma unroll
    for (int nb = 0; nb < 2; nb++)
        bRow[nb] = (uint32_t)(wn * 32 + nb * 16 + ((lane >> 4) * 8) + L7) * 128;

    float acc[2][4][4];
#pragma unroll
    for (int mi = 0; mi < 2; mi++)
#pragma unroll
        for (int nj = 0; nj < 4; nj++)
#pragma unroll
            for (int q = 0; q < 4; q++) acc[mi][nj][q] = 0.f;

    prefetch_g(Ah, Al, Wh, Wl, 0, sbase, tid);
    cp_commit();

    for (int it = 0; it < 16; it++) {
        cp_wait<0>();
        __syncthreads();
        if (it < 15) {
            prefetch_g(Ah, Al, Wh, Wl, (it + 1) * 64,
                       sbase + ((it + 1) & 1) * G_STAGE, tid);
            cp_commit();
        }
        const uint32_t tb = sbase + (it & 1) * G_STAGE;
#pragma unroll
        for (int ks = 0; ks < 4; ks++) {
            const int kx = ks * 2;
            uint32_t aH[2][4], aL[2][4], bH[2][4], bL[2][4];
#pragma unroll
            for (int mi = 0; mi < 2; mi++) {
                uint32_t ad = tb + aRow[mi] + (uint32_t)(((kx + aSel) ^ L7) << 4);
                ldsm_x4(ad, aH[mi]);
                ldsm_x4(ad + GA_TILE, aL[mi]);
            }
#pragma unroll
            for (int nb = 0; nb < 2; nb++) {
                uint32_t bd = tb + 2 * GA_TILE + bRow[nb] +
                              (uint32_t)(((kx + bSel) ^ L7) << 4);
                ldsm_x4(bd, bH[nb]);
                ldsm_x4(bd + GW_TILE, bL[nb]);
            }
#pragma unroll
            for (int mi = 0; mi < 2; mi++)
#pragma unroll
                for (int nj = 0; nj < 4; nj++)
                    mma16816(acc[mi][nj], aH[mi], &bH[nj >> 1][(nj & 1) * 2]);
#pragma unroll
            for (int mi = 0; mi < 2; mi++)
#pragma unroll
                for (int nj = 0; nj < 4; nj++)
                    mma16816(acc[mi][nj], aH[mi], &bL[nj >> 1][(nj & 1) * 2]);
#pragma unroll
            for (int mi = 0; mi < 2; mi++)
#pragma unroll
                for (int nj = 0; nj < 4; nj++)
                    mma16816(acc[mi][nj], aL[mi], &bH[nj >> 1][(nj & 1) * 2]);
        }
    }

#pragma unroll
    for (int mi = 0; mi < 2; mi++)
#pragma unroll
        for (int nj = 0; nj < 4; nj++) {
            int row0 = bm + wm * 32 + mi * 16 + (lane >> 2);
            int col  = bn + wn * 32 + nj * 8 + (lane & 3) * 2;
            float b0 = bias[col], b1 = bias[col + 1];
#pragma unroll
            for (int half = 0; half < 2; half++) {
                int row = row0 + half * 8;
                float v0 = acc[mi][nj][half * 2 + 0] + b0;
                float v1 = acc[mi][nj][half * 2 + 1] + b1;
                if (MODE == 1) {
                    int b = row >> 11, s = row & 2047;
                    int h = col >> 6,  d = col & 63;
                    size_t idx = (((size_t)(b * NHH + h)) * SS + s) * PHH + d;
                    __half2 hv = __floats2half2_rn(v0, v1);
                    *(__half2*)&Hhi[idx] = hv;
                    if (Hlo) {
                        float r0 = v0 - __half2float(__low2half(hv));
                        float r1 = v1 - __half2float(__high2half(hv));
                        *(__half2*)&Hlo[idx] = __floats2half2_rn(r0, r1);
                    }
                } else {
                    *(float2*)&C[(size_t)row * HH + col] = make_float2(v0, v1);
                }
            }
        }
}

struct Gemm3 {
    const __nv_bfloat16 *Ah[3], *Al[3], *Wh[3], *Wl[3];
    const float* bias[3];
    __half *Hh[3], *Hl[3];
};

__global__ __launch_bounds__(256, 2) void gemm_qkv(Gemm3 g)
{
    extern __shared__ char smem[];
    const uint32_t sbase = smem_u32(smem);
    const int z = blockIdx.z;
    const int bm = blockIdx.y * 128;
    const int bn = blockIdx.x * 64;
    gemm_body<1>(g.Ah[z] + (size_t)bm * KK, g.Al[z] + (size_t)bm * KK,
                 g.Wh[z] + (size_t)bn * KK, g.Wl[z] + (size_t)bn * KK,
                 g.bias[z], nullptr, g.Hh[z], g.Hl[z], bm, bn, sbase);
}

__global__ __launch_bounds__(256, 2) void gemm_out(
    const __nv_bfloat16* __restrict__ Ahi, const __nv_bfloat16* __restrict__ Alo,
    const __nv_bfloat16* __restrict__ Whi, const __nv_bfloat16* __restrict__ Wlo,
    const float* __restrict__ bias, float* __restrict__ C)
{
    extern __shared__ char smem[];
    const uint32_t sbase = smem_u32(smem);
    const int bm = blockIdx.y * 128;
    const int bn = blockIdx.x * 64;
    gemm_body<0>(Ahi + (size_t)bm * KK, Alo + (size_t)bm * KK,
                 Whi + (size_t)bn * KK, Wlo + (size_t)bn * KK,
                 bias, C, nullptr, nullptr, bm, bn, sbase);
}

// ---------------------------------------------------------------------------
// fp16 flash attention v6: 2-term score (QhKh + QlKh), 2-term PV
// (PhVh + PlVh, P split in registers), K/V single fp16.
// KV tiles 64 rows = 16KB/stage, 4-deep pipeline; Q resident fp16 hi/lo.
// smem: 32KB Q + 4x16KB KV = 96KB -> 2 CTAs/SM. One sync per kt.
// ---------------------------------------------------------------------------
#define KV6_STAGE 16384                 // K 8KB + V 8KB
#define ATT6_Q    32768
#define ATT6_SMEM (ATT6_Q + 4 * KV6_STAGE)   // 98304
#define NT6       (SS / 64)             // 32

__device__ __forceinline__ void attn6_prefetch(
    const __half* __restrict__ K16, const __half* __restrict__ V16,
    int kt, uint32_t dst, int tid)
{
    // K tile: 64 rows x 128B
#pragma unroll
    for (int p = 0; p < 2; p++) {
        int idx = tid + p * 256;
        int row = idx >> 3, ch = idx & 7;
        cp_async16(dst + row * 128 + ((ch ^ (row & 7)) << 4),
                   K16 + (size_t)(kt * 64 + row) * PHH + ch * 8);
    }
#pragma unroll
    for (int p = 0; p < 2; p++) {
        int idx = tid + p * 256;
        int row = idx >> 3, ch = idx & 7;
        cp_async16(dst + 8192 + row * 128 + ((ch ^ (row & 7)) << 4),
                   V16 + (size_t)(kt * 64 + row) * PHH + ch * 8);
    }
}

__global__ __launch_bounds__(256, 2) void attn6_kernel(
    const __half* __restrict__ Qh, const __half* __restrict__ Ql,
    const __half* __restrict__ K16, const __half* __restrict__ V16,
    const float* __restrict__ mask,
    __nv_bfloat16* __restrict__ Ch, __nv_bfloat16* __restrict__ Cl)
{
    extern __shared__ char smem[];
    const uint32_t sbase = smem_u32(smem);
    const uint32_t kvb = sbase + ATT6_Q;
    const int tid  = threadIdx.x;
    const int wid  = tid >> 5;
    const int lane = tid & 31;
    const int L7   = lane & 7;
    const int qt = blockIdx.x, h = blockIdx.y, b = blockIdx.z;
    const int q0 = qt * 128;

    const size_t hoff = ((size_t)(b * NHH + h)) * SS * PHH;
    const __half* Qhg = Qh + hoff + (size_t)q0 * PHH;
    const __half* Qlg = Ql + hoff + (size_t)q0 * PHH;
    const __half* Kg  = K16 + hoff;
    const __half* Vg  = V16 + hoff;
    const float* Mg = mask + (size_t)b * SS * SS + (size_t)q0 * SS;

    // stage Q (resident: hi at sbase, lo at sbase+16KB)
#pragma unroll
    for (int p = 0; p < 4; p++) {
        int idx = tid + p * 256;
        int row = idx >> 3, ch = idx & 7;
        uint32_t soff = sbase + row * 128 + ((ch ^ (row & 7)) << 4);
        cp_async16(soff, Qhg + (size_t)row * PHH + ch * 8);
        cp_async16(soff + 16384, Qlg + (size_t)row * PHH + ch * 8);
    }
    cp_commit();
    attn6_prefetch(Kg, Vg, 0, kvb + 0 * KV6_STAGE, tid); cp_commit();
    attn6_prefetch(Kg, Vg, 1, kvb + 1 * KV6_STAGE, tid); cp_commit();
    attn6_prefetch(Kg, Vg, 2, kvb + 2 * KV6_STAGE, tid); cp_commit();

    float pv[8][4];
#pragma unroll
    for (int nj = 0; nj < 8; nj++)
#pragma unroll
        for (int q = 0; q < 4; q++) pv[nj][q] = 0.f;
    float mA = -1e30f, mB = -1e30f, lA = 0.f, lB = 0.f;

    const int rA = wid * 16 + (lane >> 2);
    const int rB = rA + 8;
    const uint32_t aRowQ = (uint32_t)(wid * 16 + (lane & 15)) * 128;
    const int aSel = lane >> 4;
    const int bSel = (lane >> 3) & 1;

    for (int kt = 0; kt < NT6; kt++) {
        if (kt + 2 < NT6)      cp_wait<2>();
        else if (kt + 1 < NT6) cp_wait<1>();
        else                   cp_wait<0>();
        __syncthreads();
        if (kt + 3 < NT6) {
            attn6_prefetch(Kg, Vg, kt + 3, kvb + ((kt + 3) & 3) * KV6_STAGE, tid);
            cp_commit();
        }

        const uint32_t kb = kvb + (kt & 3) * KV6_STAGE;
        const uint32_t vb = kb + 8192;

        // ---- score: S[16 x 64] = QhKh + QlKh ----
        float accS[8][4];
#pragma unroll
        for (int nj = 0; nj < 8; nj++)
#pragma unroll
            for (int q = 0; q < 4; q++) accS[nj][q] = 0.f;

#pragma unroll
        for (int ks = 0; ks < 4; ks++) {
            uint32_t qad = sbase + aRowQ + (uint32_t)(((2 * ks + aSel) ^ L7) << 4);
            uint32_t qH[4], qL[4];
            ldsm_x4(qad, qH);
            ldsm_x4(qad + 16384, qL);
#pragma unroll
            for (int jp = 0; jp < 4; jp++) {
                uint32_t row = (uint32_t)(jp * 16 + ((lane >> 4) * 8) + L7);
                uint32_t ad = kb + row * 128 +
                              (uint32_t)(((2 * ks + bSel) ^ L7) << 4);
                uint32_t bK[4];
                ldsm_x4(ad, bK);
                mmaf16(accS[2*jp],   qH, &bK[0]);
                mmaf16(accS[2*jp+1], qH, &bK[2]);
                mmaf16(accS[2*jp],   qL, &bK[0]);
                mmaf16(accS[2*jp+1], qL, &bK[2]);
            }
        }

        // ---- scale * mask, online softmax ----
        {
            const int colb = kt * 64 + (lane & 3) * 2;
            const float* mra = &Mg[(size_t)rA * SS + colb];
            const float* mrb = &Mg[(size_t)rB * SS + colb];
#pragma unroll
            for (int nj = 0; nj < 8; nj++) {
                float2 ma = *(const float2*)&mra[nj * 8];
                float2 mb = *(const float2*)&mrb[nj * 8];
                accS[nj][0] *= 0.125f * ma.x;
                accS[nj][1] *= 0.125f * ma.y;
                accS[nj][2] *= 0.125f * mb.x;
                accS[nj][3] *= 0.125f * mb.y;
            }
        }
        float mxA = -1e30f, mxB = -1e30f;
#pragma unroll
        for (int nj = 0; nj < 8; nj++) {
            mxA = fmaxf(mxA, fmaxf(accS[nj][0], accS[nj][1]));
            mxB = fmaxf(mxB, fmaxf(accS[nj][2], accS[nj][3]));
        }
        mxA = fmaxf(mxA, __shfl_xor_sync(0xffffffffu, mxA, 1));
        mxA = fmaxf(mxA, __shfl_xor_sync(0xffffffffu, mxA, 2));
        mxB = fmaxf(mxB, __shfl_xor_sync(0xffffffffu, mxB, 1));
        mxB = fmaxf(mxB, __shfl_xor_sync(0xffffffffu, mxB, 2));
        float mnA = fmaxf(mA, mxA), mnB = fmaxf(mB, mxB);
        float corrA = __expf(mA - mnA), corrB = __expf(mB - mnB);
        float tsA = 0.f, tsB = 0.f;
#pragma unroll
        for (int nj = 0; nj < 8; nj++) {
            accS[nj][0] = __expf(accS[nj][0] - mnA);
            accS[nj][1] = __expf(accS[nj][1] - mnA);
            accS[nj][2] = __expf(accS[nj][2] - mnB);
            accS[nj][3] = __expf(accS[nj][3] - mnB);
            tsA += accS[nj][0] + accS[nj][1];
            tsB += accS[nj][2] + accS[nj][3];
        }
        tsA += __shfl_xor_sync(0xffffffffu, tsA, 1);
        tsA += __shfl_xor_sync(0xffffffffu, tsA, 2);
        tsB += __shfl_xor_sync(0xffffffffu, tsB, 1);
        tsB += __shfl_xor_sync(0xffffffffu, tsB, 2);
        lA = lA * corrA + tsA;
        lB = lB * corrB + tsB;
        mA = mnA; mB = mnB;

#pragma unroll
        for (int nj = 0; nj < 8; nj++) {
            pv[nj][0] *= corrA; pv[nj][1] *= corrA;
            pv[nj][2] *= corrB; pv[nj][3] *= corrB;
        }

        // ---- PV: (Ph + Pl) @ Vh, P split to fp16 in registers ----
#pragma unroll
        for (int ks = 0; ks < 4; ks++) {
            const float* s0 = accS[2*ks];
            const float* s1 = accS[2*ks+1];
            __half2 h0 = __floats2half2_rn(s0[0], s0[1]);
            __half2 h1 = __floats2half2_rn(s0[2], s0[3]);
            __half2 h2 = __floats2half2_rn(s1[0], s1[1]);
            __half2 h3 = __floats2half2_rn(s1[2], s1[3]);
            uint32_t aPH[4] = {h2bits(h0), h2bits(h1), h2bits(h2), h2bits(h3)};
            __half2 e0 = __floats2half2_rn(s0[0] - __half2float(__low2half(h0)),
                                           s0[1] - __half2float(__high2half(h0)));
            __half2 e1 = __floats2half2_rn(s0[2] - __half2float(__low2half(h1)),
                                           s0[3] - __half2float(__high2half(h1)));
            __half2 e2 = __floats2half2_rn(s1[0] - __half2float(__low2half(h2)),
                                           s1[1] - __half2float(__high2half(h2)));
            __half2 e3 = __floats2half2_rn(s1[2] - __half2float(__low2half(h3)),
                                           s1[3] - __half2float(__high2half(h3)));
            uint32_t aPL[4] = {h2bits(e0), h2bits(e1), h2bits(e2), h2bits(e3)};

            uint32_t row = (uint32_t)(ks * 16 + (lane & 15));
#pragma unroll
            for (int jp = 0; jp < 4; jp++) {
                uint32_t ad = vb + row * 128 +
                              (uint32_t)(((2 * jp + (lane >> 4)) ^ L7) << 4);
                uint32_t vK[4];
                ldsm_x4_t(ad, vK);
                mmaf16(pv[2*jp],   aPH, &vK[0]);
                mmaf16(pv[2*jp+1], aPH, &vK[2]);
                mmaf16(pv[2*jp],   aPL, &vK[0]);
                mmaf16(pv[2*jp+1], aPL, &vK[2]);
            }
        }
    }

    const float invA = 1.f / lA, invB = 1.f / lB;
    const int gA = q0 + rA, gB = q0 + rB;
#pragma unroll
    for (int nj = 0; nj < 8; nj++) {
        int d = nj * 8 + (lane & 3) * 2;
        float v0 = pv[nj][0] * invA, v1 = pv[nj][1] * invA;
        float v2 = pv[nj][2] * invB, v3 = pv[nj][3] * invB;
        size_t iA = ((size_t)b * SS + gA) * HH + h * PHH + d;
        size_t iB = ((size_t)b * SS + gB) * HH + h * PHH + d;
        __nv_bfloat162 hA = __floats2bfloat162_rn(v0, v1);
        __nv_bfloat162 lAv = __floats2bfloat162_rn(v0 - __bfloat162float(hA.x),
                                                   v1 - __bfloat162float(hA.y));
        __nv_bfloat162 hB = __floats2bfloat162_rn(v2, v3);
        __nv_bfloat162 lBv = __floats2bfloat162_rn(v2 - __bfloat162float(hB.x),
                                                   v3 - __bfloat162float(hB.y));
        *(__nv_bfloat162*)&Ch[iA] = hA;
        *(__nv_bfloat162*)&Cl[iA] = lAv;
        *(__nv_bfloat162*)&Ch[iB] = hB;
        *(__nv_bfloat162*)&Cl[iB] = lBv;
    }
}

extern "C" void kernel_launch(void* const* d_in, const int* in_sizes, int n_in,
                              void* d_out, int out_size)
{
    const float* key   = (const float*)d_in[0];
    const float* value = (const float*)d_in[1];
    const float* query = (const float*)d_in[2];
    const float* mask  = (const float*)d_in[3];
    const float* Wq = (const float*)d_in[5];
    const float* bq = (const float*)d_in[6];
    const float* Wk = (const float*)d_in[7];
    const float* bk = (const float*)d_in[8];
    const float* Wv = (const float*)d_in[9];
    const float* bv = (const float*)d_in[10];
    const float* Wo = (const float*)d_in[11];
    const float* bo = (const float*)d_in[12];
    float* out = (float*)d_out;

    __nv_bfloat16 *chp,*clp, *sqh,*sql,*skh,*skl,*svh,*svl;
    __nv_bfloat16 *wqh,*wql,*wkh,*wkl,*wvh,*wvl,*woh,*wol;
    __half *q16h,*q16l,*k16,*v16;
    cudaGetSymbolAddress((void**)&chp, g_ch); cudaGetSymbolAddress((void**)&clp, g_cl);
    cudaGetSymbolAddress((void**)&sqh, g_sqh); cudaGetSymbolAddress((void**)&sql, g_sql);
    cudaGetSymbolAddress((void**)&skh, g_skh); cudaGetSymbolAddress((void**)&skl, g_skl);
    cudaGetSymbolAddress((void**)&svh, g_svh); cudaGetSymbolAddress((void**)&svl, g_svl);
    cudaGetSymbolAddress((void**)&wqh, g_wqh); cudaGetSymbolAddress((void**)&wql, g_wql);
    cudaGetSymbolAddress((void**)&wkh, g_wkh); cudaGetSymbolAddress((void**)&wkl, g_wkl);
    cudaGetSymbolAddress((void**)&wvh, g_wvh); cudaGetSymbolAddress((void**)&wvl, g_wvl);
    cudaGetSymbolAddress((void**)&woh, g_woh); cudaGetSymbolAddress((void**)&wol, g_wol);
    cudaGetSymbolAddress((void**)&q16h, g_q16h); cudaGetSymbolAddress((void**)&q16l, g_q16l);
    cudaGetSymbolAddress((void**)&k16, g_k16);   cudaGetSymbolAddress((void**)&v16, g_v16);

    Cvt7 cv;
    cv.src[0] = query; cv.hi[0] = sqh; cv.lo[0] = sql;
    cv.src[1] = key;   cv.hi[1] = skh; cv.lo[1] = skl;
    cv.src[2] = value; cv.hi[2] = svh; cv.lo[2] = svl;
    cv.src[3] = Wq; cv.hi[3] = wqh; cv.lo[3] = wql;
    cv.src[4] = Wk; cv.hi[4] = wkh; cv.lo[4] = wkl;
    cv.src[5] = Wv; cv.hi[5] = wvh; cv.lo[5] = wvl;
    cv.src[6] = Wo; cv.hi[6] = woh; cv.lo[6] = wol;
    convert_all<<<16384, 256>>>(cv);

    Gemm3 g3;
    g3.Ah[0] = sqh; g3.Al[0] = sql; g3.Wh[0] = wqh; g3.Wl[0] = wql;
    g3.bias[0] = bq; g3.Hh[0] = q16h; g3.Hl[0] = q16l;
    g3.Ah[1] = skh; g3.Al[1] = skl; g3.Wh[1] = wkh; g3.Wl[1] = wkl;
    g3.bias[1] = bk; g3.Hh[1] = k16; g3.Hl[1] = nullptr;
    g3.Ah[2] = svh; g3.Al[2] = svl; g3.Wh[2] = wvh; g3.Wl[2] = wvl;
    g3.bias[2] = bv; g3.Hh[2] = v16; g3.Hl[2] = nullptr;

    cudaFuncSetAttribute(gemm_qkv, cudaFuncAttributeMaxDynamicSharedMemorySize, G3_SMEM);
    cudaFuncSetAttribute(gemm_out, cudaFuncAttributeMaxDynamicSharedMemorySize, G3_SMEM);
    gemm_qkv<<<dim3(HH / 64, MM / 128, 3), 256, G3_SMEM>>>(g3);

    cudaFuncSetAttribute(attn6_kernel, cudaFuncAttributeMaxDynamicSharedMemorySize, ATT6_SMEM);
    attn6_kernel<<<dim3(SS / 128, NHH, BB), 256, ATT6_SMEM>>>(
        q16h, q16l, k16, v16, mask, chp, clp);

    gemm_out<<<dim3(HH / 64, MM / 128), 256, G3_SMEM>>>(chp, clp, woh, wol, bo, out);
}

// round 14
// speedup vs baseline: 4.1820x; 1.1500x over previous
#include <cuda_runtime.h>
#include <cuda_fp16.h>
#include <cstdint>
#include <math.h>

#define BB   2
#define SS   2048
#define HH   1024
#define NHH  16
#define PHH  64
#define MM   (BB*SS)
#define KK   1024

// fp16 scratch
__device__ __half g_ch[MM*KK], g_cl[MM*KK];          // ctx (attn out, fp16 split)
__device__ __half g_sqh[MM*KK], g_sql[MM*KK];        // input staging (split)
__device__ __half g_skh[MM*KK], g_skl[MM*KK];
__device__ __half g_svh[MM*KK], g_svl[MM*KK];
__device__ __half g_wq16[HH*HH], g_wk16[HH*HH];      // weights (single fp16)
__device__ __half g_wv16[HH*HH], g_wo16[HH*HH];
// fp16 q/k/v for attention ([b,h,s,d])
__device__ __half g_q16h[MM*KK], g_q16l[MM*KK];
__device__ __half g_k16[MM*KK], g_v16[MM*KK];

__device__ __forceinline__ uint32_t smem_u32(const void* p) {
    uint32_t a;
    asm("{ .reg .u64 t; cvta.to.shared.u64 t, %1; cvt.u32.u64 %0, t; }" : "=r"(a) : "l"(p));
    return a;
}
__device__ __forceinline__ void cp_async16(uint32_t s, const void* g) {
    asm volatile("cp.async.cg.shared.global [%0], [%1], 16;" :: "r"(s), "l"(g));
}
__device__ __forceinline__ void cp_commit() {
    asm volatile("cp.async.commit_group;" ::: "memory");
}
template<int N> __device__ __forceinline__ void cp_wait() {
    asm volatile("cp.async.wait_group %0;" :: "n"(N) : "memory");
}
__device__ __forceinline__ void ldsm_x4(uint32_t addr, uint32_t* r) {
    asm volatile("ldmatrix.sync.aligned.m8n8.x4.shared.b16 {%0,%1,%2,%3}, [%4];"
                 : "=r"(r[0]), "=r"(r[1]), "=r"(r[2]), "=r"(r[3]) : "r"(addr));
}
__device__ __forceinline__ void ldsm_x4_t(uint32_t addr, uint32_t* r) {
    asm volatile("ldmatrix.sync.aligned.m8n8.x4.trans.shared.b16 {%0,%1,%2,%3}, [%4];"
                 : "=r"(r[0]), "=r"(r[1]), "=r"(r[2]), "=r"(r[3]) : "r"(addr));
}
__device__ __forceinline__ void mmaf16(float* d, const uint32_t* a, const uint32_t* b) {
    asm volatile("mma.sync.aligned.m16n8k16.row.col.f32.f16.f16.f32 "
        "{%0,%1,%2,%3}, {%4,%5,%6,%7}, {%8,%9}, {%0,%1,%2,%3};"
        : "+f"(d[0]), "+f"(d[1]), "+f"(d[2]), "+f"(d[3])
        : "r"(a[0]), "r"(a[1]), "r"(a[2]), "r"(a[3]), "r"(b[0]), "r"(b[1]));
}
__device__ __forceinline__ uint32_t h2bits(__half2 v) { return *(uint32_t*)&v; }

// ---------------------------------------------------------------------------
// Fused convert: jobs 0-2 inputs -> fp16 hi/lo split; jobs 3-6 weights ->
// single fp16. One launch, 16384 blocks.
// ---------------------------------------------------------------------------
struct Cvt7 {
    const float* src[7];
    __half* hi[7];
    __half* lo[7];   // nullptr for weights
};

__global__ __launch_bounds__(256) void convert_all(Cvt7 jobs)
{
    int bid = blockIdx.x;
    int j, base;
    if (bid < 12288) { j = bid >> 12;            base = bid & 4095; }
    else             { j = 3 + ((bid - 12288) >> 10); base = (bid - 12288) & 1023; }
    int i = base * 256 + threadIdx.x;

    float4 v = ((const float4*)jobs.src[j])[i];
    __half2 h01 = __floats2half2_rn(v.x, v.y);
    __half2 h23 = __floats2half2_rn(v.z, v.w);
    uint2 hv = make_uint2(h2bits(h01), h2bits(h23));
    *(uint2*)(jobs.hi[j] + (size_t)i * 4) = hv;
    if (j < 3) {
        __half2 l01 = __floats2half2_rn(v.x - __half2float(__low2half(h01)),
                                        v.y - __half2float(__high2half(h01)));
        __half2 l23 = __floats2half2_rn(v.z - __half2float(__low2half(h23)),
                                        v.w - __half2float(__high2half(h23)));
        uint2 lv = make_uint2(h2bits(l01), h2bits(l23));
        *(uint2*)(jobs.lo[j] + (size_t)i * 4) = lv;
    }
}

// ---------------------------------------------------------------------------
// HMMA GEMM: CTA tile 128x64, BK=64, 8 warps, fp16 2-term (AhW + AlW),
// single sync per chunk. Stage: [Ah 16K | Al 16K | W 8K] x2 = 80KB.
// MODE 0: fp32 C output. MODE 1: split-fp16 output to [b,h,s,d] (Hl optional).
// ---------------------------------------------------------------------------
#define GA_TILE 16384
#define GW_TILE 8192
#define G_STAGE (2*GA_TILE + GW_TILE)    // 40960
#define G3_SMEM (2 * G_STAGE)            // 81920

__device__ __forceinline__ void prefetch_g(
    const __half* __restrict__ Ah, const __half* __restrict__ Al,
    const __half* __restrict__ W,
    int k0, uint32_t stage, int tid)
{
#pragma unroll
    for (int t = 0; t < 2; t++) {
        const __half* src = t ? Al : Ah;
        uint32_t base = stage + t * GA_TILE;
#pragma unroll
        for (int p = 0; p < 4; p++) {
            int idx = tid + p * 256;
            int row = idx >> 3, ch = idx & 7;
            cp_async16(base + row * 128 + ((ch ^ (row & 7)) << 4),
                       src + (size_t)row * KK + k0 + ch * 8);
        }
    }
    {
        uint32_t base = stage + 2 * GA_TILE;
#pragma unroll
        for (int p = 0; p < 2; p++) {
            int idx = tid + p * 256;
            int row = idx >> 3, ch = idx & 7;
            cp_async16(base + row * 128 + ((ch ^ (row & 7)) << 4),
                       W + (size_t)row * KK + k0 + ch * 8);
        }
    }
}

template<int MODE>
__device__ __forceinline__ void gemm_body(
    const __half* Ah, const __half* Al, const __half* W,
    const float* bias, float* C,
    __half* Hhi, __half* Hlo,
    int bm, int bn, uint32_t sbase)
{
    const int tid  = threadIdx.x;
    const int wid  = tid >> 5;
    const int lane = tid & 31;
    const int wm = wid >> 1;
    const int wn = wid & 1;

    const int L7 = lane & 7;
    const int aSel = lane >> 4;
    const int bSel = (lane >> 3) & 1;
    uint32_t aRow[2], bRow[2];
#pragma unroll
    for (int mi = 0; mi < 2; mi++)
        aRow[mi] = (uint32_t)(wm * 32 + mi * 16 + (lane & 15)) * 128;
#pragma unroll
    for (int nb = 0; nb < 2; nb++)
        bRow[nb] = (uint32_t)(wn * 32 + nb * 16 + ((lane >> 4) * 8) + L7) * 128;

    float acc[2][4][4];
#pragma unroll
    for (int mi = 0; mi < 2; mi++)
#pragma unroll
        for (int nj = 0; nj < 4; nj++)
#pragma unroll
            for (int q = 0; q < 4; q++) acc[mi][nj][q] = 0.f;

    prefetch_g(Ah, Al, W, 0, sbase, tid);
    cp_commit();

    for (int it = 0; it < 16; it++) {
        cp_wait<0>();
        __syncthreads();
        if (it < 15) {
            prefetch_g(Ah, Al, W, (it + 1) * 64,
                       sbase + ((it + 1) & 1) * G_STAGE, tid);
            cp_commit();
        }
        const uint32_t tb = sbase + (it & 1) * G_STAGE;
#pragma unroll
        for (int ks = 0; ks < 4; ks++) {
            const int kx = ks * 2;
            uint32_t aH[2][4], aL[2][4], bW[2][4];
#pragma unroll
            for (int mi = 0; mi < 2; mi++) {
                uint32_t ad = tb + aRow[mi] + (uint32_t)(((kx + aSel) ^ L7) << 4);
                ldsm_x4(ad, aH[mi]);
                ldsm_x4(ad + GA_TILE, aL[mi]);
            }
#pragma unroll
            for (int nb = 0; nb < 2; nb++) {
                uint32_t bd = tb + 2 * GA_TILE + bRow[nb] +
                              (uint32_t)(((kx + bSel) ^ L7) << 4);
                ldsm_x4(bd, bW[nb]);
            }
#pragma unroll
            for (int mi = 0; mi < 2; mi++)
#pragma unroll
                for (int nj = 0; nj < 4; nj++)
                    mmaf16(acc[mi][nj], aH[mi], &bW[nj >> 1][(nj & 1) * 2]);
#pragma unroll
            for (int mi = 0; mi < 2; mi++)
#pragma unroll
                for (int nj = 0; nj < 4; nj++)
                    mmaf16(acc[mi][nj], aL[mi], &bW[nj >> 1][(nj & 1) * 2]);
        }
    }

#pragma unroll
    for (int mi = 0; mi < 2; mi++)
#pragma unroll
        for (int nj = 0; nj < 4; nj++) {
            int row0 = bm + wm * 32 + mi * 16 + (lane >> 2);
            int col  = bn + wn * 32 + nj * 8 + (lane & 3) * 2;
            float b0 = bias[col], b1 = bias[col + 1];
#pragma unroll
            for (int half = 0; half < 2; half++) {
                int row = row0 + half * 8;
                float v0 = acc[mi][nj][half * 2 + 0] + b0;
                float v1 = acc[mi][nj][half * 2 + 1] + b1;
                if (MODE == 1) {
                    int b = row >> 11, s = row & 2047;
                    int h = col >> 6,  d = col & 63;
                    size_t idx = (((size_t)(b * NHH + h)) * SS + s) * PHH + d;
                    __half2 hv = __floats2half2_rn(v0, v1);
                    *(__half2*)&Hhi[idx] = hv;
                    if (Hlo) {
                        float r0 = v0 - __half2float(__low2half(hv));
                        float r1 = v1 - __half2float(__high2half(hv));
                        *(__half2*)&Hlo[idx] = __floats2half2_rn(r0, r1);
                    }
                } else {
                    *(float2*)&C[(size_t)row * HH + col] = make_float2(v0, v1);
                }
            }
        }
}

struct Gemm3 {
    const __half *Ah[3], *Al[3], *W[3];
    const float* bias[3];
    __half *Hh[3], *Hl[3];
};

__global__ __launch_bounds__(256, 2) void gemm_qkv(Gemm3 g)
{
    extern __shared__ char smem[];
    const uint32_t sbase = smem_u32(smem);
    const int z = blockIdx.z;
    const int bm = blockIdx.y * 128;
    const int bn = blockIdx.x * 64;
    gemm_body<1>(g.Ah[z] + (size_t)bm * KK, g.Al[z] + (size_t)bm * KK,
                 g.W[z] + (size_t)bn * KK,
                 g.bias[z], nullptr, g.Hh[z], g.Hl[z], bm, bn, sbase);
}

__global__ __launch_bounds__(256, 2) void gemm_out(
    const __half* __restrict__ Ahi, const __half* __restrict__ Alo,
    const __half* __restrict__ W,
    const float* __restrict__ bias, float* __restrict__ C)
{
    extern __shared__ char smem[];
    const uint32_t sbase = smem_u32(smem);
    const int bm = blockIdx.y * 128;
    const int bn = blockIdx.x * 64;
    gemm_body<0>(Ahi + (size_t)bm * KK, Alo + (size_t)bm * KK,
                 W + (size_t)bn * KK,
                 bias, C, nullptr, nullptr, bm, bn, sbase);
}

// ---------------------------------------------------------------------------
// fp16 flash attention: 2-term score (QhKh + QlKh), 2-term PV
// (PhVh + PlVh, P split in registers), K/V single fp16.
// KV tiles 64 rows = 16KB/stage, 4-deep pipeline; Q resident fp16 hi/lo.
// smem: 32KB Q + 4x16KB KV = 96KB -> 2 CTAs/SM. One sync per kt.
// ---------------------------------------------------------------------------
#define KV6_STAGE 16384
#define ATT6_Q    32768
#define ATT6_SMEM (ATT6_Q + 4 * KV6_STAGE)
#define NT6       (SS / 64)

__device__ __forceinline__ void attn6_prefetch(
    const __half* __restrict__ K16, const __half* __restrict__ V16,
    int kt, uint32_t dst, int tid)
{
#pragma unroll
    for (int p = 0; p < 2; p++) {
        int idx = tid + p * 256;
        int row = idx >> 3, ch = idx & 7;
        cp_async16(dst + row * 128 + ((ch ^ (row & 7)) << 4),
                   K16 + (size_t)(kt * 64 + row) * PHH + ch * 8);
    }
#pragma unroll
    for (int p = 0; p < 2; p++) {
        int idx = tid + p * 256;
        int row = idx >> 3, ch = idx & 7;
        cp_async16(dst + 8192 + row * 128 + ((ch ^ (row & 7)) << 4),
                   V16 + (size_t)(kt * 64 + row) * PHH + ch * 8);
    }
}

__global__ __launch_bounds__(256, 2) void attn6_kernel(
    const __half* __restrict__ Qh, const __half* __restrict__ Ql,
    const __half* __restrict__ K16, const __half* __restrict__ V16,
    const float* __restrict__ mask,
    __half* __restrict__ Ch, __half* __restrict__ Cl)
{
    extern __shared__ char smem[];
    const uint32_t sbase = smem_u32(smem);
    const uint32_t kvb = sbase + ATT6_Q;
    const int tid  = threadIdx.x;
    const int wid  = tid >> 5;
    const int lane = tid & 31;
    const int L7   = lane & 7;
    const int qt = blockIdx.x, h = blockIdx.y, b = blockIdx.z;
    const int q0 = qt * 128;

    const size_t hoff = ((size_t)(b * NHH + h)) * SS * PHH;
    const __half* Qhg = Qh + hoff + (size_t)q0 * PHH;
    const __half* Qlg = Ql + hoff + (size_t)q0 * PHH;
    const __half* Kg  = K16 + hoff;
    const __half* Vg  = V16 + hoff;
    const float* Mg = mask + (size_t)b * SS * SS + (size_t)q0 * SS;

    // stage Q (resident: hi at sbase, lo at sbase+16KB)
#pragma unroll
    for (int p = 0; p < 4; p++) {
        int idx = tid + p * 256;
        int row = idx >> 3, ch = idx & 7;
        uint32_t soff = sbase + row * 128 + ((ch ^ (row & 7)) << 4);
        cp_async16(soff, Qhg + (size_t)row * PHH + ch * 8);
        cp_async16(soff + 16384, Qlg + (size_t)row * PHH + ch * 8);
    }
    cp_commit();
    attn6_prefetch(Kg, Vg, 0, kvb + 0 * KV6_STAGE, tid); cp_commit();
    attn6_prefetch(Kg, Vg, 1, kvb + 1 * KV6_STAGE, tid); cp_commit();
    attn6_prefetch(Kg, Vg, 2, kvb + 2 * KV6_STAGE, tid); cp_commit();

    float pv[8][4];
#pragma unroll
    for (int nj = 0; nj < 8; nj++)
#pragma unroll
        for (int q = 0; q < 4; q++) pv[nj][q] = 0.f;
    float mA = -1e30f, mB = -1e30f, lA = 0.f, lB = 0.f;

    const int rA = wid * 16 + (lane >> 2);
    const int rB = rA + 8;
    const uint32_t aRowQ = (uint32_t)(wid * 16 + (lane & 15)) * 128;
    const int aSel = lane >> 4;
    const int bSel = (lane >> 3) & 1;

    for (int kt = 0; kt < NT6; kt++) {
        if (kt + 2 < NT6)      cp_wait<2>();
        else if (kt + 1 < NT6) cp_wait<1>();
        else                   cp_wait<0>();
        __syncthreads();
        if (kt + 3 < NT6) {
            attn6_prefetch(Kg, Vg, kt + 3, kvb + ((kt + 3) & 3) * KV6_STAGE, tid);
            cp_commit();
        }

        const uint32_t kb = kvb + (kt & 3) * KV6_STAGE;
        const uint32_t vb = kb + 8192;

        float accS[8][4];
#pragma unroll
        for (int nj = 0; nj < 8; nj++)
#pragma unroll
            for (int q = 0; q < 4; q++) accS[nj][q] = 0.f;

#pragma unroll
        for (int ks = 0; ks < 4; ks++) {
            uint32_t qad = sbase + aRowQ + (uint32_t)(((2 * ks + aSel) ^ L7) << 4);
            uint32_t qH[4], qL[4];
            ldsm_x4(qad, qH);
            ldsm_x4(qad + 16384, qL);
#pragma unroll
            for (int jp = 0; jp < 4; jp++) {
                uint32_t row = (uint32_t)(jp * 16 + ((lane >> 4) * 8) + L7);
                uint32_t ad = kb + row * 128 +
                              (uint32_t)(((2 * ks + bSel) ^ L7) << 4);
                uint32_t bK[4];
                ldsm_x4(ad, bK);
                mmaf16(accS[2*jp],   qH, &bK[0]);
                mmaf16(accS[2*jp+1], qH, &bK[2]);
                mmaf16(accS[2*jp],   qL, &bK[0]);
                mmaf16(accS[2*jp+1], qL, &bK[2]);
            }
        }

        {
            const int colb = kt * 64 + (lane & 3) * 2;
            const float* mra = &Mg[(size_t)rA * SS + colb];
            const float* mrb = &Mg[(size_t)rB * SS + colb];
#pragma unroll
            for (int nj = 0; nj < 8; nj++) {
                float2 ma = *(const float2*)&mra[nj * 8];
                float2 mb = *(const float2*)&mrb[nj * 8];
                accS[nj][0] *= 0.125f * ma.x;
                accS[nj][1] *= 0.125f * ma.y;
                accS[nj][2] *= 0.125f * mb.x;
                accS[nj][3] *= 0.125f * mb.y;
            }
        }
        float mxA = -1e30f, mxB = -1e30f;
#pragma unroll
        for (int nj = 0; nj < 8; nj++) {
            mxA = fmaxf(mxA, fmaxf(accS[nj][0], accS[nj][1]));
            mxB = fmaxf(mxB, fmaxf(accS[nj][2], accS[nj][3]));
        }
        mxA = fmaxf(mxA, __shfl_xor_sync(0xffffffffu, mxA, 1));
        mxA = fmaxf(mxA, __shfl_xor_sync(0xffffffffu, mxA, 2));
        mxB = fmaxf(mxB, __shfl_xor_sync(0xffffffffu, mxB, 1));
        mxB = fmaxf(mxB, __shfl_xor_sync(0xffffffffu, mxB, 2));
        float mnA = fmaxf(mA, mxA), mnB = fmaxf(mB, mxB);
        float corrA = __expf(mA - mnA), corrB = __expf(mB - mnB);
        float tsA = 0.f, tsB = 0.f;
#pragma unroll
        for (int nj = 0; nj < 8; nj++) {
            accS[nj][0] = __expf(accS[nj][0] - mnA);
            accS[nj][1] = __expf(accS[nj][1] - mnA);
            accS[nj][2] = __expf(accS[nj][2] - mnB);
            accS[nj][3] = __expf(accS[nj][3] - mnB);
            tsA += accS[nj][0] + accS[nj][1];
            tsB += accS[nj][2] + accS[nj][3];
        }
        tsA += __shfl_xor_sync(0xffffffffu, tsA, 1);
        tsA += __shfl_xor_sync(0xffffffffu, tsA, 2);
        tsB += __shfl_xor_sync(0xffffffffu, tsB, 1);
        tsB += __shfl_xor_sync(0xffffffffu, tsB, 2);
        lA = lA * corrA + tsA;
        lB = lB * corrB + tsB;
        mA = mnA; mB = mnB;

#pragma unroll
        for (int nj = 0; nj < 8; nj++) {
            pv[nj][0] *= corrA; pv[nj][1] *= corrA;
            pv[nj][2] *= corrB; pv[nj][3] *= corrB;
        }

#pragma unroll
        for (int ks = 0; ks < 4; ks++) {
            const float* s0 = accS[2*ks];
            const float* s1 = accS[2*ks+1];
            __half2 h0 = __floats2half2_rn(s0[0], s0[1]);
            __half2 h1 = __floats2half2_rn(s0[2], s0[3]);
            __half2 h2 = __floats2half2_rn(s1[0], s1[1]);
            __half2 h3 = __floats2half2_rn(s1[2], s1[3]);
            uint32_t aPH[4] = {h2bits(h0), h2bits(h1), h2bits(h2), h2bits(h3)};
            __half2 e0 = __floats2half2_rn(s0[0] - __half2float(__low2half(h0)),
                                           s0[1] - __half2float(__high2half(h0)));
            __half2 e1 = __floats2half2_rn(s0[2] - __half2float(__low2half(h1)),
                                           s0[3] - __half2float(__high2half(h1)));
            __half2 e2 = __floats2half2_rn(s1[0] - __half2float(__low2half(h2)),
                                           s1[1] - __half2float(__high2half(h2)));
            __half2 e3 = __floats2half2_rn(s1[2] - __half2float(__low2half(h3)),
                                           s1[3] - __half2float(__high2half(h3)));
            uint32_t aPL[4] = {h2bits(e0), h2bits(e1), h2bits(e2), h2bits(e3)};

            uint32_t row = (uint32_t)(ks * 16 + (lane & 15));
#pragma unroll
            for (int jp = 0; jp < 4; jp++) {
                uint32_t ad = vb + row * 128 +
                              (uint32_t)(((2 * jp + (lane >> 4)) ^ L7) << 4);
                uint32_t vK[4];
                ldsm_x4_t(ad, vK);
                mmaf16(pv[2*jp],   aPH, &vK[0]);
                mmaf16(pv[2*jp+1], aPH, &vK[2]);
                mmaf16(pv[2*jp],   aPL, &vK[0]);
                mmaf16(pv[2*jp+1], aPL, &vK[2]);
            }
        }
    }

    const float invA = 1.f / lA, invB = 1.f / lB;
    const int gA = q0 + rA, gB = q0 + rB;
#pragma unroll
    for (int nj = 0; nj < 8; nj++) {
        int d = nj * 8 + (lane & 3) * 2;
        float v0 = pv[nj][0] * invA, v1 = pv[nj][1] * invA;
        float v2 = pv[nj][2] * invB, v3 = pv[nj][3] * invB;
        size_t iA = ((size_t)b * SS + gA) * HH + h * PHH + d;
        size_t iB = ((size_t)b * SS + gB) * HH + h * PHH + d;
        __half2 hA = __floats2half2_rn(v0, v1);
        __half2 lAv = __floats2half2_rn(v0 - __half2float(__low2half(hA)),
                                        v1 - __half2float(__high2half(hA)));
        __half2 hB = __floats2half2_rn(v2, v3);
        __half2 lBv = __floats2half2_rn(v2 - __half2float(__low2half(hB)),
                                        v3 - __half2float(__high2half(hB)));
        *(__half2*)&Ch[iA] = hA;
        *(__half2*)&Cl[iA] = lAv;
        *(__half2*)&Ch[iB] = hB;
        *(__half2*)&Cl[iB] = lBv;
    }
}

extern "C" void kernel_launch(void* const* d_in, const int* in_sizes, int n_in,
                              void* d_out, int out_size)
{
    const float* key   = (const float*)d_in[0];
    const float* value = (const float*)d_in[1];
    const float* query = (const float*)d_in[2];
    const float* mask  = (const float*)d_in[3];
    const float* Wq = (const float*)d_in[5];
    const float* bq = (const float*)d_in[6];
    const float* Wk = (const float*)d_in[7];
    const float* bk = (const float*)d_in[8];
    const float* Wv = (const float*)d_in[9];
    const float* bv = (const float*)d_in[10];
    const float* Wo = (const float*)d_in[11];
    const float* bo = (const float*)d_in[12];
    float* out = (float*)d_out;

    __half *chp,*clp, *sqh,*sql,*skh,*skl,*svh,*svl;
    __half *wq16,*wk16,*wv16,*wo16;
    __half *q16h,*q16l,*k16,*v16;
    cudaGetSymbolAddress((void**)&chp, g_ch); cudaGetSymbolAddress((void**)&clp, g_cl);
    cudaGetSymbolAddress((void**)&sqh, g_sqh); cudaGetSymbolAddress((void**)&sql, g_sql);
    cudaGetSymbolAddress((void**)&skh, g_skh); cudaGetSymbolAddress((void**)&skl, g_skl);
    cudaGetSymbolAddress((void**)&svh, g_svh); cudaGetSymbolAddress((void**)&svl, g_svl);
    cudaGetSymbolAddress((void**)&wq16, g_wq16); cudaGetSymbolAddress((void**)&wk16, g_wk16);
    cudaGetSymbolAddress((void**)&wv16, g_wv16); cudaGetSymbolAddress((void**)&wo16, g_wo16);
    cudaGetSymbolAddress((void**)&q16h, g_q16h); cudaGetSymbolAddress((void**)&q16l, g_q16l);
    cudaGetSymbolAddress((void**)&k16, g_k16);   cudaGetSymbolAddress((void**)&v16, g_v16);

    Cvt7 cv;
    cv.src[0] = query; cv.hi[0] = sqh; cv.lo[0] = sql;
    cv.src[1] = key;   cv.hi[1] = skh; cv.lo[1] = skl;
    cv.src[2] = value; cv.hi[2] = svh; cv.lo[2] = svl;
    cv.src[3] = Wq; cv.hi[3] = wq16; cv.lo[3] = nullptr;
    cv.src[4] = Wk; cv.hi[4] = wk16; cv.lo[4] = nullptr;
    cv.src[5] = Wv; cv.hi[5] = wv16; cv.lo[5] = nullptr;
    cv.src[6] = Wo; cv.hi[6] = wo16; cv.lo[6] = nullptr;
    convert_all<<<16384, 256>>>(cv);

    Gemm3 g3;
    g3.Ah[0] = sqh; g3.Al[0] = sql; g3.W[0] = wq16;
    g3.bias[0] = bq; g3.Hh[0] = q16h; g3.Hl[0] = q16l;
    g3.Ah[1] = skh; g3.Al[1] = skl; g3.W[1] = wk16;
    g3.bias[1] = bk; g3.Hh[1] = k16; g3.Hl[1] = nullptr;
    g3.Ah[2] = svh; g3.Al[2] = svl; g3.W[2] = wv16;
    g3.bias[2] = bv; g3.Hh[2] = v16; g3.Hl[2] = nullptr;

    cudaFuncSetAttribute(gemm_qkv, cudaFuncAttributeMaxDynamicSharedMemorySize, G3_SMEM);
    cudaFuncSetAttribute(gemm_out, cudaFuncAttributeMaxDynamicSharedMemorySize, G3_SMEM);
    gemm_qkv<<<dim3(HH / 64, MM / 128, 3), 256, G3_SMEM>>>(g3);

    cudaFuncSetAttribute(attn6_kernel, cudaFuncAttributeMaxDynamicSharedMemorySize, ATT6_SMEM);
    attn6_kernel<<<dim3(SS / 128, NHH, BB), 256, ATT6_SMEM>>>(
        q16h, q16l, k16, v16, mask, chp, clp);

    gemm_out<<<dim3(HH / 64, MM / 128), 256, G3_SMEM>>>(chp, clp, wo16, bo, out);
}

// round 16
// speedup vs baseline: 4.9559x; 1.1851x over previous
#include <cuda_runtime.h>
#include <cuda_fp16.h>
#include <cstdint>
#include <math.h>

#define BB   2
#define SS   2048
#define HH   1024
#define NHH  16
#define PHH  64
#define MM   (BB*SS)
#define KK   1024

// fp16 scratch (all single precision fp16 now)
__device__ __half g_c16[MM*KK];                 // ctx (attn out)
__device__ __half g_sq[MM*KK], g_sk[MM*KK], g_sv[MM*KK];   // staged inputs
__device__ __half g_wq16[HH*HH], g_wk16[HH*HH];
__device__ __half g_wv16[HH*HH], g_wo16[HH*HH];
__device__ __half g_q16[MM*KK], g_k16[MM*KK], g_v16[MM*KK]; // projected q/k/v

__device__ __forceinline__ uint32_t smem_u32(const void* p) {
    uint32_t a;
    asm("{ .reg .u64 t; cvta.to.shared.u64 t, %1; cvt.u32.u64 %0, t; }" : "=r"(a) : "l"(p));
    return a;
}
__device__ __forceinline__ void cp_async16(uint32_t s, const void* g) {
    asm volatile("cp.async.cg.shared.global [%0], [%1], 16;" :: "r"(s), "l"(g));
}
__device__ __forceinline__ void cp_commit() {
    asm volatile("cp.async.commit_group;" ::: "memory");
}
template<int N> __device__ __forceinline__ void cp_wait() {
    asm volatile("cp.async.wait_group %0;" :: "n"(N) : "memory");
}
__device__ __forceinline__ void ldsm_x4(uint32_t addr, uint32_t* r) {
    asm volatile("ldmatrix.sync.aligned.m8n8.x4.shared.b16 {%0,%1,%2,%3}, [%4];"
                 : "=r"(r[0]), "=r"(r[1]), "=r"(r[2]), "=r"(r[3]) : "r"(addr));
}
__device__ __forceinline__ void ldsm_x4_t(uint32_t addr, uint32_t* r) {
    asm volatile("ldmatrix.sync.aligned.m8n8.x4.trans.shared.b16 {%0,%1,%2,%3}, [%4];"
                 : "=r"(r[0]), "=r"(r[1]), "=r"(r[2]), "=r"(r[3]) : "r"(addr));
}
__device__ __forceinline__ void mmaf16(float* d, const uint32_t* a, const uint32_t* b) {
    asm volatile("mma.sync.aligned.m16n8k16.row.col.f32.f16.f16.f32 "
        "{%0,%1,%2,%3}, {%4,%5,%6,%7}, {%8,%9}, {%0,%1,%2,%3};"
        : "+f"(d[0]), "+f"(d[1]), "+f"(d[2]), "+f"(d[3])
        : "r"(a[0]), "r"(a[1]), "r"(a[2]), "r"(a[3]), "r"(b[0]), "r"(b[1]));
}
__device__ __forceinline__ uint32_t h2bits(__half2 v) { return *(uint32_t*)&v; }

// ---------------------------------------------------------------------------
// Fused convert: 7 arrays -> single fp16, one launch.
// Jobs 0-2: inputs (4096 blocks each); 3-6: weights (1024 blocks each).
// ---------------------------------------------------------------------------
struct Cvt7 {
    const float* src[7];
    __half* dst[7];
};

__global__ __launch_bounds__(256) void convert_all(Cvt7 jobs)
{
    int bid = blockIdx.x;
    int j, base;
    if (bid < 12288) { j = bid >> 12;            base = bid & 4095; }
    else             { j = 3 + ((bid - 12288) >> 10); base = (bid - 12288) & 1023; }
    int i = base * 256 + threadIdx.x;

    float4 v = ((const float4*)jobs.src[j])[i];
    __half2 h01 = __floats2half2_rn(v.x, v.y);
    __half2 h23 = __floats2half2_rn(v.z, v.w);
    *(uint2*)(jobs.dst[j] + (size_t)i * 4) = make_uint2(h2bits(h01), h2bits(h23));
}

// ---------------------------------------------------------------------------
// HMMA GEMM: CTA tile 128x64, BK=64, 8 warps, single fp16 (1-term),
// 4-deep cp.async pipeline. Stage: [A 16K | W 8K] = 24KB x4 = 96KB.
// MODE 0: fp32 C. MODE 1: fp16 output to [b,h,s,d].
// ---------------------------------------------------------------------------
#define GA_TILE 16384
#define GW_TILE 8192
#define G_STAGE (GA_TILE + GW_TILE)      // 24576
#define G4_SMEM (4 * G_STAGE)            // 98304
#define GNK     16

__device__ __forceinline__ void prefetch_g(
    const __half* __restrict__ A, const __half* __restrict__ W,
    int k0, uint32_t stage, int tid)
{
#pragma unroll
    for (int p = 0; p < 4; p++) {
        int idx = tid + p * 256;
        int row = idx >> 3, ch = idx & 7;
        cp_async16(stage + row * 128 + ((ch ^ (row & 7)) << 4),
                   A + (size_t)row * KK + k0 + ch * 8);
    }
#pragma unroll
    for (int p = 0; p < 2; p++) {
        int idx = tid + p * 256;
        int row = idx >> 3, ch = idx & 7;
        cp_async16(stage + GA_TILE + row * 128 + ((ch ^ (row & 7)) << 4),
                   W + (size_t)row * KK + k0 + ch * 8);
    }
}

template<int MODE>
__device__ __forceinline__ void gemm_body(
    const __half* A, const __half* W,
    const float* bias, float* C, __half* Hout,
    int bm, int bn, uint32_t sbase)
{
    const int tid  = threadIdx.x;
    const int wid  = tid >> 5;
    const int lane = tid & 31;
    const int wm = wid >> 1;
    const int wn = wid & 1;

    const int L7 = lane & 7;
    const int aSel = lane >> 4;
    const int bSel = (lane >> 3) & 1;
    uint32_t aRow[2], bRow[2];
#pragma unroll
    for (int mi = 0; mi < 2; mi++)
        aRow[mi] = (uint32_t)(wm * 32 + mi * 16 + (lane & 15)) * 128;
#pragma unroll
    for (int nb = 0; nb < 2; nb++)
        bRow[nb] = (uint32_t)(wn * 32 + nb * 16 + ((lane >> 4) * 8) + L7) * 128;

    float acc[2][4][4];
#pragma unroll
    for (int mi = 0; mi < 2; mi++)
#pragma unroll
        for (int nj = 0; nj < 4; nj++)
#pragma unroll
            for (int q = 0; q < 4; q++) acc[mi][nj][q] = 0.f;

    prefetch_g(A, W, 0, sbase + 0 * G_STAGE, tid); cp_commit();
    prefetch_g(A, W, 64, sbase + 1 * G_STAGE, tid); cp_commit();
    prefetch_g(A, W, 128, sbase + 2 * G_STAGE, tid); cp_commit();

    for (int it = 0; it < GNK; it++) {
        if (it + 2 < GNK)      cp_wait<2>();
        else if (it + 1 < GNK) cp_wait<1>();
        else                   cp_wait<0>();
        __syncthreads();
        if (it + 3 < GNK) {
            prefetch_g(A, W, (it + 3) * 64, sbase + ((it + 3) & 3) * G_STAGE, tid);
            cp_commit();
        }
        const uint32_t tb = sbase + (it & 3) * G_STAGE;
#pragma unroll
        for (int ks = 0; ks < 4; ks++) {
            const int kx = ks * 2;
            uint32_t aF[2][4], bW[2][4];
#pragma unroll
            for (int mi = 0; mi < 2; mi++) {
                uint32_t ad = tb + aRow[mi] + (uint32_t)(((kx + aSel) ^ L7) << 4);
                ldsm_x4(ad, aF[mi]);
            }
#pragma unroll
            for (int nb = 0; nb < 2; nb++) {
                uint32_t bd = tb + GA_TILE + bRow[nb] +
                              (uint32_t)(((kx + bSel) ^ L7) << 4);
                ldsm_x4(bd, bW[nb]);
            }
#pragma unroll
            for (int mi = 0; mi < 2; mi++)
#pragma unroll
                for (int nj = 0; nj < 4; nj++)
                    mmaf16(acc[mi][nj], aF[mi], &bW[nj >> 1][(nj & 1) * 2]);
        }
    }

#pragma unroll
    for (int mi = 0; mi < 2; mi++)
#pragma unroll
        for (int nj = 0; nj < 4; nj++) {
            int row0 = bm + wm * 32 + mi * 16 + (lane >> 2);
            int col  = bn + wn * 32 + nj * 8 + (lane & 3) * 2;
            float b0 = bias[col], b1 = bias[col + 1];
#pragma unroll
            for (int half = 0; half < 2; half++) {
                int row = row0 + half * 8;
                float v0 = acc[mi][nj][half * 2 + 0] + b0;
                float v1 = acc[mi][nj][half * 2 + 1] + b1;
                if (MODE == 1) {
                    int b = row >> 11, s = row & 2047;
                    int h = col >> 6,  d = col & 63;
                    size_t idx = (((size_t)(b * NHH + h)) * SS + s) * PHH + d;
                    *(__half2*)&Hout[idx] = __floats2half2_rn(v0, v1);
                } else {
                    *(float2*)&C[(size_t)row * HH + col] = make_float2(v0, v1);
                }
            }
        }
}

struct Gemm3 {
    const __half *A[3], *W[3];
    const float* bias[3];
    __half *H[3];
};

__global__ __launch_bounds__(256, 2) void gemm_qkv(Gemm3 g)
{
    extern __shared__ char smem[];
    const uint32_t sbase = smem_u32(smem);
    const int z = blockIdx.z;
    const int bm = blockIdx.y * 128;
    const int bn = blockIdx.x * 64;
    gemm_body<1>(g.A[z] + (size_t)bm * KK, g.W[z] + (size_t)bn * KK,
                 g.bias[z], nullptr, g.H[z], bm, bn, sbase);
}

__global__ __launch_bounds__(256, 2) void gemm_out(
    const __half* __restrict__ A, const __half* __restrict__ W,
    const float* __restrict__ bias, float* __restrict__ C)
{
    extern __shared__ char smem[];
    const uint32_t sbase = smem_u32(smem);
    const int bm = blockIdx.y * 128;
    const int bn = blockIdx.x * 64;
    gemm_body<0>(A + (size_t)bm * KK, W + (size_t)bn * KK,
                 bias, C, nullptr, bm, bn, sbase);
}

// ---------------------------------------------------------------------------
// fp16 flash attention: 1-term score (QK), 1-term PV (PV), all single fp16.
// KV tiles 64 rows = 16KB/stage, 4-deep pipeline; Q resident (16KB).
// smem: 16KB Q + 4x16KB KV = 80KB -> 2 CTAs/SM. One sync per kt.
// ---------------------------------------------------------------------------
#define KV7_STAGE 16384
#define ATT7_Q    16384
#define ATT7_SMEM (ATT7_Q + 4 * KV7_STAGE)   // 81920
#define NT7       (SS / 64)

__device__ __forceinline__ void attn7_prefetch(
    const __half* __restrict__ K16, const __half* __restrict__ V16,
    int kt, uint32_t dst, int tid)
{
#pragma unroll
    for (int p = 0; p < 2; p++) {
        int idx = tid + p * 256;
        int row = idx >> 3, ch = idx & 7;
        cp_async16(dst + row * 128 + ((ch ^ (row & 7)) << 4),
                   K16 + (size_t)(kt * 64 + row) * PHH + ch * 8);
    }
#pragma unroll
    for (int p = 0; p < 2; p++) {
        int idx = tid + p * 256;
        int row = idx >> 3, ch = idx & 7;
        cp_async16(dst + 8192 + row * 128 + ((ch ^ (row & 7)) << 4),
                   V16 + (size_t)(kt * 64 + row) * PHH + ch * 8);
    }
}

__global__ __launch_bounds__(256, 2) void attn7_kernel(
    const __half* __restrict__ Q16,
    const __half* __restrict__ K16, const __half* __restrict__ V16,
    const float* __restrict__ mask,
    __half* __restrict__ C16)
{
    extern __shared__ char smem[];
    const uint32_t sbase = smem_u32(smem);
    const uint32_t kvb = sbase + ATT7_Q;
    const int tid  = threadIdx.x;
    const int wid  = tid >> 5;
    const int lane = tid & 31;
    const int L7   = lane & 7;
    const int qt = blockIdx.x, h = blockIdx.y, b = blockIdx.z;
    const int q0 = qt * 128;

    const size_t hoff = ((size_t)(b * NHH + h)) * SS * PHH;
    const __half* Qg = Q16 + hoff + (size_t)q0 * PHH;
    const __half* Kg = K16 + hoff;
    const __half* Vg = V16 + hoff;
    const float* Mg = mask + (size_t)b * SS * SS + (size_t)q0 * SS;

    // stage Q (resident)
#pragma unroll
    for (int p = 0; p < 4; p++) {
        int idx = tid + p * 256;
        int row = idx >> 3, ch = idx & 7;
        cp_async16(sbase + row * 128 + ((ch ^ (row & 7)) << 4),
                   Qg + (size_t)row * PHH + ch * 8);
    }
    cp_commit();
    attn7_prefetch(Kg, Vg, 0, kvb + 0 * KV7_STAGE, tid); cp_commit();
    attn7_prefetch(Kg, Vg, 1, kvb + 1 * KV7_STAGE, tid); cp_commit();
    attn7_prefetch(Kg, Vg, 2, kvb + 2 * KV7_STAGE, tid); cp_commit();

    float pv[8][4];
#pragma unroll
    for (int nj = 0; nj < 8; nj++)
#pragma unroll
        for (int q = 0; q < 4; q++) pv[nj][q] = 0.f;
    float mA = -1e30f, mB = -1e30f, lA = 0.f, lB = 0.f;

    const int rA = wid * 16 + (lane >> 2);
    const int rB = rA + 8;
    const uint32_t aRowQ = (uint32_t)(wid * 16 + (lane & 15)) * 128;
    const int aSel = lane >> 4;
    const int bSel = (lane >> 3) & 1;

    // Q fragments live in registers for the whole kernel (single precision Q)
    uint32_t qF[4][4];
#pragma unroll
    for (int p = 0; p < 3; p++) { }   // (no-op; Q frags loaded after first wait)

    for (int kt = 0; kt < NT7; kt++) {
        if (kt + 2 < NT7)      cp_wait<2>();
        else if (kt + 1 < NT7) cp_wait<1>();
        else                   cp_wait<0>();
        __syncthreads();
        if (kt == 0) {
#pragma unroll
            for (int ks = 0; ks < 4; ks++) {
                uint32_t qad = sbase + aRowQ + (uint32_t)(((2 * ks + aSel) ^ L7) << 4);
                ldsm_x4(qad, qF[ks]);
            }
        }
        if (kt + 3 < NT7) {
            attn7_prefetch(Kg, Vg, kt + 3, kvb + ((kt + 3) & 3) * KV7_STAGE, tid);
            cp_commit();
        }

        const uint32_t kb = kvb + (kt & 3) * KV7_STAGE;
        const uint32_t vb = kb + 8192;

        // ---- score: S[16 x 64] = Q K^T ----
        float accS[8][4];
#pragma unroll
        for (int nj = 0; nj < 8; nj++)
#pragma unroll
            for (int q = 0; q < 4; q++) accS[nj][q] = 0.f;

#pragma unroll
        for (int ks = 0; ks < 4; ks++) {
#pragma unroll
            for (int jp = 0; jp < 4; jp++) {
                uint32_t row = (uint32_t)(jp * 16 + ((lane >> 4) * 8) + L7);
                uint32_t ad = kb + row * 128 +
                              (uint32_t)(((2 * ks + bSel) ^ L7) << 4);
                uint32_t bK[4];
                ldsm_x4(ad, bK);
                mmaf16(accS[2*jp],   qF[ks], &bK[0]);
                mmaf16(accS[2*jp+1], qF[ks], &bK[2]);
            }
        }

        // ---- scale * mask, online softmax ----
        {
            const int colb = kt * 64 + (lane & 3) * 2;
            const float* mra = &Mg[(size_t)rA * SS + colb];
            const float* mrb = &Mg[(size_t)rB * SS + colb];
#pragma unroll
            for (int nj = 0; nj < 8; nj++) {
                float2 ma = *(const float2*)&mra[nj * 8];
                float2 mb = *(const float2*)&mrb[nj * 8];
                accS[nj][0] *= 0.125f * ma.x;
                accS[nj][1] *= 0.125f * ma.y;
                accS[nj][2] *= 0.125f * mb.x;
                accS[nj][3] *= 0.125f * mb.y;
            }
        }
        float mxA = -1e30f, mxB = -1e30f;
#pragma unroll
        for (int nj = 0; nj < 8; nj++) {
            mxA = fmaxf(mxA, fmaxf(accS[nj][0], accS[nj][1]));
            mxB = fmaxf(mxB, fmaxf(accS[nj][2], accS[nj][3]));
        }
        mxA = fmaxf(mxA, __shfl_xor_sync(0xffffffffu, mxA, 1));
        mxA = fmaxf(mxA, __shfl_xor_sync(0xffffffffu, mxA, 2));
        mxB = fmaxf(mxB, __shfl_xor_sync(0xffffffffu, mxB, 1));
        mxB = fmaxf(mxB, __shfl_xor_sync(0xffffffffu, mxB, 2));
        float mnA = fmaxf(mA, mxA), mnB = fmaxf(mB, mxB);
        float corrA = __expf(mA - mnA), corrB = __expf(mB - mnB);
        float tsA = 0.f, tsB = 0.f;
#pragma unroll
        for (int nj = 0; nj < 8; nj++) {
            accS[nj][0] = __expf(accS[nj][0] - mnA);
            accS[nj][1] = __expf(accS[nj][1] - mnA);
            accS[nj][2] = __expf(accS[nj][2] - mnB);
            accS[nj][3] = __expf(accS[nj][3] - mnB);
            tsA += accS[nj][0] + accS[nj][1];
            tsB += accS[nj][2] + accS[nj][3];
        }
        tsA += __shfl_xor_sync(0xffffffffu, tsA, 1);
        tsA += __shfl_xor_sync(0xffffffffu, tsA, 2);
        tsB += __shfl_xor_sync(0xffffffffu, tsB, 1);
        tsB += __shfl_xor_sync(0xffffffffu, tsB, 2);
        lA = lA * corrA + tsA;
        lB = lB * corrB + tsB;
        mA = mnA; mB = mnB;

#pragma unroll
        for (int nj = 0; nj < 8; nj++) {
            pv[nj][0] *= corrA; pv[nj][1] *= corrA;
            pv[nj][2] *= corrB; pv[nj][3] *= corrB;
        }

        // ---- PV: P (fp16, from registers) @ V ----
#pragma unroll
        for (int ks = 0; ks < 4; ks++) {
            const float* s0 = accS[2*ks];
            const float* s1 = accS[2*ks+1];
            __half2 h0 = __floats2half2_rn(s0[0], s0[1]);
            __half2 h1 = __floats2half2_rn(s0[2], s0[3]);
            __half2 h2 = __floats2half2_rn(s1[0], s1[1]);
            __half2 h3 = __floats2half2_rn(s1[2], s1[3]);
            uint32_t aP[4] = {h2bits(h0), h2bits(h1), h2bits(h2), h2bits(h3)};

            uint32_t row = (uint32_t)(ks * 16 + (lane & 15));
#pragma unroll
            for (int jp = 0; jp < 4; jp++) {
                uint32_t ad = vb + row * 128 +
                              (uint32_t)(((2 * jp + (lane >> 4)) ^ L7) << 4);
                uint32_t vK[4];
                ldsm_x4_t(ad, vK);
                mmaf16(pv[2*jp],   aP, &vK[0]);
                mmaf16(pv[2*jp+1], aP, &vK[2]);
            }
        }
    }

    const float invA = 1.f / lA, invB = 1.f / lB;
    const int gA = q0 + rA, gB = q0 + rB;
#pragma unroll
    for (int nj = 0; nj < 8; nj++) {
        int d = nj * 8 + (lane & 3) * 2;
        size_t iA = ((size_t)b * SS + gA) * HH + h * PHH + d;
        size_t iB = ((size_t)b * SS + gB) * HH + h * PHH + d;
        *(__half2*)&C16[iA] = __floats2half2_rn(pv[nj][0] * invA, pv[nj][1] * invA);
        *(__half2*)&C16[iB] = __floats2half2_rn(pv[nj][2] * invB, pv[nj][3] * invB);
    }
}

extern "C" void kernel_launch(void* const* d_in, const int* in_sizes, int n_in,
                              void* d_out, int out_size)
{
    const float* key   = (const float*)d_in[0];
    const float* value = (const float*)d_in[1];
    const float* query = (const float*)d_in[2];
    const float* mask  = (const float*)d_in[3];
    const float* Wq = (const float*)d_in[5];
    const float* bq = (const float*)d_in[6];
    const float* Wk = (const float*)d_in[7];
    const float* bk = (const float*)d_in[8];
    const float* Wv = (const float*)d_in[9];
    const float* bv = (const float*)d_in[10];
    const float* Wo = (const float*)d_in[11];
    const float* bo = (const float*)d_in[12];
    float* out = (float*)d_out;

    __half *c16, *sq, *sk, *sv, *wq16, *wk16, *wv16, *wo16, *q16, *k16, *v16;
    cudaGetSymbolAddress((void**)&c16, g_c16);
    cudaGetSymbolAddress((void**)&sq, g_sq);
    cudaGetSymbolAddress((void**)&sk, g_sk);
    cudaGetSymbolAddress((void**)&sv, g_sv);
    cudaGetSymbolAddress((void**)&wq16, g_wq16);
    cudaGetSymbolAddress((void**)&wk16, g_wk16);
    cudaGetSymbolAddress((void**)&wv16, g_wv16);
    cudaGetSymbolAddress((void**)&wo16, g_wo16);
    cudaGetSymbolAddress((void**)&q16, g_q16);
    cudaGetSymbolAddress((void**)&k16, g_k16);
    cudaGetSymbolAddress((void**)&v16, g_v16);

    Cvt7 cv;
    cv.src[0] = query; cv.dst[0] = sq;
    cv.src[1] = key;   cv.dst[1] = sk;
    cv.src[2] = value; cv.dst[2] = sv;
    cv.src[3] = Wq; cv.dst[3] = wq16;
    cv.src[4] = Wk; cv.dst[4] = wk16;
    cv.src[5] = Wv; cv.dst[5] = wv16;
    cv.src[6] = Wo; cv.dst[6] = wo16;
    convert_all<<<16384, 256>>>(cv);

    Gemm3 g3;
    g3.A[0] = sq; g3.W[0] = wq16; g3.bias[0] = bq; g3.H[0] = q16;
    g3.A[1] = sk; g3.W[1] = wk16; g3.bias[1] = bk; g3.H[1] = k16;
    g3.A[2] = sv; g3.W[2] = wv16; g3.bias[2] = bv; g3.H[2] = v16;

    cudaFuncSetAttribute(gemm_qkv, cudaFuncAttributeMaxDynamicSharedMemorySize, G4_SMEM);
    cudaFuncSetAttribute(gemm_out, cudaFuncAttributeMaxDynamicSharedMemorySize, G4_SMEM);
    gemm_qkv<<<dim3(HH / 64, MM / 128, 3), 256, G4_SMEM>>>(g3);

    cudaFuncSetAttribute(attn7_kernel, cudaFuncAttributeMaxDynamicSharedMemorySize, ATT7_SMEM);
    attn7_kernel<<<dim3(SS / 128, NHH, BB), 256, ATT7_SMEM>>>(
        q16, k16, v16, mask, c16);

    gemm_out<<<dim3(HH / 64, MM / 128), 256, G4_SMEM>>>(c16, wo16, bo, out);
}

// round 17
// speedup vs baseline: 5.2869x; 1.0668x over previous
#include <cuda_runtime.h>
#include <cuda_fp16.h>
#include <cstdint>
#include <math.h>

#define BB   2
#define SS   2048
#define HH   1024
#define NHH  16
#define PHH  64
#define MM   (BB*SS)
#define KK   1024

__device__ __half g_c16[MM*KK];
__device__ __half g_sq[MM*KK], g_sk[MM*KK], g_sv[MM*KK];
__device__ __half g_wq16[HH*HH], g_wk16[HH*HH];
__device__ __half g_wv16[HH*HH], g_wo16[HH*HH];
__device__ __half g_q16[MM*KK], g_k16[MM*KK], g_v16[MM*KK];

__device__ __forceinline__ uint32_t smem_u32(const void* p) {
    uint32_t a;
    asm("{ .reg .u64 t; cvta.to.shared.u64 t, %1; cvt.u32.u64 %0, t; }" : "=r"(a) : "l"(p));
    return a;
}
__device__ __forceinline__ void cp_async16(uint32_t s, const void* g) {
    asm volatile("cp.async.cg.shared.global [%0], [%1], 16;" :: "r"(s), "l"(g));
}
__device__ __forceinline__ void cp_commit() {
    asm volatile("cp.async.commit_group;" ::: "memory");
}
template<int N> __device__ __forceinline__ void cp_wait() {
    asm volatile("cp.async.wait_group %0;" :: "n"(N) : "memory");
}
__device__ __forceinline__ void ldsm_x4(uint32_t addr, uint32_t* r) {
    asm volatile("ldmatrix.sync.aligned.m8n8.x4.shared.b16 {%0,%1,%2,%3}, [%4];"
                 : "=r"(r[0]), "=r"(r[1]), "=r"(r[2]), "=r"(r[3]) : "r"(addr));
}
__device__ __forceinline__ void ldsm_x4_t(uint32_t addr, uint32_t* r) {
    asm volatile("ldmatrix.sync.aligned.m8n8.x4.trans.shared.b16 {%0,%1,%2,%3}, [%4];"
                 : "=r"(r[0]), "=r"(r[1]), "=r"(r[2]), "=r"(r[3]) : "r"(addr));
}
__device__ __forceinline__ void mmaf16(float* d, const uint32_t* a, const uint32_t* b) {
    asm volatile("mma.sync.aligned.m16n8k16.row.col.f32.f16.f16.f32 "
        "{%0,%1,%2,%3}, {%4,%5,%6,%7}, {%8,%9}, {%0,%1,%2,%3};"
        : "+f"(d[0]), "+f"(d[1]), "+f"(d[2]), "+f"(d[3])
        : "r"(a[0]), "r"(a[1]), "r"(a[2]), "r"(a[3]), "r"(b[0]), "r"(b[1]));
}
__device__ __forceinline__ uint32_t h2bits(__half2 v) { return *(uint32_t*)&v; }

// ---------------------------------------------------------------------------
// Fused convert: 7 arrays -> fp16, one launch.
// ---------------------------------------------------------------------------
struct Cvt7 {
    const float* src[7];
    __half* dst[7];
};

__global__ __launch_bounds__(256) void convert_all(Cvt7 jobs)
{
    int bid = blockIdx.x;
    int j, base;
    if (bid < 12288) { j = bid >> 12;            base = bid & 4095; }
    else             { j = 3 + ((bid - 12288) >> 10); base = (bid - 12288) & 1023; }
    int i = base * 256 + threadIdx.x;

    float4 v = ((const float4*)jobs.src[j])[i];
    __half2 h01 = __floats2half2_rn(v.x, v.y);
    __half2 h23 = __floats2half2_rn(v.z, v.w);
    *(uint2*)(jobs.dst[j] + (size_t)i * 4) = make_uint2(h2bits(h01), h2bits(h23));
}

// ---------------------------------------------------------------------------
// HMMA GEMM: CTA tile 128x128, BK=64, 8 warps (warp tile 32x64), fp16 1-term,
// 3-deep cp.async pipeline. Stage: [A 16K | W 16K] = 32KB x3 = 96KB.
// ---------------------------------------------------------------------------
#define GA_TILE 16384
#define GW_TILE 16384
#define G_STAGE (GA_TILE + GW_TILE)      // 32768
#define G5_SMEM (3 * G_STAGE)            // 98304
#define GNK     16

__device__ __forceinline__ void prefetch_g(
    const __half* __restrict__ A, const __half* __restrict__ W,
    int k0, uint32_t stage, int tid)
{
#pragma unroll
    for (int p = 0; p < 4; p++) {
        int idx = tid + p * 256;
        int row = idx >> 3, ch = idx & 7;
        cp_async16(stage + row * 128 + ((ch ^ (row & 7)) << 4),
                   A + (size_t)row * KK + k0 + ch * 8);
    }
#pragma unroll
    for (int p = 0; p < 4; p++) {
        int idx = tid + p * 256;
        int row = idx >> 3, ch = idx & 7;
        cp_async16(stage + GA_TILE + row * 128 + ((ch ^ (row & 7)) << 4),
                   W + (size_t)row * KK + k0 + ch * 8);
    }
}

template<int MODE>
__device__ __forceinline__ void gemm_body(
    const __half* A, const __half* W,
    const float* bias, float* C, __half* Hout,
    int bm, int bn, uint32_t sbase)
{
    const int tid  = threadIdx.x;
    const int wid  = tid >> 5;
    const int lane = tid & 31;
    const int wm = wid >> 1;          // 0..3 (32 rows each)
    const int wn = wid & 1;           // 0..1 (64 cols each)

    const int L7 = lane & 7;
    const int aSel = lane >> 4;
    const int bSel = (lane >> 3) & 1;
    uint32_t aRow[2], bRow[4];
#pragma unroll
    for (int mi = 0; mi < 2; mi++)
        aRow[mi] = (uint32_t)(wm * 32 + mi * 16 + (lane & 15)) * 128;
#pragma unroll
    for (int nb = 0; nb < 4; nb++)
        bRow[nb] = (uint32_t)(wn * 64 + nb * 16 + ((lane >> 4) * 8) + L7) * 128;

    float acc[2][8][4];
#pragma unroll
    for (int mi = 0; mi < 2; mi++)
#pragma unroll
        for (int nj = 0; nj < 8; nj++)
#pragma unroll
            for (int q = 0; q < 4; q++) acc[mi][nj][q] = 0.f;

    prefetch_g(A, W, 0, sbase + 0 * G_STAGE, tid); cp_commit();
    prefetch_g(A, W, 64, sbase + 1 * G_STAGE, tid); cp_commit();

    for (int it = 0; it < GNK; it++) {
        if (it + 1 < GNK) cp_wait<1>();
        else              cp_wait<0>();
        __syncthreads();
        if (it + 2 < GNK) {
            prefetch_g(A, W, (it + 2) * 64, sbase + ((it + 2) % 3) * G_STAGE, tid);
            cp_commit();
        }
        const uint32_t tb = sbase + (it % 3) * G_STAGE;
#pragma unroll
        for (int ks = 0; ks < 4; ks++) {
            const int kx = ks * 2;
            uint32_t aF[2][4], bW[4][4];
#pragma unroll
            for (int mi = 0; mi < 2; mi++) {
                uint32_t ad = tb + aRow[mi] + (uint32_t)(((kx + aSel) ^ L7) << 4);
                ldsm_x4(ad, aF[mi]);
            }
#pragma unroll
            for (int nb = 0; nb < 4; nb++) {
                uint32_t bd = tb + GA_TILE + bRow[nb] +
                              (uint32_t)(((kx + bSel) ^ L7) << 4);
                ldsm_x4(bd, bW[nb]);
            }
#pragma unroll
            for (int mi = 0; mi < 2; mi++)
#pragma unroll
                for (int nj = 0; nj < 8; nj++)
                    mmaf16(acc[mi][nj], aF[mi], &bW[nj >> 1][(nj & 1) * 2]);
        }
    }

#pragma unroll
    for (int mi = 0; mi < 2; mi++)
#pragma unroll
        for (int nj = 0; nj < 8; nj++) {
            int row0 = bm + wm * 32 + mi * 16 + (lane >> 2);
            int col  = bn + wn * 64 + nj * 8 + (lane & 3) * 2;
            float b0 = bias[col], b1 = bias[col + 1];
#pragma unroll
            for (int half = 0; half < 2; half++) {
                int row = row0 + half * 8;
                float v0 = acc[mi][nj][half * 2 + 0] + b0;
                float v1 = acc[mi][nj][half * 2 + 1] + b1;
                if (MODE == 1) {
                    int b = row >> 11, s = row & 2047;
                    int h = col >> 6,  d = col & 63;
                    size_t idx = (((size_t)(b * NHH + h)) * SS + s) * PHH + d;
                    *(__half2*)&Hout[idx] = __floats2half2_rn(v0, v1);
                } else {
                    *(float2*)&C[(size_t)row * HH + col] = make_float2(v0, v1);
                }
            }
        }
}

struct Gemm3 {
    const __half *A[3], *W[3];
    const float* bias[3];
    __half *H[3];
};

__global__ __launch_bounds__(256, 2) void gemm_qkv(Gemm3 g)
{
    extern __shared__ char smem[];
    const uint32_t sbase = smem_u32(smem);
    const int z = blockIdx.z;
    const int bm = blockIdx.y * 128;
    const int bn = blockIdx.x * 128;
    gemm_body<1>(g.A[z] + (size_t)bm * KK, g.W[z] + (size_t)bn * KK,
                 g.bias[z], nullptr, g.H[z], bm, bn, sbase);
}

__global__ __launch_bounds__(256, 2) void gemm_out(
    const __half* __restrict__ A, const __half* __restrict__ W,
    const float* __restrict__ bias, float* __restrict__ C)
{
    extern __shared__ char smem[];
    const uint32_t sbase = smem_u32(smem);
    const int bm = blockIdx.y * 128;
    const int bn = blockIdx.x * 128;
    gemm_body<0>(A + (size_t)bm * KK, W + (size_t)bn * KK,
                 bias, C, nullptr, bm, bn, sbase);
}

// ---------------------------------------------------------------------------
// fp16 flash attention, 2 HEADS PER CTA (mask regs reused across heads).
// Grid (S/128, NH/2, B). KV stage = K0|V0|K1|V1 = 32KB, 4-deep.
// smem: 32KB Q(2 heads) + 128KB KV = 160KB -> 1 CTA/SM.
// ---------------------------------------------------------------------------
#define KV8_STAGE 32768
#define ATT8_Q    32768
#define ATT8_SMEM (ATT8_Q + 4 * KV8_STAGE)   // 163840
#define NT8       (SS / 64)

__device__ __forceinline__ void attn8_prefetch(
    const __half* __restrict__ K0, const __half* __restrict__ V0,
    const __half* __restrict__ K1, const __half* __restrict__ V1,
    int kt, uint32_t dst, int tid)
{
    const __half* srcs[4] = {K0, V0, K1, V1};
#pragma unroll
    for (int t = 0; t < 4; t++) {
#pragma unroll
        for (int p = 0; p < 2; p++) {
            int idx = tid + p * 256;
            int row = idx >> 3, ch = idx & 7;
            cp_async16(dst + t * 8192 + row * 128 + ((ch ^ (row & 7)) << 4),
                       srcs[t] + (size_t)(kt * 64 + row) * PHH + ch * 8);
        }
    }
}

__global__ __launch_bounds__(256, 1) void attn8_kernel(
    const __half* __restrict__ Q16,
    const __half* __restrict__ K16, const __half* __restrict__ V16,
    const float* __restrict__ mask,
    __half* __restrict__ C16)
{
    extern __shared__ char smem[];
    const uint32_t sbase = smem_u32(smem);
    const uint32_t kvb = sbase + ATT8_Q;
    const int tid  = threadIdx.x;
    const int wid  = tid >> 5;
    const int lane = tid & 31;
    const int L7   = lane & 7;
    const int qt = blockIdx.x, hy = blockIdx.y, b = blockIdx.z;
    const int q0 = qt * 128;
    const int h0 = hy * 2;

    const size_t hoff0 = ((size_t)(b * NHH + h0)) * SS * PHH;
    const size_t hoff1 = hoff0 + (size_t)SS * PHH;
    const __half* Qg0 = Q16 + hoff0 + (size_t)q0 * PHH;
    const __half* Qg1 = Q16 + hoff1 + (size_t)q0 * PHH;
    const __half* Kg0 = K16 + hoff0;
    const __half* Vg0 = V16 + hoff0;
    const __half* Kg1 = K16 + hoff1;
    const __half* Vg1 = V16 + hoff1;
    const float* Mg = mask + (size_t)b * SS * SS + (size_t)q0 * SS;

    // stage both Q tiles (resident)
#pragma unroll
    for (int p = 0; p < 4; p++) {
        int idx = tid + p * 256;
        int row = idx >> 3, ch = idx & 7;
        uint32_t soff = sbase + row * 128 + ((ch ^ (row & 7)) << 4);
        cp_async16(soff, Qg0 + (size_t)row * PHH + ch * 8);
        cp_async16(soff + 16384, Qg1 + (size_t)row * PHH + ch * 8);
    }
    cp_commit();
    attn8_prefetch(Kg0, Vg0, Kg1, Vg1, 0, kvb + 0 * KV8_STAGE, tid); cp_commit();
    attn8_prefetch(Kg0, Vg0, Kg1, Vg1, 1, kvb + 1 * KV8_STAGE, tid); cp_commit();
    attn8_prefetch(Kg0, Vg0, Kg1, Vg1, 2, kvb + 2 * KV8_STAGE, tid); cp_commit();

    float pv[2][8][4];
#pragma unroll
    for (int hh = 0; hh < 2; hh++)
#pragma unroll
        for (int nj = 0; nj < 8; nj++)
#pragma unroll
            for (int q = 0; q < 4; q++) pv[hh][nj][q] = 0.f;
    float mA[2] = {-1e30f, -1e30f}, mB[2] = {-1e30f, -1e30f};
    float lA[2] = {0.f, 0.f}, lB[2] = {0.f, 0.f};

    const int rA = wid * 16 + (lane >> 2);
    const int rB = rA + 8;
    const uint32_t aRowQ = (uint32_t)(wid * 16 + (lane & 15)) * 128;
    const int aSel = lane >> 4;
    const int bSel = (lane >> 3) & 1;

    for (int kt = 0; kt < NT8; kt++) {
        if (kt + 2 < NT8)      cp_wait<2>();
        else if (kt + 1 < NT8) cp_wait<1>();
        else                   cp_wait<0>();
        __syncthreads();
        if (kt + 3 < NT8) {
            attn8_prefetch(Kg0, Vg0, Kg1, Vg1, kt + 3,
                           kvb + ((kt + 3) & 3) * KV8_STAGE, tid);
            cp_commit();
        }

        // ---- mask into regs, reused by BOTH heads ----
        float2 pmA[8], pmB[8];
        {
            const int colb = kt * 64 + (lane & 3) * 2;
            const float* mra = &Mg[(size_t)rA * SS + colb];
            const float* mrb = &Mg[(size_t)rB * SS + colb];
#pragma unroll
            for (int nj = 0; nj < 8; nj++) {
                pmA[nj] = *(const float2*)&mra[nj * 8];
                pmB[nj] = *(const float2*)&mrb[nj * 8];
            }
        }

        const uint32_t stg = kvb + (kt & 3) * KV8_STAGE;

#pragma unroll
        for (int hh = 0; hh < 2; hh++) {
            const uint32_t qb = sbase + hh * 16384;
            const uint32_t kb = stg + hh * 16384;
            const uint32_t vb = kb + 8192;

            // Q fragments for this head
            uint32_t qF[4][4];
#pragma unroll
            for (int ks = 0; ks < 4; ks++) {
                uint32_t qad = qb + aRowQ + (uint32_t)(((2 * ks + aSel) ^ L7) << 4);
                ldsm_x4(qad, qF[ks]);
            }

            // score
            float accS[8][4];
#pragma unroll
            for (int nj = 0; nj < 8; nj++)
#pragma unroll
                for (int q = 0; q < 4; q++) accS[nj][q] = 0.f;

#pragma unroll
            for (int ks = 0; ks < 4; ks++) {
#pragma unroll
                for (int jp = 0; jp < 4; jp++) {
                    uint32_t row = (uint32_t)(jp * 16 + ((lane >> 4) * 8) + L7);
                    uint32_t ad = kb + row * 128 +
                                  (uint32_t)(((2 * ks + bSel) ^ L7) << 4);
                    uint32_t bK[4];
                    ldsm_x4(ad, bK);
                    mmaf16(accS[2*jp],   qF[ks], &bK[0]);
                    mmaf16(accS[2*jp+1], qF[ks], &bK[2]);
                }
            }

            // scale * mask, online softmax
#pragma unroll
            for (int nj = 0; nj < 8; nj++) {
                accS[nj][0] *= 0.125f * pmA[nj].x;
                accS[nj][1] *= 0.125f * pmA[nj].y;
                accS[nj][2] *= 0.125f * pmB[nj].x;
                accS[nj][3] *= 0.125f * pmB[nj].y;
            }
            float mxA = -1e30f, mxB = -1e30f;
#pragma unroll
            for (int nj = 0; nj < 8; nj++) {
                mxA = fmaxf(mxA, fmaxf(accS[nj][0], accS[nj][1]));
                mxB = fmaxf(mxB, fmaxf(accS[nj][2], accS[nj][3]));
            }
            mxA = fmaxf(mxA, __shfl_xor_sync(0xffffffffu, mxA, 1));
            mxA = fmaxf(mxA, __shfl_xor_sync(0xffffffffu, mxA, 2));
            mxB = fmaxf(mxB, __shfl_xor_sync(0xffffffffu, mxB, 1));
            mxB = fmaxf(mxB, __shfl_xor_sync(0xffffffffu, mxB, 2));
            float mnA = fmaxf(mA[hh], mxA), mnB = fmaxf(mB[hh], mxB);
            float corrA = __expf(mA[hh] - mnA), corrB = __expf(mB[hh] - mnB);
            float tsA = 0.f, tsB = 0.f;
#pragma unroll
            for (int nj = 0; nj < 8; nj++) {
                accS[nj][0] = __expf(accS[nj][0] - mnA);
                accS[nj][1] = __expf(accS[nj][1] - mnA);
                accS[nj][2] = __expf(accS[nj][2] - mnB);
                accS[nj][3] = __expf(accS[nj][3] - mnB);
                tsA += accS[nj][0] + accS[nj][1];
                tsB += accS[nj][2] + accS[nj][3];
            }
            tsA += __shfl_xor_sync(0xffffffffu, tsA, 1);
            tsA += __shfl_xor_sync(0xffffffffu, tsA, 2);
            tsB += __shfl_xor_sync(0xffffffffu, tsB, 1);
            tsB += __shfl_xor_sync(0xffffffffu, tsB, 2);
            lA[hh] = lA[hh] * corrA + tsA;
            lB[hh] = lB[hh] * corrB + tsB;
            mA[hh] = mnA; mB[hh] = mnB;

#pragma unroll
            for (int nj = 0; nj < 8; nj++) {
                pv[hh][nj][0] *= corrA; pv[hh][nj][1] *= corrA;
                pv[hh][nj][2] *= corrB; pv[hh][nj][3] *= corrB;
            }

            // PV
#pragma unroll
            for (int ks = 0; ks < 4; ks++) {
                const float* s0 = accS[2*ks];
                const float* s1 = accS[2*ks+1];
                __half2 p0 = __floats2half2_rn(s0[0], s0[1]);
                __half2 p1 = __floats2half2_rn(s0[2], s0[3]);
                __half2 p2 = __floats2half2_rn(s1[0], s1[1]);
                __half2 p3 = __floats2half2_rn(s1[2], s1[3]);
                uint32_t aP[4] = {h2bits(p0), h2bits(p1), h2bits(p2), h2bits(p3)};

                uint32_t row = (uint32_t)(ks * 16 + (lane & 15));
#pragma unroll
                for (int jp = 0; jp < 4; jp++) {
                    uint32_t ad = vb + row * 128 +
                                  (uint32_t)(((2 * jp + (lane >> 4)) ^ L7) << 4);
                    uint32_t vK[4];
                    ldsm_x4_t(ad, vK);
                    mmaf16(pv[hh][2*jp],   aP, &vK[0]);
                    mmaf16(pv[hh][2*jp+1], aP, &vK[2]);
                }
            }
        }
    }

    const int gA = q0 + rA, gB = q0 + rB;
#pragma unroll
    for (int hh = 0; hh < 2; hh++) {
        const float invA = 1.f / lA[hh], invB = 1.f / lB[hh];
        const int hcol = (h0 + hh) * PHH;
#pragma unroll
        for (int nj = 0; nj < 8; nj++) {
            int d = nj * 8 + (lane & 3) * 2;
            size_t iA = ((size_t)b * SS + gA) * HH + hcol + d;
            size_t iB = ((size_t)b * SS + gB) * HH + hcol + d;
            *(__half2*)&C16[iA] = __floats2half2_rn(pv[hh][nj][0] * invA,
                                                    pv[hh][nj][1] * invA);
            *(__half2*)&C16[iB] = __floats2half2_rn(pv[hh][nj][2] * invB,
                                                    pv[hh][nj][3] * invB);
        }
    }
}

extern "C" void kernel_launch(void* const* d_in, const int* in_sizes, int n_in,
                              void* d_out, int out_size)
{
    const float* key   = (const float*)d_in[0];
    const float* value = (const float*)d_in[1];
    const float* query = (const float*)d_in[2];
    const float* mask  = (const float*)d_in[3];
    const float* Wq = (const float*)d_in[5];
    const float* bq = (const float*)d_in[6];
    const float* Wk = (const float*)d_in[7];
    const float* bk = (const float*)d_in[8];
    const float* Wv = (const float*)d_in[9];
    const float* bv = (const float*)d_in[10];
    const float* Wo = (const float*)d_in[11];
    const float* bo = (const float*)d_in[12];
    float* out = (float*)d_out;

    __half *c16, *sq, *sk, *sv, *wq16, *wk16, *wv16, *wo16, *q16, *k16, *v16;
    cudaGetSymbolAddress((void**)&c16, g_c16);
    cudaGetSymbolAddress((void**)&sq, g_sq);
    cudaGetSymbolAddress((void**)&sk, g_sk);
    cudaGetSymbolAddress((void**)&sv, g_sv);
    cudaGetSymbolAddress((void**)&wq16, g_wq16);
    cudaGetSymbolAddress((void**)&wk16, g_wk16);
    cudaGetSymbolAddress((void**)&wv16, g_wv16);
    cudaGetSymbolAddress((void**)&wo16, g_wo16);
    cudaGetSymbolAddress((void**)&q16, g_q16);
    cudaGetSymbolAddress((void**)&k16, g_k16);
    cudaGetSymbolAddress((void**)&v16, g_v16);

    Cvt7 cv;
    cv.src[0] = query; cv.dst[0] = sq;
    cv.src[1] = key;   cv.dst[1] = sk;
    cv.src[2] = value; cv.dst[2] = sv;
    cv.src[3] = Wq; cv.dst[3] = wq16;
    cv.src[4] = Wk; cv.dst[4] = wk16;
    cv.src[5] = Wv; cv.dst[5] = wv16;
    cv.src[6] = Wo; cv.dst[6] = wo16;
    convert_all<<<16384, 256>>>(cv);

    Gemm3 g3;
    g3.A[0] = sq; g3.W[0] = wq16; g3.bias[0] = bq; g3.H[0] = q16;
    g3.A[1] = sk; g3.W[1] = wk16; g3.bias[1] = bk; g3.H[1] = k16;
    g3.A[2] = sv; g3.W[2] = wv16; g3.bias[2] = bv; g3.H[2] = v16;

    cudaFuncSetAttribute(gemm_qkv, cudaFuncAttributeMaxDynamicSharedMemorySize, G5_SMEM);
    cudaFuncSetAttribute(gemm_out, cudaFuncAttributeMaxDynamicSharedMemorySize, G5_SMEM);
    gemm_qkv<<<dim3(HH / 128, MM / 128, 3), 256, G5_SMEM>>>(g3);

    cudaFuncSetAttribute(attn8_kernel, cudaFuncAttributeMaxDynamicSharedMemorySize, ATT8_SMEM);
    attn8_kernel<<<dim3(SS / 128, NHH / 2, BB), 256, ATT8_SMEM>>>(
        q16, k16, v16, mask, c16);

    gemm_out<<<dim3(HH / 128, MM / 128), 256, G5_SMEM>>>(c16, wo16, bo, out);
}